// round 8
// baseline (speedup 1.0000x reference)
#include <cuda_runtime.h>
#include <cuda_bf16.h>
#include <mma.h>

using namespace nvcuda;

#define Bb 2
#define Ss 2048
#define Dd 768
#define Pp 16
#define SCALE 0.03608439182435161f   // 1/sqrt(768)

#define PSEG (Bb * Ss * (Ss + Pp * 32))   // padded P elems
#define VSEG (Bb * Dd * (Ss + Pp * 32))   // padded V elems

// ---------------- scratch (device globals) -------------------------------------
__device__ __align__(256) float g_sc[Bb * Ss * Ss];
__device__ __align__(256) __nv_bfloat16 g_xh[Bb * Ss * Dd], g_xl[Bb * Ss * Dd];
__device__ __align__(256) __nv_bfloat16 g_wth[3 * Dd * Dd], g_wtl[3 * Dd * Dd];
__device__ __align__(256) __nv_bfloat16 g_qh[Bb * Ss * Dd], g_ql[Bb * Ss * Dd];
__device__ __align__(256) __nv_bfloat16 g_kh[Bb * Ss * Dd], g_kl[Bb * Ss * Dd];
__device__ __align__(256) __nv_bfloat16 g_ph[PSEG], g_pl[PSEG];
__device__ __align__(256) __nv_bfloat16 g_vh[VSEG], g_vl[VSEG];
__device__ int g_seg[Bb * Pp];
__device__ int g_Lp[Bb * Pp];
__device__ long long g_poff[Bb * Pp];
__device__ long long g_voff[Bb * Pp];
__device__ int g_sp[Bb * Ss];

// ---------------- wmma types ----------------------------------------------------
typedef wmma::fragment<wmma::matrix_a, 16, 16, 16, __nv_bfloat16, wmma::row_major> frag_a;
typedef wmma::fragment<wmma::matrix_b, 16, 16, 16, __nv_bfloat16, wmma::col_major> frag_b;
typedef wmma::fragment<wmma::accumulator, 16, 16, 16, float> frag_c;

// Block tile 128(M) x 256(N), K-chunk 32. Warp tile 64x64, warps 2x4.
#define TLD 40                        // smem ld (bf16): 80B rows
#define A_TILE 10240                  // 128 x TLD x 2B
#define B_TILE 20480                  // 256 x TLD x 2B
#define STAGE_B 61440                 // Ahi+Alo+Bhi+Blo
#define SMEM_BYTES 122880             // 2 stages

// ---------------- helpers -------------------------------------------------------
__device__ __forceinline__ unsigned smem_u32(const void* p) {
    unsigned a;
    asm("{ .reg .u64 t; cvta.to.shared.u64 t, %1; cvt.u32.u64 %0, t; }" : "=r"(a) : "l"(p));
    return a;
}
#define CP16(daddr, gptr) \
    asm volatile("cp.async.cg.shared.global [%0], [%1], 16;" :: "r"(daddr), "l"(gptr) : "memory")
__device__ __forceinline__ void cp_commit() { asm volatile("cp.async.commit_group;" ::: "memory"); }
__device__ __forceinline__ void cp_wait0() { asm volatile("cp.async.wait_group 0;" ::: "memory"); }

__device__ __forceinline__ void split2(float v, __nv_bfloat16& h, __nv_bfloat16& l) {
    h = __float2bfloat16(v);
    l = __float2bfloat16(v - __bfloat162float(h));
}

// stage one K=32 chunk: A(128 rows) + B(256 rows), hi/lo, pure 16B async copies
__device__ __forceinline__ void stage_ab(const __nv_bfloat16* Ah, const __nv_bfloat16* Al, long lda,
                                         const __nv_bfloat16* Bh, const __nv_bfloat16* Bl, long ldb,
                                         unsigned sb, int tid) {
    #pragma unroll
    for (int i = 0; i < 2; i++) {
        int ch = i * 256 + tid;              // 0..511
        int r = ch >> 2, c = (ch & 3) << 3;
        unsigned so = (unsigned)(r * 80 + c * 2);
        CP16(sb + so, Ah + (long)r * lda + c);
        CP16(sb + A_TILE + so, Al + (long)r * lda + c);
    }
    #pragma unroll
    for (int i = 0; i < 4; i++) {
        int ch = i * 256 + tid;              // 0..1023
        int r = ch >> 2, c = (ch & 3) << 3;
        unsigned so = (unsigned)(r * 80 + c * 2);
        CP16(sb + 2 * A_TILE + so, Bh + (long)r * ldb + c);
        CP16(sb + 2 * A_TILE + B_TILE + so, Bl + (long)r * ldb + c);
    }
}

// 3-term split MMA over one staged K=32 chunk; warp tile 64x64 at (wm, wn).
// B fragments streamed (one hi/lo pair live) to stay under the register cap.
__device__ __forceinline__ void mma_chunk(frag_c (&acc)[4][4], const char* buf, int wm, int wn) {
    const __nv_bfloat16* sAh = (const __nv_bfloat16*)buf;
    const __nv_bfloat16* sAl = (const __nv_bfloat16*)(buf + A_TILE);
    const __nv_bfloat16* sBh = (const __nv_bfloat16*)(buf + 2 * A_TILE);
    const __nv_bfloat16* sBl = (const __nv_bfloat16*)(buf + 2 * A_TILE + B_TILE);
    #pragma unroll
    for (int ks = 0; ks < 2; ks++) {
        frag_a ah[4], al[4];
        #pragma unroll
        for (int i = 0; i < 4; i++) {
            wmma::load_matrix_sync(ah[i], sAh + (wm * 64 + i * 16) * TLD + ks * 16, TLD);
            wmma::load_matrix_sync(al[i], sAl + (wm * 64 + i * 16) * TLD + ks * 16, TLD);
        }
        #pragma unroll
        for (int j = 0; j < 4; j++) {
            frag_b bh, bl;
            wmma::load_matrix_sync(bh, sBh + (wn * 64 + j * 16) * TLD + ks * 16, TLD);
            wmma::load_matrix_sync(bl, sBl + (wn * 64 + j * 16) * TLD + ks * 16, TLD);
            #pragma unroll
            for (int i = 0; i < 4; i++)
                wmma::mma_sync(acc[i][j], ah[i], bh, acc[i][j]);
            #pragma unroll
            for (int i = 0; i < 4; i++)
                wmma::mma_sync(acc[i][j], ah[i], bl, acc[i][j]);
            #pragma unroll
            for (int i = 0; i < 4; i++)
                wmma::mma_sync(acc[i][j], al[i], bh, acc[i][j]);
        }
    }
}

// ---------------- decode + layout metadata --------------------------------------
__global__ void decode_idx(const void* __restrict__ raw) {
    const long long* p64 = (const long long*)raw;
    const int* p32 = (const int*)raw;
    bool ok64 = true;
    for (int b = 0; b < Bb && ok64; b++) {
        long long prev = -1;
        for (int p = 0; p < Pp; p++) {
            long long v = p64[b * Pp + p];
            if (v < 0 || v >= Ss || v <= prev) { ok64 = false; break; }
            prev = v;
        }
    }
    for (int i = 0; i < Bb * Pp; i++)
        g_seg[i] = ok64 ? (int)p64[i] : p32[i];
    long long po = 0, vo = 0;
    for (int bp = 0; bp < Bb * Pp; bp++) {
        int p = bp & 15;
        int s0 = g_seg[bp];
        int e0 = (p == Pp - 1) ? Ss : g_seg[bp + 1];
        int Lp = ((e0 - s0) + 31) & ~31;
        g_Lp[bp] = Lp;
        g_poff[bp] = po;
        g_voff[bp] = vo;
        po += (long long)Ss * Lp;
        vo += (long long)Dd * Lp;
    }
}

__global__ void sp_map() {
    int i = blockIdx.x * blockDim.x + threadIdx.x;
    if (i >= Bb * Ss) return;
    int b = i >> 11, s = i & (Ss - 1);
    int p = -1;
    #pragma unroll
    for (int j = 0; j < Pp; j++)
        if (s >= g_seg[b * Pp + j]) p = j;
    g_sp[i] = p;
}

__global__ void zero_vpad() {
    int bp = blockIdx.x;
    int p = bp & 15;
    int s0 = g_seg[bp];
    int e0 = (p == Pp - 1) ? Ss : g_seg[bp + 1];
    int L = e0 - s0, Lp = g_Lp[bp], pad = Lp - L;
    if (pad == 0) return;
    long long off = g_voff[bp];
    __nv_bfloat16 z = __float2bfloat16(0.f);
    for (int i = threadIdx.x; i < Dd * pad; i += blockDim.x) {
        int d = i / pad, k = L + i % pad;
        long long dst = off + (long long)d * Lp + k;
        g_vh[dst] = z;
        g_vl[dst] = z;
    }
}

// ---------------- pre-split inputs ----------------------------------------------
__global__ void split_x(const float* __restrict__ x) {
    long i = (long)blockIdx.x * 256 + threadIdx.x;
    float4 v = ((const float4*)x)[i];
    __nv_bfloat16 h[4], l[4];
    split2(v.x, h[0], l[0]); split2(v.y, h[1], l[1]);
    split2(v.z, h[2], l[2]); split2(v.w, h[3], l[3]);
    *(uint2*)&g_xh[i * 4] = *(uint2*)h;
    *(uint2*)&g_xl[i * 4] = *(uint2*)l;
}

__global__ void transpose_w(const float* __restrict__ Wq, const float* __restrict__ Wk,
                            const float* __restrict__ Wv) {
    __shared__ float t[32][33];
    int z = blockIdx.z;
    const float* W = (z == 0) ? Wq : (z == 1) ? Wk : Wv;
    int x0 = blockIdx.x * 32, y0 = blockIdx.y * 32;
    int tx = threadIdx.x, ty = threadIdx.y;
    #pragma unroll
    for (int i = 0; i < 32; i += 8) t[ty + i][tx] = W[(y0 + ty + i) * Dd + x0 + tx];
    __syncthreads();
    #pragma unroll
    for (int i = 0; i < 32; i += 8) {
        float v = t[tx][ty + i];
        __nv_bfloat16 h, l;
        split2(v, h, l);
        long dst = (long)z * Dd * Dd + (long)(x0 + ty + i) * Dd + y0 + tx;
        g_wth[dst] = h;
        g_wtl[dst] = l;
    }
}

// ---------------- projection GEMM (x @ W^T-rows), block 128x256 ------------------
__global__ void __launch_bounds__(256, 1) proj_tc(const float* __restrict__ b0,
                                                  const float* __restrict__ b1,
                                                  const float* __restrict__ b2) {
    extern __shared__ char smx[];
    unsigned sbu = smem_u32(smx);
    const int tid = threadIdx.x, warp = tid >> 5, lane = tid & 31;
    const int wm = warp >> 2, wn = warp & 3;
    const int z = blockIdx.z;
    const int n0 = blockIdx.x * 256, m0 = blockIdx.y * 128;

    const __nv_bfloat16* Ah = g_xh + (long)m0 * Dd;
    const __nv_bfloat16* Al = g_xl + (long)m0 * Dd;
    const __nv_bfloat16* Bh = g_wth + (long)z * Dd * Dd + (long)n0 * Dd;
    const __nv_bfloat16* Bl = g_wtl + (long)z * Dd * Dd + (long)n0 * Dd;

    frag_c acc[4][4];
    #pragma unroll
    for (int i = 0; i < 4; i++)
        #pragma unroll
        for (int j = 0; j < 4; j++) wmma::fill_fragment(acc[i][j], 0.f);

    const int NC = Dd / 32;
    stage_ab(Ah, Al, Dd, Bh, Bl, Dd, sbu, tid);
    cp_commit();
    for (int c = 0; c < NC; c++) {
        cp_wait0();
        __syncthreads();
        if (c + 1 < NC) {
            int k = (c + 1) * 32;
            stage_ab(Ah + k, Al + k, Dd, Bh + k, Bl + k, Dd, sbu + ((c + 1) & 1) * STAGE_B, tid);
            cp_commit();
        }
        mma_chunk(acc, smx + (c & 1) * STAGE_B, wm, wn);
    }
    __syncthreads();

    const float* bias = (z == 0) ? b0 : (z == 1) ? b1 : b2;
    float* bounce = (float*)smx + warp * 320;        // 16x20 per warp
    #pragma unroll
    for (int i = 0; i < 4; i++)
        #pragma unroll
        for (int j = 0; j < 4; j++) {
            wmma::store_matrix_sync(bounce, acc[i][j], 20, wmma::mem_row_major);
            __syncwarp();
            int gm = m0 + wm * 64 + i * 16;
            int gn = n0 + wn * 64 + j * 16;
            if (z == 2) {
                int c = lane >> 1, rs = (lane & 1) * 8;
                int d = gn + c;
                float bi = bias[d];
                int bb = m0 >> 11;
                int sbase = (gm & (Ss - 1)) + rs;
                #pragma unroll
                for (int t = 0; t < 8; t++) {
                    int s = sbase + t;
                    int p = g_sp[bb * Ss + s];
                    if (p >= 0) {
                        int bpi = bb * Pp + p;
                        long long dst = g_voff[bpi] + (long long)d * g_Lp[bpi]
                                        + (s - g_seg[bpi]);
                        __nv_bfloat16 h, l;
                        split2(bounce[(rs + t) * 20 + c] + bi, h, l);
                        g_vh[dst] = h;
                        g_vl[dst] = l;
                    }
                }
            } else {
                int r = lane >> 1, cs = (lane & 1) * 8;
                __nv_bfloat16 hh[8], ll[8];
                #pragma unroll
                for (int t = 0; t < 8; t++) {
                    float val = bounce[r * 20 + cs + t] + bias[gn + cs + t];
                    if (z == 0) val *= SCALE;
                    split2(val, hh[t], ll[t]);
                }
                long dst = (long)(gm + r) * Dd + gn + cs;
                if (z == 0) {
                    *(uint4*)&g_qh[dst] = *(uint4*)hh;
                    *(uint4*)&g_ql[dst] = *(uint4*)ll;
                } else {
                    *(uint4*)&g_kh[dst] = *(uint4*)hh;
                    *(uint4*)&g_kl[dst] = *(uint4*)ll;
                }
            }
            __syncwarp();
        }
}

// ---------------- scores GEMM: sc = (q*scale) @ k^T, block 128x256 ---------------
__global__ void __launch_bounds__(256, 1) scores_tc() {
    extern __shared__ char smx[];
    unsigned sbu = smem_u32(smx);
    const int tid = threadIdx.x, warp = tid >> 5;
    const int wm = warp >> 2, wn = warp & 3;
    const int b = blockIdx.z;
    const int n0 = blockIdx.x * 256, m0 = blockIdx.y * 128;

    const __nv_bfloat16* Ah = g_qh + ((long)b * Ss + m0) * Dd;
    const __nv_bfloat16* Al = g_ql + ((long)b * Ss + m0) * Dd;
    const __nv_bfloat16* Bh = g_kh + ((long)b * Ss + n0) * Dd;
    const __nv_bfloat16* Bl = g_kl + ((long)b * Ss + n0) * Dd;

    frag_c acc[4][4];
    #pragma unroll
    for (int i = 0; i < 4; i++)
        #pragma unroll
        for (int j = 0; j < 4; j++) wmma::fill_fragment(acc[i][j], 0.f);

    const int NC = Dd / 32;
    stage_ab(Ah, Al, Dd, Bh, Bl, Dd, sbu, tid);
    cp_commit();
    for (int c = 0; c < NC; c++) {
        cp_wait0();
        __syncthreads();
        if (c + 1 < NC) {
            int k = (c + 1) * 32;
            stage_ab(Ah + k, Al + k, Dd, Bh + k, Bl + k, Dd, sbu + ((c + 1) & 1) * STAGE_B, tid);
            cp_commit();
        }
        mma_chunk(acc, smx + (c & 1) * STAGE_B, wm, wn);
    }

    float* dst = g_sc + (long)b * Ss * Ss;
    #pragma unroll
    for (int i = 0; i < 4; i++)
        #pragma unroll
        for (int j = 0; j < 4; j++) {
            int gm = m0 + wm * 64 + i * 16;
            int gn = n0 + wn * 64 + j * 16;
            wmma::store_matrix_sync(&dst[(long)gm * Ss + gn], acc[i][j], Ss,
                                    wmma::mem_row_major);
        }
}

// ---------------- softmax stats -> padded P (bf16 hi/lo) -------------------------
__global__ void stats_kernel() {
    const int wid = (blockIdx.x * blockDim.x + threadIdx.x) >> 5;
    const int lane = threadIdx.x & 31;
    const int q = wid & (Ss - 1);
    const int bp = wid / Ss;
    const int b = bp >> 4, p = bp & 15;
    const int s0 = g_seg[bp];
    const int e0 = (p == Pp - 1) ? Ss : g_seg[bp + 1];
    const int Lp = g_Lp[bp];
    const float* row = g_sc + ((long)b * Ss + q) * Ss;
    float mx = -1e30f;
    for (int k = s0 + lane; k < e0; k += 32) mx = fmaxf(mx, row[k]);
    #pragma unroll
    for (int o = 16; o; o >>= 1) mx = fmaxf(mx, __shfl_xor_sync(0xffffffffu, mx, o));
    float sum = 0.f;
    for (int k = s0 + lane; k < e0; k += 32) sum += __expf(row[k] - mx);
    #pragma unroll
    for (int o = 16; o; o >>= 1) sum += __shfl_xor_sync(0xffffffffu, sum, o);
    float inv = 1.0f / sum;
    long long po = g_poff[bp] + (long long)q * Lp;
    for (int k = s0 + lane; k < s0 + Lp; k += 32) {
        float pv = (k < e0) ? __expf(row[k] - mx) * inv : 0.f;
        __nv_bfloat16 h, l;
        split2(pv, h, l);
        g_ph[po + (k - s0)] = h;
        g_pl[po + (k - s0)] = l;
    }
}

// ---------------- output GEMM: out[bp] = P @ V, block 128x256 --------------------
__global__ void __launch_bounds__(256, 1) out_tc(float* __restrict__ out) {
    extern __shared__ char smx[];
    unsigned sbu = smem_u32(smx);
    const int tid = threadIdx.x, warp = tid >> 5;
    const int wm = warp >> 2, wn = warp & 3;
    const int bp = blockIdx.z;
    const int Lp = g_Lp[bp];
    const int NC = Lp >> 5;
    const int n0 = blockIdx.x * 256, m0 = blockIdx.y * 128;

    const __nv_bfloat16* Ah = g_ph + g_poff[bp] + (long long)m0 * Lp;
    const __nv_bfloat16* Al = g_pl + g_poff[bp] + (long long)m0 * Lp;
    const __nv_bfloat16* Bh = g_vh + g_voff[bp] + (long long)n0 * Lp;
    const __nv_bfloat16* Bl = g_vl + g_voff[bp] + (long long)n0 * Lp;

    frag_c acc[4][4];
    #pragma unroll
    for (int i = 0; i < 4; i++)
        #pragma unroll
        for (int j = 0; j < 4; j++) wmma::fill_fragment(acc[i][j], 0.f);

    stage_ab(Ah, Al, Lp, Bh, Bl, Lp, sbu, tid);
    cp_commit();
    for (int c = 0; c < NC; c++) {
        cp_wait0();
        __syncthreads();
        if (c + 1 < NC) {
            int k = (c + 1) * 32;
            stage_ab(Ah + k, Al + k, Lp, Bh + k, Bl + k, Lp, sbu + ((c + 1) & 1) * STAGE_B, tid);
            cp_commit();
        }
        mma_chunk(acc, smx + (c & 1) * STAGE_B, wm, wn);
    }

    float* dst = out + ((long)bp * Ss + m0) * Dd;
    #pragma unroll
    for (int i = 0; i < 4; i++)
        #pragma unroll
        for (int j = 0; j < 4; j++) {
            int rm = wm * 64 + i * 16;
            int gn = n0 + wn * 64 + j * 16;
            wmma::store_matrix_sync(&dst[(long)rm * Dd + gn], acc[i][j], Dd,
                                    wmma::mem_row_major);
        }
}

// ---------------- launch ----------------------------------------------------------
extern "C" void kernel_launch(void* const* d_in, const int* in_sizes, int n_in,
                              void* d_out, int out_size) {
    const float* x = (const float*)d_in[0];
    const void* pidx = d_in[1];
    const float* Wq = (const float*)d_in[2];
    const float* bq = (const float*)d_in[3];
    const float* Wk = (const float*)d_in[4];
    const float* bk = (const float*)d_in[5];
    const float* Wv = (const float*)d_in[6];
    const float* bv = (const float*)d_in[7];
    float* out = (float*)d_out;

    static int attr_done = 0;
    if (!attr_done) {
        cudaFuncSetAttribute(proj_tc, cudaFuncAttributeMaxDynamicSharedMemorySize, SMEM_BYTES);
        cudaFuncSetAttribute(scores_tc, cudaFuncAttributeMaxDynamicSharedMemorySize, SMEM_BYTES);
        cudaFuncSetAttribute(out_tc, cudaFuncAttributeMaxDynamicSharedMemorySize, SMEM_BYTES);
        attr_done = 1;
    }

    decode_idx<<<1, 1>>>(pidx);
    sp_map<<<(Bb * Ss) / 256, 256>>>();
    zero_vpad<<<Bb * Pp, 256>>>();
    split_x<<<(Bb * Ss * Dd / 4) / 256, 256>>>(x);

    dim3 tg(Dd / 32, Dd / 32, 3);
    transpose_w<<<tg, dim3(32, 8)>>>(Wq, Wk, Wv);

    dim3 pg(Dd / 256, (Bb * Ss) / 128, 3);           // 3 x 32 x 3
    proj_tc<<<pg, 256, SMEM_BYTES>>>(bq, bk, bv);

    dim3 sg(Ss / 256, Ss / 128, Bb);                 // 8 x 16 x 2
    scores_tc<<<sg, 256, SMEM_BYTES>>>();

    stats_kernel<<<(Bb * Pp * Ss) / 8, 256>>>();

    dim3 og(Dd / 256, Ss / 128, Bb * Pp);            // 3 x 16 x 32
    out_tc<<<og, 256, SMEM_BYTES>>>(out);
}

// round 9
// speedup vs baseline: 1.2501x; 1.2501x over previous
#include <cuda_runtime.h>
#include <cuda_bf16.h>
#include <cuda_fp16.h>
#include <mma.h>

using namespace nvcuda;

#define Bb 2
#define Ss 2048
#define Dd 768
#define Pp 16
#define SCALE 0.03608439182435161f   // 1/sqrt(768)

#define PSEG (Bb * Ss * (Ss + Pp * 32))   // padded P elems
#define VSEG (Bb * Dd * (Ss + Pp * 32))   // padded V elems

// ---------------- scratch (device globals) -------------------------------------
__device__ __align__(256) float g_sc[Bb * Ss * Ss];
__device__ __align__(256) __nv_bfloat16 g_xh[Bb * Ss * Dd], g_xl[Bb * Ss * Dd];
__device__ __align__(256) __nv_bfloat16 g_wth[3 * Dd * Dd], g_wtl[3 * Dd * Dd];
__device__ __align__(256) __nv_bfloat16 g_qh[Bb * Ss * Dd], g_ql[Bb * Ss * Dd];
__device__ __align__(256) __nv_bfloat16 g_kh[Bb * Ss * Dd], g_kl[Bb * Ss * Dd];
__device__ __align__(256) __half g_pf[PSEG];     // P, single fp16
__device__ __align__(256) __half g_vf[VSEG];     // V, single fp16
__device__ int g_seg[Bb * Pp];
__device__ int g_Lp[Bb * Pp];
__device__ long long g_poff[Bb * Pp];
__device__ long long g_voff[Bb * Pp];
__device__ int g_sp[Bb * Ss];

// ---------------- wmma types ----------------------------------------------------
typedef wmma::fragment<wmma::matrix_a, 16, 16, 16, __nv_bfloat16, wmma::row_major> frag_a;
typedef wmma::fragment<wmma::matrix_b, 16, 16, 16, __nv_bfloat16, wmma::col_major> frag_b;
typedef wmma::fragment<wmma::matrix_a, 16, 16, 16, __half, wmma::row_major> frag_ha;
typedef wmma::fragment<wmma::matrix_b, 16, 16, 16, __half, wmma::col_major> frag_hb;
typedef wmma::fragment<wmma::accumulator, 16, 16, 16, float> frag_c;

// Block tile 128(M) x 256(N), K-chunk 32. Warp tile 64x64, warps 2x4.
#define TLD 40                        // smem ld (elems): 80B rows
#define A_TILE 10240                  // 128 x TLD x 2B
#define B_TILE 20480                  // 256 x TLD x 2B
#define STAGE_B 61440                 // Ahi+Alo+Bhi+Blo (split kernels)
#define SMEM_BYTES 122880             // 2 stages
#define H_STAGE 30720                 // A + B (fp16 kernel)
#define H_SMEM 61440                  // 2 stages

// ---------------- helpers -------------------------------------------------------
__device__ __forceinline__ unsigned smem_u32(const void* p) {
    unsigned a;
    asm("{ .reg .u64 t; cvta.to.shared.u64 t, %1; cvt.u32.u64 %0, t; }" : "=r"(a) : "l"(p));
    return a;
}
#define CP16(daddr, gptr) \
    asm volatile("cp.async.cg.shared.global [%0], [%1], 16;" :: "r"(daddr), "l"(gptr) : "memory")
__device__ __forceinline__ void cp_commit() { asm volatile("cp.async.commit_group;" ::: "memory"); }
__device__ __forceinline__ void cp_wait0() { asm volatile("cp.async.wait_group 0;" ::: "memory"); }

__device__ __forceinline__ void split2(float v, __nv_bfloat16& h, __nv_bfloat16& l) {
    h = __float2bfloat16(v);
    l = __float2bfloat16(v - __bfloat162float(h));
}

// stage one K=32 chunk: A(128 rows) + B(256 rows), hi/lo, pure 16B async copies
__device__ __forceinline__ void stage_ab(const __nv_bfloat16* Ah, const __nv_bfloat16* Al, long lda,
                                         const __nv_bfloat16* Bh, const __nv_bfloat16* Bl, long ldb,
                                         unsigned sb, int tid) {
    #pragma unroll
    for (int i = 0; i < 2; i++) {
        int ch = i * 256 + tid;
        int r = ch >> 2, c = (ch & 3) << 3;
        unsigned so = (unsigned)(r * 80 + c * 2);
        CP16(sb + so, Ah + (long)r * lda + c);
        CP16(sb + A_TILE + so, Al + (long)r * lda + c);
    }
    #pragma unroll
    for (int i = 0; i < 4; i++) {
        int ch = i * 256 + tid;
        int r = ch >> 2, c = (ch & 3) << 3;
        unsigned so = (unsigned)(r * 80 + c * 2);
        CP16(sb + 2 * A_TILE + so, Bh + (long)r * ldb + c);
        CP16(sb + 2 * A_TILE + B_TILE + so, Bl + (long)r * ldb + c);
    }
}

// fp16 single stage: A(128 rows) + B(256 rows)
__device__ __forceinline__ void stage_h(const __half* A, long lda,
                                        const __half* B, long ldb,
                                        unsigned sb, int tid) {
    #pragma unroll
    for (int i = 0; i < 2; i++) {
        int ch = i * 256 + tid;
        int r = ch >> 2, c = (ch & 3) << 3;
        CP16(sb + (unsigned)(r * 80 + c * 2), A + (long)r * lda + c);
    }
    #pragma unroll
    for (int i = 0; i < 4; i++) {
        int ch = i * 256 + tid;
        int r = ch >> 2, c = (ch & 3) << 3;
        CP16(sb + A_TILE + (unsigned)(r * 80 + c * 2), B + (long)r * ldb + c);
    }
}

// 3-term split MMA over one staged K=32 chunk; warp tile 64x64 at (wm, wn)
__device__ __forceinline__ void mma_chunk(frag_c (&acc)[4][4], const char* buf, int wm, int wn) {
    const __nv_bfloat16* sAh = (const __nv_bfloat16*)buf;
    const __nv_bfloat16* sAl = (const __nv_bfloat16*)(buf + A_TILE);
    const __nv_bfloat16* sBh = (const __nv_bfloat16*)(buf + 2 * A_TILE);
    const __nv_bfloat16* sBl = (const __nv_bfloat16*)(buf + 2 * A_TILE + B_TILE);
    #pragma unroll
    for (int ks = 0; ks < 2; ks++) {
        frag_a ah[4], al[4];
        frag_b bh[4], bl[4];
        #pragma unroll
        for (int i = 0; i < 4; i++) {
            wmma::load_matrix_sync(ah[i], sAh + (wm * 64 + i * 16) * TLD + ks * 16, TLD);
            wmma::load_matrix_sync(al[i], sAl + (wm * 64 + i * 16) * TLD + ks * 16, TLD);
        }
        #pragma unroll
        for (int j = 0; j < 4; j++) {
            wmma::load_matrix_sync(bh[j], sBh + (wn * 64 + j * 16) * TLD + ks * 16, TLD);
            wmma::load_matrix_sync(bl[j], sBl + (wn * 64 + j * 16) * TLD + ks * 16, TLD);
        }
        #pragma unroll
        for (int i = 0; i < 4; i++)
            #pragma unroll
            for (int j = 0; j < 4; j++)
                wmma::mma_sync(acc[i][j], ah[i], bh[j], acc[i][j]);
        #pragma unroll
        for (int i = 0; i < 4; i++)
            #pragma unroll
            for (int j = 0; j < 4; j++)
                wmma::mma_sync(acc[i][j], ah[i], bl[j], acc[i][j]);
        #pragma unroll
        for (int i = 0; i < 4; i++)
            #pragma unroll
            for (int j = 0; j < 4; j++)
                wmma::mma_sync(acc[i][j], al[i], bh[j], acc[i][j]);
    }
}

// fp16 single-term MMA over one staged K=32 chunk
__device__ __forceinline__ void mma_chunk_h(frag_c (&acc)[4][4], const char* buf, int wm, int wn) {
    const __half* sA = (const __half*)buf;
    const __half* sB = (const __half*)(buf + A_TILE);
    #pragma unroll
    for (int ks = 0; ks < 2; ks++) {
        frag_ha a[4];
        frag_hb b[4];
        #pragma unroll
        for (int i = 0; i < 4; i++)
            wmma::load_matrix_sync(a[i], sA + (wm * 64 + i * 16) * TLD + ks * 16, TLD);
        #pragma unroll
        for (int j = 0; j < 4; j++)
            wmma::load_matrix_sync(b[j], sB + (wn * 64 + j * 16) * TLD + ks * 16, TLD);
        #pragma unroll
        for (int i = 0; i < 4; i++)
            #pragma unroll
            for (int j = 0; j < 4; j++)
                wmma::mma_sync(acc[i][j], a[i], b[j], acc[i][j]);
    }
}

// ---------------- decode + layout metadata --------------------------------------
__global__ void decode_idx(const void* __restrict__ raw) {
    const long long* p64 = (const long long*)raw;
    const int* p32 = (const int*)raw;
    bool ok64 = true;
    for (int b = 0; b < Bb && ok64; b++) {
        long long prev = -1;
        for (int p = 0; p < Pp; p++) {
            long long v = p64[b * Pp + p];
            if (v < 0 || v >= Ss || v <= prev) { ok64 = false; break; }
            prev = v;
        }
    }
    for (int i = 0; i < Bb * Pp; i++)
        g_seg[i] = ok64 ? (int)p64[i] : p32[i];
    long long po = 0, vo = 0;
    for (int bp = 0; bp < Bb * Pp; bp++) {
        int p = bp & 15;
        int s0 = g_seg[bp];
        int e0 = (p == Pp - 1) ? Ss : g_seg[bp + 1];
        int Lp = ((e0 - s0) + 31) & ~31;
        g_Lp[bp] = Lp;
        g_poff[bp] = po;
        g_voff[bp] = vo;
        po += (long long)Ss * Lp;
        vo += (long long)Dd * Lp;
    }
}

__global__ void sp_map() {
    int i = blockIdx.x * blockDim.x + threadIdx.x;
    if (i >= Bb * Ss) return;
    int b = i >> 11, s = i & (Ss - 1);
    int p = -1;
    #pragma unroll
    for (int j = 0; j < Pp; j++)
        if (s >= g_seg[b * Pp + j]) p = j;
    g_sp[i] = p;
}

__global__ void zero_vpad() {
    int bp = blockIdx.x;
    int p = bp & 15;
    int s0 = g_seg[bp];
    int e0 = (p == Pp - 1) ? Ss : g_seg[bp + 1];
    int L = e0 - s0, Lp = g_Lp[bp], pad = Lp - L;
    if (pad == 0) return;
    long long off = g_voff[bp];
    __half z = __float2half(0.f);
    for (int i = threadIdx.x; i < Dd * pad; i += blockDim.x) {
        int d = i / pad, k = L + i % pad;
        g_vf[off + (long long)d * Lp + k] = z;
    }
}

// ---------------- pre-split inputs ----------------------------------------------
__global__ void split_x(const float* __restrict__ x) {
    long i = (long)blockIdx.x * 256 + threadIdx.x;
    float4 v = ((const float4*)x)[i];
    __nv_bfloat16 h[4], l[4];
    split2(v.x, h[0], l[0]); split2(v.y, h[1], l[1]);
    split2(v.z, h[2], l[2]); split2(v.w, h[3], l[3]);
    *(uint2*)&g_xh[i * 4] = *(uint2*)h;
    *(uint2*)&g_xl[i * 4] = *(uint2*)l;
}

__global__ void transpose_w(const float* __restrict__ Wq, const float* __restrict__ Wk,
                            const float* __restrict__ Wv) {
    __shared__ float t[32][33];
    int z = blockIdx.z;
    const float* W = (z == 0) ? Wq : (z == 1) ? Wk : Wv;
    int x0 = blockIdx.x * 32, y0 = blockIdx.y * 32;
    int tx = threadIdx.x, ty = threadIdx.y;
    #pragma unroll
    for (int i = 0; i < 32; i += 8) t[ty + i][tx] = W[(y0 + ty + i) * Dd + x0 + tx];
    __syncthreads();
    #pragma unroll
    for (int i = 0; i < 32; i += 8) {
        float v = t[tx][ty + i];
        __nv_bfloat16 h, l;
        split2(v, h, l);
        long dst = (long)z * Dd * Dd + (long)(x0 + ty + i) * Dd + y0 + tx;
        g_wth[dst] = h;
        g_wtl[dst] = l;
    }
}

// ---------------- projection GEMM (x @ W^T-rows), block 128x256 ------------------
__global__ void __launch_bounds__(256, 1) proj_tc(const float* __restrict__ b0,
                                                  const float* __restrict__ b1,
                                                  const float* __restrict__ b2) {
    extern __shared__ char smx[];
    unsigned sbu = smem_u32(smx);
    const int tid = threadIdx.x, warp = tid >> 5, lane = tid & 31;
    const int wm = warp >> 2, wn = warp & 3;
    const int z = blockIdx.z;
    const int n0 = blockIdx.x * 256, m0 = blockIdx.y * 128;

    const __nv_bfloat16* Ah = g_xh + (long)m0 * Dd;
    const __nv_bfloat16* Al = g_xl + (long)m0 * Dd;
    const __nv_bfloat16* Bh = g_wth + (long)z * Dd * Dd + (long)n0 * Dd;
    const __nv_bfloat16* Bl = g_wtl + (long)z * Dd * Dd + (long)n0 * Dd;

    frag_c acc[4][4];
    #pragma unroll
    for (int i = 0; i < 4; i++)
        #pragma unroll
        for (int j = 0; j < 4; j++) wmma::fill_fragment(acc[i][j], 0.f);

    const int NC = Dd / 32;
    stage_ab(Ah, Al, Dd, Bh, Bl, Dd, sbu, tid);
    cp_commit();
    for (int c = 0; c < NC; c++) {
        cp_wait0();
        __syncthreads();
        if (c + 1 < NC) {
            int k = (c + 1) * 32;
            stage_ab(Ah + k, Al + k, Dd, Bh + k, Bl + k, Dd, sbu + ((c + 1) & 1) * STAGE_B, tid);
            cp_commit();
        }
        mma_chunk(acc, smx + (c & 1) * STAGE_B, wm, wn);
    }
    __syncthreads();

    const float* bias = (z == 0) ? b0 : (z == 1) ? b1 : b2;
    float* bounce = (float*)smx + warp * 320;        // 16x20 per warp
    #pragma unroll
    for (int i = 0; i < 4; i++)
        #pragma unroll
        for (int j = 0; j < 4; j++) {
            wmma::store_matrix_sync(bounce, acc[i][j], 20, wmma::mem_row_major);
            __syncwarp();
            int gm = m0 + wm * 64 + i * 16;
            int gn = n0 + wn * 64 + j * 16;
            if (z == 2) {
                int c = lane >> 1, rs = (lane & 1) * 8;
                int d = gn + c;
                float bi = bias[d];
                int bb = m0 >> 11;
                int sbase = (gm & (Ss - 1)) + rs;
                #pragma unroll
                for (int t = 0; t < 8; t++) {
                    int s = sbase + t;
                    int p = g_sp[bb * Ss + s];
                    if (p >= 0) {
                        int bpi = bb * Pp + p;
                        long long dst = g_voff[bpi] + (long long)d * g_Lp[bpi]
                                        + (s - g_seg[bpi]);
                        g_vf[dst] = __float2half(bounce[(rs + t) * 20 + c] + bi);
                    }
                }
            } else {
                int r = lane >> 1, cs = (lane & 1) * 8;
                __nv_bfloat16 hh[8], ll[8];
                #pragma unroll
                for (int t = 0; t < 8; t++) {
                    float val = bounce[r * 20 + cs + t] + bias[gn + cs + t];
                    if (z == 0) val *= SCALE;
                    split2(val, hh[t], ll[t]);
                }
                long dst = (long)(gm + r) * Dd + gn + cs;
                if (z == 0) {
                    *(uint4*)&g_qh[dst] = *(uint4*)hh;
                    *(uint4*)&g_ql[dst] = *(uint4*)ll;
                } else {
                    *(uint4*)&g_kh[dst] = *(uint4*)hh;
                    *(uint4*)&g_kl[dst] = *(uint4*)ll;
                }
            }
            __syncwarp();
        }
}

// ---------------- scores GEMM: sc = (q*scale) @ k^T, block 128x256 ---------------
__global__ void __launch_bounds__(256, 1) scores_tc() {
    extern __shared__ char smx[];
    unsigned sbu = smem_u32(smx);
    const int tid = threadIdx.x, warp = tid >> 5;
    const int wm = warp >> 2, wn = warp & 3;
    const int b = blockIdx.z;
    const int n0 = blockIdx.x * 256, m0 = blockIdx.y * 128;

    const __nv_bfloat16* Ah = g_qh + ((long)b * Ss + m0) * Dd;
    const __nv_bfloat16* Al = g_ql + ((long)b * Ss + m0) * Dd;
    const __nv_bfloat16* Bh = g_kh + ((long)b * Ss + n0) * Dd;
    const __nv_bfloat16* Bl = g_kl + ((long)b * Ss + n0) * Dd;

    frag_c acc[4][4];
    #pragma unroll
    for (int i = 0; i < 4; i++)
        #pragma unroll
        for (int j = 0; j < 4; j++) wmma::fill_fragment(acc[i][j], 0.f);

    const int NC = Dd / 32;
    stage_ab(Ah, Al, Dd, Bh, Bl, Dd, sbu, tid);
    cp_commit();
    for (int c = 0; c < NC; c++) {
        cp_wait0();
        __syncthreads();
        if (c + 1 < NC) {
            int k = (c + 1) * 32;
            stage_ab(Ah + k, Al + k, Dd, Bh + k, Bl + k, Dd, sbu + ((c + 1) & 1) * STAGE_B, tid);
            cp_commit();
        }
        mma_chunk(acc, smx + (c & 1) * STAGE_B, wm, wn);
    }

    float* dst = g_sc + (long)b * Ss * Ss;
    #pragma unroll
    for (int i = 0; i < 4; i++)
        #pragma unroll
        for (int j = 0; j < 4; j++) {
            int gm = m0 + wm * 64 + i * 16;
            int gn = n0 + wn * 64 + j * 16;
            wmma::store_matrix_sync(&dst[(long)gm * Ss + gn], acc[i][j], Ss,
                                    wmma::mem_row_major);
        }
}

// ---------------- softmax stats -> padded P (fp16) -------------------------------
__global__ void stats_kernel() {
    const int wid = (blockIdx.x * blockDim.x + threadIdx.x) >> 5;
    const int lane = threadIdx.x & 31;
    const int q = wid & (Ss - 1);
    const int bp = wid / Ss;
    const int b = bp >> 4, p = bp & 15;
    const int s0 = g_seg[bp];
    const int e0 = (p == Pp - 1) ? Ss : g_seg[bp + 1];
    const int Lp = g_Lp[bp];
    const float* row = g_sc + ((long)b * Ss + q) * Ss;
    float mx = -1e30f;
    for (int k = s0 + lane; k < e0; k += 32) mx = fmaxf(mx, row[k]);
    #pragma unroll
    for (int o = 16; o; o >>= 1) mx = fmaxf(mx, __shfl_xor_sync(0xffffffffu, mx, o));
    float sum = 0.f;
    for (int k = s0 + lane; k < e0; k += 32) sum += __expf(row[k] - mx);
    #pragma unroll
    for (int o = 16; o; o >>= 1) sum += __shfl_xor_sync(0xffffffffu, sum, o);
    float inv = 1.0f / sum;
    long long po = g_poff[bp] + (long long)q * Lp;
    for (int k = s0 + lane; k < s0 + Lp; k += 32) {
        float pv = (k < e0) ? __expf(row[k] - mx) * inv : 0.f;
        g_pf[po + (k - s0)] = __float2half(pv);
    }
}

// ---------------- output GEMM: out[bp] = P @ V, fp16 single, block 128x256 -------
__global__ void __launch_bounds__(256, 1) out_tc(float* __restrict__ out) {
    extern __shared__ char smx[];
    unsigned sbu = smem_u32(smx);
    const int tid = threadIdx.x, warp = tid >> 5;
    const int wm = warp >> 2, wn = warp & 3;
    const int bp = blockIdx.z;
    const int Lp = g_Lp[bp];
    const int NC = Lp >> 5;
    const int n0 = blockIdx.x * 256, m0 = blockIdx.y * 128;

    const __half* A = g_pf + g_poff[bp] + (long long)m0 * Lp;
    const __half* B = g_vf + g_voff[bp] + (long long)n0 * Lp;

    frag_c acc[4][4];
    #pragma unroll
    for (int i = 0; i < 4; i++)
        #pragma unroll
        for (int j = 0; j < 4; j++) wmma::fill_fragment(acc[i][j], 0.f);

    stage_h(A, Lp, B, Lp, sbu, tid);
    cp_commit();
    for (int c = 0; c < NC; c++) {
        cp_wait0();
        __syncthreads();
        if (c + 1 < NC) {
            int k = (c + 1) * 32;
            stage_h(A + k, Lp, B + k, Lp, sbu + ((c + 1) & 1) * H_STAGE, tid);
            cp_commit();
        }
        mma_chunk_h(acc, smx + (c & 1) * H_STAGE, wm, wn);
    }

    float* dst = out + ((long)bp * Ss + m0) * Dd;
    #pragma unroll
    for (int i = 0; i < 4; i++)
        #pragma unroll
        for (int j = 0; j < 4; j++) {
            int rm = wm * 64 + i * 16;
            int gn = n0 + wn * 64 + j * 16;
            wmma::store_matrix_sync(&dst[(long)rm * Dd + gn], acc[i][j], Dd,
                                    wmma::mem_row_major);
        }
}

// ---------------- launch ----------------------------------------------------------
extern "C" void kernel_launch(void* const* d_in, const int* in_sizes, int n_in,
                              void* d_out, int out_size) {
    const float* x = (const float*)d_in[0];
    const void* pidx = d_in[1];
    const float* Wq = (const float*)d_in[2];
    const float* bq = (const float*)d_in[3];
    const float* Wk = (const float*)d_in[4];
    const float* bk = (const float*)d_in[5];
    const float* Wv = (const float*)d_in[6];
    const float* bv = (const float*)d_in[7];
    float* out = (float*)d_out;

    static int attr_done = 0;
    if (!attr_done) {
        cudaFuncSetAttribute(proj_tc, cudaFuncAttributeMaxDynamicSharedMemorySize, SMEM_BYTES);
        cudaFuncSetAttribute(scores_tc, cudaFuncAttributeMaxDynamicSharedMemorySize, SMEM_BYTES);
        cudaFuncSetAttribute(out_tc, cudaFuncAttributeMaxDynamicSharedMemorySize, H_SMEM);
        attr_done = 1;
    }

    decode_idx<<<1, 1>>>(pidx);
    sp_map<<<(Bb * Ss) / 256, 256>>>();
    zero_vpad<<<Bb * Pp, 256>>>();
    split_x<<<(Bb * Ss * Dd / 4) / 256, 256>>>(x);

    dim3 tg(Dd / 32, Dd / 32, 3);
    transpose_w<<<tg, dim3(32, 8)>>>(Wq, Wk, Wv);

    dim3 pg(Dd / 256, (Bb * Ss) / 128, 3);           // 3 x 32 x 3
    proj_tc<<<pg, 256, SMEM_BYTES>>>(bq, bk, bv);

    dim3 sg(Ss / 256, Ss / 128, Bb);                 // 8 x 16 x 2
    scores_tc<<<sg, 256, SMEM_BYTES>>>();

    stats_kernel<<<(Bb * Pp * Ss) / 8, 256>>>();

    dim3 og(Dd / 256, Ss / 128, Bb * Pp);            // 3 x 16 x 32
    out_tc<<<og, 256, H_SMEM>>>(out);
}

// round 10
// speedup vs baseline: 1.5410x; 1.2327x over previous
#include <cuda_runtime.h>
#include <cuda_bf16.h>
#include <cuda_fp16.h>
#include <mma.h>

using namespace nvcuda;

#define Bb 2
#define Ss 2048
#define Dd 768
#define Pp 16
#define SCALE 0.03608439182435161f   // 1/sqrt(768)

#define PSEG (Bb * Ss * (Ss + Pp * 32))   // padded P elems
#define VSEG (Bb * Dd * (Ss + Pp * 32))   // padded V elems

// ---------------- scratch (device globals) -------------------------------------
__device__ __align__(256) float g_sc[Bb * Ss * Ss];
__device__ __align__(256) __nv_bfloat16 g_xh[Bb * Ss * Dd], g_xl[Bb * Ss * Dd];
__device__ __align__(256) __nv_bfloat16 g_wth[3 * Dd * Dd], g_wtl[3 * Dd * Dd];
__device__ __align__(256) __half g_qf[Bb * Ss * Dd];   // q (pre-scaled), fp16
__device__ __align__(256) __half g_kf[Bb * Ss * Dd];   // k, fp16
__device__ __align__(256) __half g_pf[PSEG];           // P, fp16
__device__ __align__(256) __half g_vf[VSEG];           // V, fp16
__device__ int g_seg[Bb * Pp];
__device__ int g_Lp[Bb * Pp];
__device__ long long g_poff[Bb * Pp];
__device__ long long g_voff[Bb * Pp];
__device__ int g_sp[Bb * Ss];

// ---------------- wmma types ----------------------------------------------------
typedef wmma::fragment<wmma::matrix_a, 16, 16, 16, __nv_bfloat16, wmma::row_major> frag_a;
typedef wmma::fragment<wmma::matrix_b, 16, 16, 16, __nv_bfloat16, wmma::col_major> frag_b;
typedef wmma::fragment<wmma::matrix_a, 16, 16, 16, __half, wmma::row_major> frag_ha;
typedef wmma::fragment<wmma::matrix_b, 16, 16, 16, __half, wmma::col_major> frag_hb;
typedef wmma::fragment<wmma::accumulator, 16, 16, 16, float> frag_c;

// Block tile 128(M) x 256(N), K-chunk 32. Warp tile 64x64, warps 2x4.
#define TLD 40                        // smem ld (elems): 80B rows
#define A_TILE 10240                  // 128 x TLD x 2B
#define B_TILE 20480                  // 256 x TLD x 2B
#define STAGE_B 61440                 // Ahi+Alo+Bhi+Blo (split kernel)
#define SMEM_BYTES 122880             // 2 stages
#define H_STAGE 30720                 // A + B (fp16 kernels)
#define H_SMEM 61440                  // 2 stages

// ---------------- helpers -------------------------------------------------------
__device__ __forceinline__ unsigned smem_u32(const void* p) {
    unsigned a;
    asm("{ .reg .u64 t; cvta.to.shared.u64 t, %1; cvt.u32.u64 %0, t; }" : "=r"(a) : "l"(p));
    return a;
}
#define CP16(daddr, gptr) \
    asm volatile("cp.async.cg.shared.global [%0], [%1], 16;" :: "r"(daddr), "l"(gptr) : "memory")
__device__ __forceinline__ void cp_commit() { asm volatile("cp.async.commit_group;" ::: "memory"); }
__device__ __forceinline__ void cp_wait0() { asm volatile("cp.async.wait_group 0;" ::: "memory"); }

__device__ __forceinline__ void split2(float v, __nv_bfloat16& h, __nv_bfloat16& l) {
    h = __float2bfloat16(v);
    l = __float2bfloat16(v - __bfloat162float(h));
}

// stage one K=32 chunk: A(128 rows) + B(256 rows), bf16 hi/lo, 16B async copies
__device__ __forceinline__ void stage_ab(const __nv_bfloat16* Ah, const __nv_bfloat16* Al, long lda,
                                         const __nv_bfloat16* Bh, const __nv_bfloat16* Bl, long ldb,
                                         unsigned sb, int tid) {
    #pragma unroll
    for (int i = 0; i < 2; i++) {
        int ch = i * 256 + tid;
        int r = ch >> 2, c = (ch & 3) << 3;
        unsigned so = (unsigned)(r * 80 + c * 2);
        CP16(sb + so, Ah + (long)r * lda + c);
        CP16(sb + A_TILE + so, Al + (long)r * lda + c);
    }
    #pragma unroll
    for (int i = 0; i < 4; i++) {
        int ch = i * 256 + tid;
        int r = ch >> 2, c = (ch & 3) << 3;
        unsigned so = (unsigned)(r * 80 + c * 2);
        CP16(sb + 2 * A_TILE + so, Bh + (long)r * ldb + c);
        CP16(sb + 2 * A_TILE + B_TILE + so, Bl + (long)r * ldb + c);
    }
}

// fp16 single stage: A(128 rows) + B(256 rows)
__device__ __forceinline__ void stage_h(const __half* A, long lda,
                                        const __half* B, long ldb,
                                        unsigned sb, int tid) {
    #pragma unroll
    for (int i = 0; i < 2; i++) {
        int ch = i * 256 + tid;
        int r = ch >> 2, c = (ch & 3) << 3;
        CP16(sb + (unsigned)(r * 80 + c * 2), A + (long)r * lda + c);
    }
    #pragma unroll
    for (int i = 0; i < 4; i++) {
        int ch = i * 256 + tid;
        int r = ch >> 2, c = (ch & 3) << 3;
        CP16(sb + A_TILE + (unsigned)(r * 80 + c * 2), B + (long)r * ldb + c);
    }
}

// 3-term split MMA over one staged K=32 chunk; warp tile 64x64 at (wm, wn)
__device__ __forceinline__ void mma_chunk(frag_c (&acc)[4][4], const char* buf, int wm, int wn) {
    const __nv_bfloat16* sAh = (const __nv_bfloat16*)buf;
    const __nv_bfloat16* sAl = (const __nv_bfloat16*)(buf + A_TILE);
    const __nv_bfloat16* sBh = (const __nv_bfloat16*)(buf + 2 * A_TILE);
    const __nv_bfloat16* sBl = (const __nv_bfloat16*)(buf + 2 * A_TILE + B_TILE);
    #pragma unroll
    for (int ks = 0; ks < 2; ks++) {
        frag_a ah[4], al[4];
        frag_b bh[4], bl[4];
        #pragma unroll
        for (int i = 0; i < 4; i++) {
            wmma::load_matrix_sync(ah[i], sAh + (wm * 64 + i * 16) * TLD + ks * 16, TLD);
            wmma::load_matrix_sync(al[i], sAl + (wm * 64 + i * 16) * TLD + ks * 16, TLD);
        }
        #pragma unroll
        for (int j = 0; j < 4; j++) {
            wmma::load_matrix_sync(bh[j], sBh + (wn * 64 + j * 16) * TLD + ks * 16, TLD);
            wmma::load_matrix_sync(bl[j], sBl + (wn * 64 + j * 16) * TLD + ks * 16, TLD);
        }
        #pragma unroll
        for (int i = 0; i < 4; i++)
            #pragma unroll
            for (int j = 0; j < 4; j++)
                wmma::mma_sync(acc[i][j], ah[i], bh[j], acc[i][j]);
        #pragma unroll
        for (int i = 0; i < 4; i++)
            #pragma unroll
            for (int j = 0; j < 4; j++)
                wmma::mma_sync(acc[i][j], ah[i], bl[j], acc[i][j]);
        #pragma unroll
        for (int i = 0; i < 4; i++)
            #pragma unroll
            for (int j = 0; j < 4; j++)
                wmma::mma_sync(acc[i][j], al[i], bh[j], acc[i][j]);
    }
}

// fp16 single-term MMA over one staged K=32 chunk
__device__ __forceinline__ void mma_chunk_h(frag_c (&acc)[4][4], const char* buf, int wm, int wn) {
    const __half* sA = (const __half*)buf;
    const __half* sB = (const __half*)(buf + A_TILE);
    #pragma unroll
    for (int ks = 0; ks < 2; ks++) {
        frag_ha a[4];
        frag_hb b[4];
        #pragma unroll
        for (int i = 0; i < 4; i++)
            wmma::load_matrix_sync(a[i], sA + (wm * 64 + i * 16) * TLD + ks * 16, TLD);
        #pragma unroll
        for (int j = 0; j < 4; j++)
            wmma::load_matrix_sync(b[j], sB + (wn * 64 + j * 16) * TLD + ks * 16, TLD);
        #pragma unroll
        for (int i = 0; i < 4; i++)
            #pragma unroll
            for (int j = 0; j < 4; j++)
                wmma::mma_sync(acc[i][j], a[i], b[j], acc[i][j]);
    }
}

// ---------------- decode + layout metadata --------------------------------------
__global__ void decode_idx(const void* __restrict__ raw) {
    const long long* p64 = (const long long*)raw;
    const int* p32 = (const int*)raw;
    bool ok64 = true;
    for (int b = 0; b < Bb && ok64; b++) {
        long long prev = -1;
        for (int p = 0; p < Pp; p++) {
            long long v = p64[b * Pp + p];
            if (v < 0 || v >= Ss || v <= prev) { ok64 = false; break; }
            prev = v;
        }
    }
    for (int i = 0; i < Bb * Pp; i++)
        g_seg[i] = ok64 ? (int)p64[i] : p32[i];
    long long po = 0, vo = 0;
    for (int bp = 0; bp < Bb * Pp; bp++) {
        int p = bp & 15;
        int s0 = g_seg[bp];
        int e0 = (p == Pp - 1) ? Ss : g_seg[bp + 1];
        int Lp = ((e0 - s0) + 31) & ~31;
        g_Lp[bp] = Lp;
        g_poff[bp] = po;
        g_voff[bp] = vo;
        po += (long long)Ss * Lp;
        vo += (long long)Dd * Lp;
    }
}

__global__ void sp_map() {
    int i = blockIdx.x * blockDim.x + threadIdx.x;
    if (i >= Bb * Ss) return;
    int b = i >> 11, s = i & (Ss - 1);
    int p = -1;
    #pragma unroll
    for (int j = 0; j < Pp; j++)
        if (s >= g_seg[b * Pp + j]) p = j;
    g_sp[i] = p;
}

__global__ void zero_vpad() {
    int bp = blockIdx.x;
    int p = bp & 15;
    int s0 = g_seg[bp];
    int e0 = (p == Pp - 1) ? Ss : g_seg[bp + 1];
    int L = e0 - s0, Lp = g_Lp[bp], pad = Lp - L;
    if (pad == 0) return;
    long long off = g_voff[bp];
    __half z = __float2half(0.f);
    for (int i = threadIdx.x; i < Dd * pad; i += blockDim.x) {
        int d = i / pad, k = L + i % pad;
        g_vf[off + (long long)d * Lp + k] = z;
    }
}

// ---------------- pre-split inputs ----------------------------------------------
__global__ void split_x(const float* __restrict__ x) {
    long i = (long)blockIdx.x * 256 + threadIdx.x;
    float4 v = ((const float4*)x)[i];
    __nv_bfloat16 h[4], l[4];
    split2(v.x, h[0], l[0]); split2(v.y, h[1], l[1]);
    split2(v.z, h[2], l[2]); split2(v.w, h[3], l[3]);
    *(uint2*)&g_xh[i * 4] = *(uint2*)h;
    *(uint2*)&g_xl[i * 4] = *(uint2*)l;
}

__global__ void transpose_w(const float* __restrict__ Wq, const float* __restrict__ Wk,
                            const float* __restrict__ Wv) {
    __shared__ float t[32][33];
    int z = blockIdx.z;
    const float* W = (z == 0) ? Wq : (z == 1) ? Wk : Wv;
    int x0 = blockIdx.x * 32, y0 = blockIdx.y * 32;
    int tx = threadIdx.x, ty = threadIdx.y;
    #pragma unroll
    for (int i = 0; i < 32; i += 8) t[ty + i][tx] = W[(y0 + ty + i) * Dd + x0 + tx];
    __syncthreads();
    #pragma unroll
    for (int i = 0; i < 32; i += 8) {
        float v = t[tx][ty + i];
        __nv_bfloat16 h, l;
        split2(v, h, l);
        long dst = (long)z * Dd * Dd + (long)(x0 + ty + i) * Dd + y0 + tx;
        g_wth[dst] = h;
        g_wtl[dst] = l;
    }
}

// ---------------- projection GEMM (x @ W^T-rows), block 128x256 ------------------
__global__ void __launch_bounds__(256, 1) proj_tc(const float* __restrict__ b0,
                                                  const float* __restrict__ b1,
                                                  const float* __restrict__ b2) {
    extern __shared__ char smx[];
    unsigned sbu = smem_u32(smx);
    const int tid = threadIdx.x, warp = tid >> 5, lane = tid & 31;
    const int wm = warp >> 2, wn = warp & 3;
    const int z = blockIdx.z;
    const int n0 = blockIdx.x * 256, m0 = blockIdx.y * 128;

    const __nv_bfloat16* Ah = g_xh + (long)m0 * Dd;
    const __nv_bfloat16* Al = g_xl + (long)m0 * Dd;
    const __nv_bfloat16* Bh = g_wth + (long)z * Dd * Dd + (long)n0 * Dd;
    const __nv_bfloat16* Bl = g_wtl + (long)z * Dd * Dd + (long)n0 * Dd;

    frag_c acc[4][4];
    #pragma unroll
    for (int i = 0; i < 4; i++)
        #pragma unroll
        for (int j = 0; j < 4; j++) wmma::fill_fragment(acc[i][j], 0.f);

    const int NC = Dd / 32;
    stage_ab(Ah, Al, Dd, Bh, Bl, Dd, sbu, tid);
    cp_commit();
    for (int c = 0; c < NC; c++) {
        cp_wait0();
        __syncthreads();
        if (c + 1 < NC) {
            int k = (c + 1) * 32;
            stage_ab(Ah + k, Al + k, Dd, Bh + k, Bl + k, Dd, sbu + ((c + 1) & 1) * STAGE_B, tid);
            cp_commit();
        }
        mma_chunk(acc, smx + (c & 1) * STAGE_B, wm, wn);
    }
    __syncthreads();

    const float* bias = (z == 0) ? b0 : (z == 1) ? b1 : b2;
    float* bounce = (float*)smx + warp * 320;        // 16x20 per warp
    #pragma unroll
    for (int i = 0; i < 4; i++)
        #pragma unroll
        for (int j = 0; j < 4; j++) {
            wmma::store_matrix_sync(bounce, acc[i][j], 20, wmma::mem_row_major);
            __syncwarp();
            int gm = m0 + wm * 64 + i * 16;
            int gn = n0 + wn * 64 + j * 16;
            if (z == 2) {
                int c = lane >> 1, rs = (lane & 1) * 8;
                int d = gn + c;
                float bi = bias[d];
                int bb = m0 >> 11;
                int sbase = (gm & (Ss - 1)) + rs;
                #pragma unroll
                for (int t = 0; t < 8; t++) {
                    int s = sbase + t;
                    int p = g_sp[bb * Ss + s];
                    if (p >= 0) {
                        int bpi = bb * Pp + p;
                        long long dst = g_voff[bpi] + (long long)d * g_Lp[bpi]
                                        + (s - g_seg[bpi]);
                        g_vf[dst] = __float2half(bounce[(rs + t) * 20 + c] + bi);
                    }
                }
            } else {
                int r = lane >> 1, cs = (lane & 1) * 8;
                __half hh[8];
                #pragma unroll
                for (int t = 0; t < 8; t++) {
                    float val = bounce[r * 20 + cs + t] + bias[gn + cs + t];
                    if (z == 0) val *= SCALE;
                    hh[t] = __float2half(val);
                }
                long dst = (long)(gm + r) * Dd + gn + cs;
                if (z == 0) *(uint4*)&g_qf[dst] = *(uint4*)hh;
                else        *(uint4*)&g_kf[dst] = *(uint4*)hh;
            }
            __syncwarp();
        }
}

// ---------------- scores GEMM: sc = (q*scale) @ k^T, fp16 single -----------------
__global__ void __launch_bounds__(256, 1) scores_tc() {
    extern __shared__ char smx[];
    unsigned sbu = smem_u32(smx);
    const int tid = threadIdx.x, warp = tid >> 5;
    const int wm = warp >> 2, wn = warp & 3;
    const int b = blockIdx.z;
    const int n0 = blockIdx.x * 256, m0 = blockIdx.y * 128;

    const __half* A = g_qf + ((long)b * Ss + m0) * Dd;
    const __half* B = g_kf + ((long)b * Ss + n0) * Dd;

    frag_c acc[4][4];
    #pragma unroll
    for (int i = 0; i < 4; i++)
        #pragma unroll
        for (int j = 0; j < 4; j++) wmma::fill_fragment(acc[i][j], 0.f);

    const int NC = Dd / 32;
    stage_h(A, Dd, B, Dd, sbu, tid);
    cp_commit();
    for (int c = 0; c < NC; c++) {
        cp_wait0();
        __syncthreads();
        if (c + 1 < NC) {
            int k = (c + 1) * 32;
            stage_h(A + k, Dd, B + k, Dd, sbu + ((c + 1) & 1) * H_STAGE, tid);
            cp_commit();
        }
        mma_chunk_h(acc, smx + (c & 1) * H_STAGE, wm, wn);
    }

    float* dst = g_sc + (long)b * Ss * Ss;
    #pragma unroll
    for (int i = 0; i < 4; i++)
        #pragma unroll
        for (int j = 0; j < 4; j++) {
            int gm = m0 + wm * 64 + i * 16;
            int gn = n0 + wn * 64 + j * 16;
            wmma::store_matrix_sync(&dst[(long)gm * Ss + gn], acc[i][j], Ss,
                                    wmma::mem_row_major);
        }
}

// ---------------- softmax stats -> padded P (fp16) -------------------------------
__global__ void stats_kernel() {
    const int wid = (blockIdx.x * blockDim.x + threadIdx.x) >> 5;
    const int lane = threadIdx.x & 31;
    const int q = wid & (Ss - 1);
    const int bp = wid / Ss;
    const int b = bp >> 4, p = bp & 15;
    const int s0 = g_seg[bp];
    const int e0 = (p == Pp - 1) ? Ss : g_seg[bp + 1];
    const int Lp = g_Lp[bp];
    const float* row = g_sc + ((long)b * Ss + q) * Ss;
    float mx = -1e30f;
    for (int k = s0 + lane; k < e0; k += 32) mx = fmaxf(mx, row[k]);
    #pragma unroll
    for (int o = 16; o; o >>= 1) mx = fmaxf(mx, __shfl_xor_sync(0xffffffffu, mx, o));
    float sum = 0.f;
    for (int k = s0 + lane; k < e0; k += 32) sum += __expf(row[k] - mx);
    #pragma unroll
    for (int o = 16; o; o >>= 1) sum += __shfl_xor_sync(0xffffffffu, sum, o);
    float inv = 1.0f / sum;
    long long po = g_poff[bp] + (long long)q * Lp;
    for (int k = s0 + lane; k < s0 + Lp; k += 32) {
        float pv = (k < e0) ? __expf(row[k] - mx) * inv : 0.f;
        g_pf[po + (k - s0)] = __float2half(pv);
    }
}

// ---------------- output GEMM: out[bp] = P @ V, fp16 single ----------------------
__global__ void __launch_bounds__(256, 1) out_tc(float* __restrict__ out) {
    extern __shared__ char smx[];
    unsigned sbu = smem_u32(smx);
    const int tid = threadIdx.x, warp = tid >> 5;
    const int wm = warp >> 2, wn = warp & 3;
    const int bp = blockIdx.z;
    const int Lp = g_Lp[bp];
    const int NC = Lp >> 5;
    const int n0 = blockIdx.x * 256, m0 = blockIdx.y * 128;

    const __half* A = g_pf + g_poff[bp] + (long long)m0 * Lp;
    const __half* B = g_vf + g_voff[bp] + (long long)n0 * Lp;

    frag_c acc[4][4];
    #pragma unroll
    for (int i = 0; i < 4; i++)
        #pragma unroll
        for (int j = 0; j < 4; j++) wmma::fill_fragment(acc[i][j], 0.f);

    stage_h(A, Lp, B, Lp, sbu, tid);
    cp_commit();
    for (int c = 0; c < NC; c++) {
        cp_wait0();
        __syncthreads();
        if (c + 1 < NC) {
            int k = (c + 1) * 32;
            stage_h(A + k, Lp, B + k, Lp, sbu + ((c + 1) & 1) * H_STAGE, tid);
            cp_commit();
        }
        mma_chunk_h(acc, smx + (c & 1) * H_STAGE, wm, wn);
    }

    float* dst = out + ((long)bp * Ss + m0) * Dd;
    #pragma unroll
    for (int i = 0; i < 4; i++)
        #pragma unroll
        for (int j = 0; j < 4; j++) {
            int rm = wm * 64 + i * 16;
            int gn = n0 + wn * 64 + j * 16;
            wmma::store_matrix_sync(&dst[(long)rm * Dd + gn], acc[i][j], Dd,
                                    wmma::mem_row_major);
        }
}

// ---------------- launch ----------------------------------------------------------
extern "C" void kernel_launch(void* const* d_in, const int* in_sizes, int n_in,
                              void* d_out, int out_size) {
    const float* x = (const float*)d_in[0];
    const void* pidx = d_in[1];
    const float* Wq = (const float*)d_in[2];
    const float* bq = (const float*)d_in[3];
    const float* Wk = (const float*)d_in[4];
    const float* bk = (const float*)d_in[5];
    const float* Wv = (const float*)d_in[6];
    const float* bv = (const float*)d_in[7];
    float* out = (float*)d_out;

    static int attr_done = 0;
    if (!attr_done) {
        cudaFuncSetAttribute(proj_tc, cudaFuncAttributeMaxDynamicSharedMemorySize, SMEM_BYTES);
        cudaFuncSetAttribute(scores_tc, cudaFuncAttributeMaxDynamicSharedMemorySize, H_SMEM);
        cudaFuncSetAttribute(out_tc, cudaFuncAttributeMaxDynamicSharedMemorySize, H_SMEM);
        attr_done = 1;
    }

    decode_idx<<<1, 1>>>(pidx);
    sp_map<<<(Bb * Ss) / 256, 256>>>();
    zero_vpad<<<Bb * Pp, 256>>>();
    split_x<<<(Bb * Ss * Dd / 4) / 256, 256>>>(x);

    dim3 tg(Dd / 32, Dd / 32, 3);
    transpose_w<<<tg, dim3(32, 8)>>>(Wq, Wk, Wv);

    dim3 pg(Dd / 256, (Bb * Ss) / 128, 3);           // 3 x 32 x 3
    proj_tc<<<pg, 256, SMEM_BYTES>>>(bq, bk, bv);

    dim3 sg(Ss / 256, Ss / 128, Bb);                 // 8 x 16 x 2
    scores_tc<<<sg, 256, H_SMEM>>>();

    stats_kernel<<<(Bb * Pp * Ss) / 8, 256>>>();

    dim3 og(Dd / 256, Ss / 128, Bb * Pp);            // 3 x 16 x 32
    out_tc<<<og, 256, H_SMEM>>>(out);
}

// round 11
// speedup vs baseline: 1.9910x; 1.2920x over previous
#include <cuda_runtime.h>
#include <cuda_fp16.h>
#include <mma.h>

using namespace nvcuda;

#define Bb 2
#define Ss 2048
#define Dd 768
#define Pp 16
#define SCALE 0.03608439182435161f   // 1/sqrt(768)

#define PSEG (Bb * Ss * (Ss + Pp * 32))   // padded P elems
#define VSEG (Bb * Dd * (Ss + Pp * 32))   // padded V elems

// ---------------- scratch (device globals) -------------------------------------
__device__ __align__(256) float g_sc[Bb * Ss * Ss];
__device__ __align__(256) __half g_xf[Bb * Ss * Dd];    // x, fp16
__device__ __align__(256) __half g_wtf[3 * Dd * Dd];    // W^T rows, fp16
__device__ __align__(256) __half g_qf[Bb * Ss * Dd];    // q (pre-scaled), fp16
__device__ __align__(256) __half g_kf[Bb * Ss * Dd];    // k, fp16
__device__ __align__(256) __half g_pf[PSEG];            // P, fp16
__device__ __align__(256) __half g_vf[VSEG];            // V, fp16
__device__ int g_seg[Bb * Pp];
__device__ int g_Lp[Bb * Pp];
__device__ long long g_poff[Bb * Pp];
__device__ long long g_voff[Bb * Pp];
__device__ int g_sp[Bb * Ss];

// ---------------- wmma types ----------------------------------------------------
typedef wmma::fragment<wmma::matrix_a, 16, 16, 16, __half, wmma::row_major> frag_ha;
typedef wmma::fragment<wmma::matrix_b, 16, 16, 16, __half, wmma::col_major> frag_hb;
typedef wmma::fragment<wmma::accumulator, 16, 16, 16, float> frag_c;

// Block tile 128(M) x 256(N), K-chunk 32. Warp tile 64x64, warps 2x4.
#define TLD 40                        // smem ld (elems): 80B rows
#define A_TILE 10240                  // 128 x TLD x 2B
#define H_STAGE 30720                 // A + B
#define H_SMEM 61440                  // 2 stages

// ---------------- helpers -------------------------------------------------------
__device__ __forceinline__ unsigned smem_u32(const void* p) {
    unsigned a;
    asm("{ .reg .u64 t; cvta.to.shared.u64 t, %1; cvt.u32.u64 %0, t; }" : "=r"(a) : "l"(p));
    return a;
}
#define CP16(daddr, gptr) \
    asm volatile("cp.async.cg.shared.global [%0], [%1], 16;" :: "r"(daddr), "l"(gptr) : "memory")
__device__ __forceinline__ void cp_commit() { asm volatile("cp.async.commit_group;" ::: "memory"); }
__device__ __forceinline__ void cp_wait0() { asm volatile("cp.async.wait_group 0;" ::: "memory"); }

// fp16 single stage: A(128 rows) + B(256 rows), pure 16B async copies
__device__ __forceinline__ void stage_h(const __half* A, long lda,
                                        const __half* B, long ldb,
                                        unsigned sb, int tid) {
    #pragma unroll
    for (int i = 0; i < 2; i++) {
        int ch = i * 256 + tid;
        int r = ch >> 2, c = (ch & 3) << 3;
        CP16(sb + (unsigned)(r * 80 + c * 2), A + (long)r * lda + c);
    }
    #pragma unroll
    for (int i = 0; i < 4; i++) {
        int ch = i * 256 + tid;
        int r = ch >> 2, c = (ch & 3) << 3;
        CP16(sb + A_TILE + (unsigned)(r * 80 + c * 2), B + (long)r * ldb + c);
    }
}

// fp16 MMA over one staged K=32 chunk; warp tile 64x64 at (wm, wn)
__device__ __forceinline__ void mma_chunk_h(frag_c (&acc)[4][4], const char* buf, int wm, int wn) {
    const __half* sA = (const __half*)buf;
    const __half* sB = (const __half*)(buf + A_TILE);
    #pragma unroll
    for (int ks = 0; ks < 2; ks++) {
        frag_ha a[4];
        frag_hb b[4];
        #pragma unroll
        for (int i = 0; i < 4; i++)
            wmma::load_matrix_sync(a[i], sA + (wm * 64 + i * 16) * TLD + ks * 16, TLD);
        #pragma unroll
        for (int j = 0; j < 4; j++)
            wmma::load_matrix_sync(b[j], sB + (wn * 64 + j * 16) * TLD + ks * 16, TLD);
        #pragma unroll
        for (int i = 0; i < 4; i++)
            #pragma unroll
            for (int j = 0; j < 4; j++)
                wmma::mma_sync(acc[i][j], a[i], b[j], acc[i][j]);
    }
}

// ---------------- decode + layout metadata --------------------------------------
__global__ void decode_idx(const void* __restrict__ raw) {
    const long long* p64 = (const long long*)raw;
    const int* p32 = (const int*)raw;
    bool ok64 = true;
    for (int b = 0; b < Bb && ok64; b++) {
        long long prev = -1;
        for (int p = 0; p < Pp; p++) {
            long long v = p64[b * Pp + p];
            if (v < 0 || v >= Ss || v <= prev) { ok64 = false; break; }
            prev = v;
        }
    }
    for (int i = 0; i < Bb * Pp; i++)
        g_seg[i] = ok64 ? (int)p64[i] : p32[i];
    long long po = 0, vo = 0;
    for (int bp = 0; bp < Bb * Pp; bp++) {
        int p = bp & 15;
        int s0 = g_seg[bp];
        int e0 = (p == Pp - 1) ? Ss : g_seg[bp + 1];
        int Lp = ((e0 - s0) + 31) & ~31;
        g_Lp[bp] = Lp;
        g_poff[bp] = po;
        g_voff[bp] = vo;
        po += (long long)Ss * Lp;
        vo += (long long)Dd * Lp;
    }
}

__global__ void sp_map() {
    int i = blockIdx.x * blockDim.x + threadIdx.x;
    if (i >= Bb * Ss) return;
    int b = i >> 11, s = i & (Ss - 1);
    int p = -1;
    #pragma unroll
    for (int j = 0; j < Pp; j++)
        if (s >= g_seg[b * Pp + j]) p = j;
    g_sp[i] = p;
}

__global__ void zero_vpad() {
    int bp = blockIdx.x;
    int p = bp & 15;
    int s0 = g_seg[bp];
    int e0 = (p == Pp - 1) ? Ss : g_seg[bp + 1];
    int L = e0 - s0, Lp = g_Lp[bp], pad = Lp - L;
    if (pad == 0) return;
    long long off = g_voff[bp];
    __half z = __float2half(0.f);
    for (int i = threadIdx.x; i < Dd * pad; i += blockDim.x) {
        int d = i / pad, k = L + i % pad;
        g_vf[off + (long long)d * Lp + k] = z;
    }
}

// ---------------- convert inputs to fp16 ------------------------------------------
__global__ void cvt_x(const float* __restrict__ x) {
    long i = (long)blockIdx.x * 256 + threadIdx.x;
    float4 v = ((const float4*)x)[i];
    __half h[4] = { __float2half(v.x), __float2half(v.y),
                    __float2half(v.z), __float2half(v.w) };
    *(uint2*)&g_xf[i * 4] = *(uint2*)h;
}

__global__ void transpose_w(const float* __restrict__ Wq, const float* __restrict__ Wk,
                            const float* __restrict__ Wv) {
    __shared__ float t[32][33];
    int z = blockIdx.z;
    const float* W = (z == 0) ? Wq : (z == 1) ? Wk : Wv;
    int x0 = blockIdx.x * 32, y0 = blockIdx.y * 32;
    int tx = threadIdx.x, ty = threadIdx.y;
    #pragma unroll
    for (int i = 0; i < 32; i += 8) t[ty + i][tx] = W[(y0 + ty + i) * Dd + x0 + tx];
    __syncthreads();
    #pragma unroll
    for (int i = 0; i < 32; i += 8)
        g_wtf[(long)z * Dd * Dd + (long)(x0 + ty + i) * Dd + y0 + tx] =
            __float2half(t[tx][ty + i]);
}

// ---------------- projection GEMM (x @ W^T-rows), fp16 single --------------------
__global__ void __launch_bounds__(256, 1) proj_tc(const float* __restrict__ b0,
                                                  const float* __restrict__ b1,
                                                  const float* __restrict__ b2) {
    extern __shared__ char smx[];
    unsigned sbu = smem_u32(smx);
    const int tid = threadIdx.x, warp = tid >> 5, lane = tid & 31;
    const int wm = warp >> 2, wn = warp & 3;
    const int z = blockIdx.z;
    const int n0 = blockIdx.x * 256, m0 = blockIdx.y * 128;

    const __half* A = g_xf + (long)m0 * Dd;
    const __half* B = g_wtf + (long)z * Dd * Dd + (long)n0 * Dd;

    frag_c acc[4][4];
    #pragma unroll
    for (int i = 0; i < 4; i++)
        #pragma unroll
        for (int j = 0; j < 4; j++) wmma::fill_fragment(acc[i][j], 0.f);

    const int NC = Dd / 32;
    stage_h(A, Dd, B, Dd, sbu, tid);
    cp_commit();
    for (int c = 0; c < NC; c++) {
        cp_wait0();
        __syncthreads();
        if (c + 1 < NC) {
            int k = (c + 1) * 32;
            stage_h(A + k, Dd, B + k, Dd, sbu + ((c + 1) & 1) * H_STAGE, tid);
            cp_commit();
        }
        mma_chunk_h(acc, smx + (c & 1) * H_STAGE, wm, wn);
    }
    __syncthreads();

    const float* bias = (z == 0) ? b0 : (z == 1) ? b1 : b2;
    float* bounce = (float*)smx + warp * 320;        // 16x20 per warp
    #pragma unroll
    for (int i = 0; i < 4; i++)
        #pragma unroll
        for (int j = 0; j < 4; j++) {
            wmma::store_matrix_sync(bounce, acc[i][j], 20, wmma::mem_row_major);
            __syncwarp();
            int gm = m0 + wm * 64 + i * 16;
            int gn = n0 + wn * 64 + j * 16;
            if (z == 2) {
                int c = lane >> 1, rs = (lane & 1) * 8;
                int d = gn + c;
                float bi = bias[d];
                int bb = m0 >> 11;
                int sbase = (gm & (Ss - 1)) + rs;
                #pragma unroll
                for (int t = 0; t < 8; t++) {
                    int s = sbase + t;
                    int p = g_sp[bb * Ss + s];
                    if (p >= 0) {
                        int bpi = bb * Pp + p;
                        long long dst = g_voff[bpi] + (long long)d * g_Lp[bpi]
                                        + (s - g_seg[bpi]);
                        g_vf[dst] = __float2half(bounce[(rs + t) * 20 + c] + bi);
                    }
                }
            } else {
                int r = lane >> 1, cs = (lane & 1) * 8;
                __half hh[8];
                #pragma unroll
                for (int t = 0; t < 8; t++) {
                    float val = bounce[r * 20 + cs + t] + bias[gn + cs + t];
                    if (z == 0) val *= SCALE;
                    hh[t] = __float2half(val);
                }
                long dst = (long)(gm + r) * Dd + gn + cs;
                if (z == 0) *(uint4*)&g_qf[dst] = *(uint4*)hh;
                else        *(uint4*)&g_kf[dst] = *(uint4*)hh;
            }
            __syncwarp();
        }
}

// ---------------- scores GEMM: sc = (q*scale) @ k^T, fp16 single -----------------
__global__ void __launch_bounds__(256, 1) scores_tc() {
    extern __shared__ char smx[];
    unsigned sbu = smem_u32(smx);
    const int tid = threadIdx.x, warp = tid >> 5;
    const int wm = warp >> 2, wn = warp & 3;
    const int b = blockIdx.z;
    const int n0 = blockIdx.x * 256, m0 = blockIdx.y * 128;

    const __half* A = g_qf + ((long)b * Ss + m0) * Dd;
    const __half* B = g_kf + ((long)b * Ss + n0) * Dd;

    frag_c acc[4][4];
    #pragma unroll
    for (int i = 0; i < 4; i++)
        #pragma unroll
        for (int j = 0; j < 4; j++) wmma::fill_fragment(acc[i][j], 0.f);

    const int NC = Dd / 32;
    stage_h(A, Dd, B, Dd, sbu, tid);
    cp_commit();
    for (int c = 0; c < NC; c++) {
        cp_wait0();
        __syncthreads();
        if (c + 1 < NC) {
            int k = (c + 1) * 32;
            stage_h(A + k, Dd, B + k, Dd, sbu + ((c + 1) & 1) * H_STAGE, tid);
            cp_commit();
        }
        mma_chunk_h(acc, smx + (c & 1) * H_STAGE, wm, wn);
    }

    float* dst = g_sc + (long)b * Ss * Ss;
    #pragma unroll
    for (int i = 0; i < 4; i++)
        #pragma unroll
        for (int j = 0; j < 4; j++) {
            int gm = m0 + wm * 64 + i * 16;
            int gn = n0 + wn * 64 + j * 16;
            wmma::store_matrix_sync(&dst[(long)gm * Ss + gn], acc[i][j], Ss,
                                    wmma::mem_row_major);
        }
}

// ---------------- softmax stats -> padded P (fp16) -------------------------------
__global__ void stats_kernel() {
    const int wid = (blockIdx.x * blockDim.x + threadIdx.x) >> 5;
    const int lane = threadIdx.x & 31;
    const int q = wid & (Ss - 1);
    const int bp = wid / Ss;
    const int b = bp >> 4, p = bp & 15;
    const int s0 = g_seg[bp];
    const int e0 = (p == Pp - 1) ? Ss : g_seg[bp + 1];
    const int Lp = g_Lp[bp];
    const float* row = g_sc + ((long)b * Ss + q) * Ss;
    float mx = -1e30f;
    for (int k = s0 + lane; k < e0; k += 32) mx = fmaxf(mx, row[k]);
    #pragma unroll
    for (int o = 16; o; o >>= 1) mx = fmaxf(mx, __shfl_xor_sync(0xffffffffu, mx, o));
    float sum = 0.f;
    for (int k = s0 + lane; k < e0; k += 32) sum += __expf(row[k] - mx);
    #pragma unroll
    for (int o = 16; o; o >>= 1) sum += __shfl_xor_sync(0xffffffffu, sum, o);
    float inv = 1.0f / sum;
    long long po = g_poff[bp] + (long long)q * Lp;
    for (int k = s0 + lane; k < s0 + Lp; k += 32) {
        float pv = (k < e0) ? __expf(row[k] - mx) * inv : 0.f;
        g_pf[po + (k - s0)] = __float2half(pv);
    }
}

// ---------------- output GEMM: out[bp] = P @ V, fp16 single ----------------------
__global__ void __launch_bounds__(256, 1) out_tc(float* __restrict__ out) {
    extern __shared__ char smx[];
    unsigned sbu = smem_u32(smx);
    const int tid = threadIdx.x, warp = tid >> 5;
    const int wm = warp >> 2, wn = warp & 3;
    const int bp = blockIdx.z;
    const int Lp = g_Lp[bp];
    const int NC = Lp >> 5;
    const int n0 = blockIdx.x * 256, m0 = blockIdx.y * 128;

    const __half* A = g_pf + g_poff[bp] + (long long)m0 * Lp;
    const __half* B = g_vf + g_voff[bp] + (long long)n0 * Lp;

    frag_c acc[4][4];
    #pragma unroll
    for (int i = 0; i < 4; i++)
        #pragma unroll
        for (int j = 0; j < 4; j++) wmma::fill_fragment(acc[i][j], 0.f);

    stage_h(A, Lp, B, Lp, sbu, tid);
    cp_commit();
    for (int c = 0; c < NC; c++) {
        cp_wait0();
        __syncthreads();
        if (c + 1 < NC) {
            int k = (c + 1) * 32;
            stage_h(A + k, Lp, B + k, Lp, sbu + ((c + 1) & 1) * H_STAGE, tid);
            cp_commit();
        }
        mma_chunk_h(acc, smx + (c & 1) * H_STAGE, wm, wn);
    }

    float* dst = out + ((long)bp * Ss + m0) * Dd;
    #pragma unroll
    for (int i = 0; i < 4; i++)
        #pragma unroll
        for (int j = 0; j < 4; j++) {
            int rm = wm * 64 + i * 16;
            int gn = n0 + wn * 64 + j * 16;
            wmma::store_matrix_sync(&dst[(long)rm * Dd + gn], acc[i][j], Dd,
                                    wmma::mem_row_major);
        }
}

// ---------------- launch ----------------------------------------------------------
extern "C" void kernel_launch(void* const* d_in, const int* in_sizes, int n_in,
                              void* d_out, int out_size) {
    const float* x = (const float*)d_in[0];
    const void* pidx = d_in[1];
    const float* Wq = (const float*)d_in[2];
    const float* bq = (const float*)d_in[3];
    const float* Wk = (const float*)d_in[4];
    const float* bk = (const float*)d_in[5];
    const float* Wv = (const float*)d_in[6];
    const float* bv = (const float*)d_in[7];
    float* out = (float*)d_out;

    static int attr_done = 0;
    if (!attr_done) {
        cudaFuncSetAttribute(proj_tc, cudaFuncAttributeMaxDynamicSharedMemorySize, H_SMEM);
        cudaFuncSetAttribute(scores_tc, cudaFuncAttributeMaxDynamicSharedMemorySize, H_SMEM);
        cudaFuncSetAttribute(out_tc, cudaFuncAttributeMaxDynamicSharedMemorySize, H_SMEM);
        attr_done = 1;
    }

    decode_idx<<<1, 1>>>(pidx);
    sp_map<<<(Bb * Ss) / 256, 256>>>();
    zero_vpad<<<Bb * Pp, 256>>>();
    cvt_x<<<(Bb * Ss * Dd / 4) / 256, 256>>>(x);

    dim3 tg(Dd / 32, Dd / 32, 3);
    transpose_w<<<tg, dim3(32, 8)>>>(Wq, Wk, Wv);

    dim3 pg(Dd / 256, (Bb * Ss) / 128, 3);           // 3 x 32 x 3
    proj_tc<<<pg, 256, H_SMEM>>>(bq, bk, bv);

    dim3 sg(Ss / 256, Ss / 128, Bb);                 // 8 x 16 x 2
    scores_tc<<<sg, 256, H_SMEM>>>();

    stats_kernel<<<(Bb * Pp * Ss) / 8, 256>>>();

    dim3 og(Dd / 256, Ss / 128, Bb * Pp);            // 3 x 16 x 32
    out_tc<<<og, 256, H_SMEM>>>(out);
}

// round 12
// speedup vs baseline: 1.9928x; 1.0009x over previous
#include <cuda_runtime.h>
#include <cuda_fp16.h>
#include <mma.h>

using namespace nvcuda;

#define Bb 2
#define Ss 2048
#define Dd 768
#define Pp 16
#define SCALE 0.03608439182435161f   // 1/sqrt(768)

#define PSEG (Bb * Ss * (Ss + Pp * 64))   // padded P elems (Lp aligned 64)
#define VSEG (Bb * Dd * (Ss + Pp * 64))   // padded V elems

// ---------------- scratch (device globals) -------------------------------------
__device__ __align__(256) float g_sc[Bb * Ss * Ss];
__device__ __align__(256) __half g_xf[Bb * Ss * Dd];    // x, fp16
__device__ __align__(256) __half g_wtf[3 * Dd * Dd];    // W^T rows, fp16
__device__ __align__(256) __half g_qf[Bb * Ss * Dd];    // q (pre-scaled), fp16
__device__ __align__(256) __half g_kf[Bb * Ss * Dd];    // k, fp16
__device__ __align__(256) __half g_pf[PSEG];            // P, fp16
__device__ __align__(256) __half g_vf[VSEG];            // V, fp16
__device__ int g_seg[Bb * Pp];
__device__ int g_Lp[Bb * Pp];
__device__ long long g_poff[Bb * Pp];
__device__ long long g_voff[Bb * Pp];
__device__ int g_sp[Bb * Ss];

// ---------------- wmma types ----------------------------------------------------
typedef wmma::fragment<wmma::matrix_a, 16, 16, 16, __half, wmma::row_major> frag_ha;
typedef wmma::fragment<wmma::matrix_b, 16, 16, 16, __half, wmma::col_major> frag_hb;
typedef wmma::fragment<wmma::accumulator, 16, 16, 16, float> frag_c;

// Block tile 128(M) x 256(N), K-chunk 64. Warp tile 64x64, warps 2x4.
#define TLD 72                        // smem ld (elems): 144B rows
#define A_TILE 18432                  // 128 x TLD x 2B
#define H_STAGE 55296                 // A + B (B = 256 x TLD x 2B)
#define H_SMEM 110592                 // 2 stages

// ---------------- helpers -------------------------------------------------------
__device__ __forceinline__ unsigned smem_u32(const void* p) {
    unsigned a;
    asm("{ .reg .u64 t; cvta.to.shared.u64 t, %1; cvt.u32.u64 %0, t; }" : "=r"(a) : "l"(p));
    return a;
}
#define CP16(daddr, gptr) \
    asm volatile("cp.async.cg.shared.global [%0], [%1], 16;" :: "r"(daddr), "l"(gptr) : "memory")
__device__ __forceinline__ void cp_commit() { asm volatile("cp.async.commit_group;" ::: "memory"); }
__device__ __forceinline__ void cp_wait0() { asm volatile("cp.async.wait_group 0;" ::: "memory"); }

// fp16 stage, K=64 chunk: A(128 rows, 128B each) + B(256 rows), 16B async copies
__device__ __forceinline__ void stage_h(const __half* A, long lda,
                                        const __half* B, long ldb,
                                        unsigned sb, int tid) {
    #pragma unroll
    for (int i = 0; i < 4; i++) {
        int ch = i * 256 + tid;              // 0..1023
        int r = ch >> 3, c16 = ch & 7;
        CP16(sb + (unsigned)(r * 144 + c16 * 16), A + (long)r * lda + c16 * 8);
    }
    #pragma unroll
    for (int i = 0; i < 8; i++) {
        int ch = i * 256 + tid;              // 0..2047
        int r = ch >> 3, c16 = ch & 7;
        CP16(sb + A_TILE + (unsigned)(r * 144 + c16 * 16), B + (long)r * ldb + c16 * 8);
    }
}

// fp16 MMA over one staged K=64 chunk; warp tile 64x64 at (wm, wn)
__device__ __forceinline__ void mma_chunk_h(frag_c (&acc)[4][4], const char* buf, int wm, int wn) {
    const __half* sA = (const __half*)buf;
    const __half* sB = (const __half*)(buf + A_TILE);
    #pragma unroll
    for (int ks = 0; ks < 4; ks++) {
        frag_ha a[4];
        frag_hb b[4];
        #pragma unroll
        for (int i = 0; i < 4; i++)
            wmma::load_matrix_sync(a[i], sA + (wm * 64 + i * 16) * TLD + ks * 16, TLD);
        #pragma unroll
        for (int j = 0; j < 4; j++)
            wmma::load_matrix_sync(b[j], sB + (wn * 64 + j * 16) * TLD + ks * 16, TLD);
        #pragma unroll
        for (int i = 0; i < 4; i++)
            #pragma unroll
            for (int j = 0; j < 4; j++)
                wmma::mma_sync(acc[i][j], a[i], b[j], acc[i][j]);
    }
}

// ---------------- decode + sp_map (one block) ------------------------------------
__global__ void decode_idx(const void* __restrict__ raw) {
    if (threadIdx.x == 0) {
        const long long* p64 = (const long long*)raw;
        const int* p32 = (const int*)raw;
        bool ok64 = true;
        for (int b = 0; b < Bb && ok64; b++) {
            long long prev = -1;
            for (int p = 0; p < Pp; p++) {
                long long v = p64[b * Pp + p];
                if (v < 0 || v >= Ss || v <= prev) { ok64 = false; break; }
                prev = v;
            }
        }
        for (int i = 0; i < Bb * Pp; i++)
            g_seg[i] = ok64 ? (int)p64[i] : p32[i];
        long long po = 0, vo = 0;
        for (int bp = 0; bp < Bb * Pp; bp++) {
            int p = bp & 15;
            int s0 = g_seg[bp];
            int e0 = (p == Pp - 1) ? Ss : g_seg[bp + 1];
            int Lp = ((e0 - s0) + 63) & ~63;
            g_Lp[bp] = Lp;
            g_poff[bp] = po;
            g_voff[bp] = vo;
            po += (long long)Ss * Lp;
            vo += (long long)Dd * Lp;
        }
    }
    __syncthreads();
    for (int i = threadIdx.x; i < Bb * Ss; i += blockDim.x) {
        int b = i >> 11, s = i & (Ss - 1);
        int p = -1;
        #pragma unroll
        for (int j = 0; j < Pp; j++)
            if (s >= g_seg[b * Pp + j]) p = j;
        g_sp[i] = p;
    }
}

__global__ void zero_vpad() {
    int bp = blockIdx.x;
    int p = bp & 15;
    int s0 = g_seg[bp];
    int e0 = (p == Pp - 1) ? Ss : g_seg[bp + 1];
    int L = e0 - s0, Lp = g_Lp[bp], pad = Lp - L;
    if (pad == 0) return;
    long long off = g_voff[bp];
    __half z = __float2half(0.f);
    for (int i = threadIdx.x; i < Dd * pad; i += blockDim.x) {
        int d = i / pad, k = L + i % pad;
        g_vf[off + (long long)d * Lp + k] = z;
    }
}

// ---------------- convert inputs to fp16 ------------------------------------------
__global__ void cvt_x(const float* __restrict__ x) {
    long i = (long)blockIdx.x * 256 + threadIdx.x;
    float4 v = ((const float4*)x)[i];
    __half h[4] = { __float2half(v.x), __float2half(v.y),
                    __float2half(v.z), __float2half(v.w) };
    *(uint2*)&g_xf[i * 4] = *(uint2*)h;
}

__global__ void transpose_w(const float* __restrict__ Wq, const float* __restrict__ Wk,
                            const float* __restrict__ Wv) {
    __shared__ float t[32][33];
    int z = blockIdx.z;
    const float* W = (z == 0) ? Wq : (z == 1) ? Wk : Wv;
    int x0 = blockIdx.x * 32, y0 = blockIdx.y * 32;
    int tx = threadIdx.x, ty = threadIdx.y;
    #pragma unroll
    for (int i = 0; i < 32; i += 8) t[ty + i][tx] = W[(y0 + ty + i) * Dd + x0 + tx];
    __syncthreads();
    #pragma unroll
    for (int i = 0; i < 32; i += 8)
        g_wtf[(long)z * Dd * Dd + (long)(x0 + ty + i) * Dd + y0 + tx] =
            __float2half(t[tx][ty + i]);
}

// ---------------- projection GEMM (x @ W^T-rows), fp16 single --------------------
__global__ void __launch_bounds__(256, 1) proj_tc(const float* __restrict__ b0,
                                                  const float* __restrict__ b1,
                                                  const float* __restrict__ b2) {
    extern __shared__ char smx[];
    unsigned sbu = smem_u32(smx);
    const int tid = threadIdx.x, warp = tid >> 5, lane = tid & 31;
    const int wm = warp >> 2, wn = warp & 3;
    const int z = blockIdx.z;
    const int n0 = blockIdx.x * 256, m0 = blockIdx.y * 128;

    const __half* A = g_xf + (long)m0 * Dd;
    const __half* B = g_wtf + (long)z * Dd * Dd + (long)n0 * Dd;

    frag_c acc[4][4];
    #pragma unroll
    for (int i = 0; i < 4; i++)
        #pragma unroll
        for (int j = 0; j < 4; j++) wmma::fill_fragment(acc[i][j], 0.f);

    const int NC = Dd / 64;
    stage_h(A, Dd, B, Dd, sbu, tid);
    cp_commit();
    for (int c = 0; c < NC; c++) {
        cp_wait0();
        __syncthreads();
        if (c + 1 < NC) {
            int k = (c + 1) * 64;
            stage_h(A + k, Dd, B + k, Dd, sbu + ((c + 1) & 1) * H_STAGE, tid);
            cp_commit();
        }
        mma_chunk_h(acc, smx + (c & 1) * H_STAGE, wm, wn);
    }
    __syncthreads();

    const float* bias = (z == 0) ? b0 : (z == 1) ? b1 : b2;
    float* bounce = (float*)smx + warp * 320;        // 16x20 per warp
    #pragma unroll
    for (int i = 0; i < 4; i++)
        #pragma unroll
        for (int j = 0; j < 4; j++) {
            wmma::store_matrix_sync(bounce, acc[i][j], 20, wmma::mem_row_major);
            __syncwarp();
            int gm = m0 + wm * 64 + i * 16;
            int gn = n0 + wn * 64 + j * 16;
            if (z == 2) {
                int c = lane >> 1, rs = (lane & 1) * 8;
                int d = gn + c;
                float bi = bias[d];
                int bb = m0 >> 11;
                int sbase = (gm & (Ss - 1)) + rs;
                #pragma unroll
                for (int t = 0; t < 8; t++) {
                    int s = sbase + t;
                    int p = g_sp[bb * Ss + s];
                    if (p >= 0) {
                        int bpi = bb * Pp + p;
                        long long dst = g_voff[bpi] + (long long)d * g_Lp[bpi]
                                        + (s - g_seg[bpi]);
                        g_vf[dst] = __float2half(bounce[(rs + t) * 20 + c] + bi);
                    }
                }
            } else {
                int r = lane >> 1, cs = (lane & 1) * 8;
                __half hh[8];
                #pragma unroll
                for (int t = 0; t < 8; t++) {
                    float val = bounce[r * 20 + cs + t] + bias[gn + cs + t];
                    if (z == 0) val *= SCALE;
                    hh[t] = __float2half(val);
                }
                long dst = (long)(gm + r) * Dd + gn + cs;
                if (z == 0) *(uint4*)&g_qf[dst] = *(uint4*)hh;
                else        *(uint4*)&g_kf[dst] = *(uint4*)hh;
            }
            __syncwarp();
        }
}

// ---------------- scores GEMM: sc = (q*scale) @ k^T, fp16 single -----------------
__global__ void __launch_bounds__(256, 1) scores_tc() {
    extern __shared__ char smx[];
    unsigned sbu = smem_u32(smx);
    const int tid = threadIdx.x, warp = tid >> 5;
    const int wm = warp >> 2, wn = warp & 3;
    const int b = blockIdx.z;
    const int n0 = blockIdx.x * 256, m0 = blockIdx.y * 128;

    const __half* A = g_qf + ((long)b * Ss + m0) * Dd;
    const __half* B = g_kf + ((long)b * Ss + n0) * Dd;

    frag_c acc[4][4];
    #pragma unroll
    for (int i = 0; i < 4; i++)
        #pragma unroll
        for (int j = 0; j < 4; j++) wmma::fill_fragment(acc[i][j], 0.f);

    const int NC = Dd / 64;
    stage_h(A, Dd, B, Dd, sbu, tid);
    cp_commit();
    for (int c = 0; c < NC; c++) {
        cp_wait0();
        __syncthreads();
        if (c + 1 < NC) {
            int k = (c + 1) * 64;
            stage_h(A + k, Dd, B + k, Dd, sbu + ((c + 1) & 1) * H_STAGE, tid);
            cp_commit();
        }
        mma_chunk_h(acc, smx + (c & 1) * H_STAGE, wm, wn);
    }

    float* dst = g_sc + (long)b * Ss * Ss;
    #pragma unroll
    for (int i = 0; i < 4; i++)
        #pragma unroll
        for (int j = 0; j < 4; j++) {
            int gm = m0 + wm * 64 + i * 16;
            int gn = n0 + wn * 64 + j * 16;
            wmma::store_matrix_sync(&dst[(long)gm * Ss + gn], acc[i][j], Ss,
                                    wmma::mem_row_major);
        }
}

// ---------------- softmax: single-exp, smem-cached -> padded P (fp16) ------------
// 8 warps/block, one (bp, q) row per warp; exp cached in smem, written once.
__global__ void __launch_bounds__(256) stats_kernel() {
    __shared__ __half cache[8][Ss];
    const int w = threadIdx.x >> 5;
    const int lane = threadIdx.x & 31;
    const int wid = blockIdx.x * 8 + w;
    const int q = wid & (Ss - 1);
    const int bp = wid / Ss;
    const int b = bp >> 4, p = bp & 15;
    const int s0 = g_seg[bp];
    const int e0 = (p == Pp - 1) ? Ss : g_seg[bp + 1];
    const int Lp = g_Lp[bp];
    const float* row = g_sc + ((long)b * Ss + q) * Ss;
    float mx = -1e30f;
    for (int k = s0 + lane; k < e0; k += 32) mx = fmaxf(mx, row[k]);
    #pragma unroll
    for (int o = 16; o; o >>= 1) mx = fmaxf(mx, __shfl_xor_sync(0xffffffffu, mx, o));
    float sum = 0.f;
    for (int k = s0 + lane; k < s0 + Lp; k += 32) {
        float e = (k < e0) ? __expf(row[k] - mx) : 0.f;
        cache[w][k - s0] = __float2half(e);
        sum += e;
    }
    #pragma unroll
    for (int o = 16; o; o >>= 1) sum += __shfl_xor_sync(0xffffffffu, sum, o);
    float inv = 1.0f / sum;
    long long po = g_poff[bp] + (long long)q * Lp;
    // vectorized write: each lane handles 2 adjacent elems (Lp multiple of 64)
    for (int k = lane * 2; k < Lp; k += 64) {
        float2 e2 = __half22float2(*(const __half2*)&cache[w][k]);
        __half2 o2 = __floats2half2_rn(e2.x * inv, e2.y * inv);
        *(__half2*)&g_pf[po + k] = o2;
    }
}

// ---------------- output GEMM: out[bp] = P @ V, fp16 single ----------------------
__global__ void __launch_bounds__(256, 1) out_tc(float* __restrict__ out) {
    extern __shared__ char smx[];
    unsigned sbu = smem_u32(smx);
    const int tid = threadIdx.x, warp = tid >> 5;
    const int wm = warp >> 2, wn = warp & 3;
    const int bp = blockIdx.z;
    const int Lp = g_Lp[bp];
    const int NC = Lp >> 6;
    const int n0 = blockIdx.x * 256, m0 = blockIdx.y * 128;

    const __half* A = g_pf + g_poff[bp] + (long long)m0 * Lp;
    const __half* B = g_vf + g_voff[bp] + (long long)n0 * Lp;

    frag_c acc[4][4];
    #pragma unroll
    for (int i = 0; i < 4; i++)
        #pragma unroll
        for (int j = 0; j < 4; j++) wmma::fill_fragment(acc[i][j], 0.f);

    stage_h(A, Lp, B, Lp, sbu, tid);
    cp_commit();
    for (int c = 0; c < NC; c++) {
        cp_wait0();
        __syncthreads();
        if (c + 1 < NC) {
            int k = (c + 1) * 64;
            stage_h(A + k, Lp, B + k, Lp, sbu + ((c + 1) & 1) * H_STAGE, tid);
            cp_commit();
        }
        mma_chunk_h(acc, smx + (c & 1) * H_STAGE, wm, wn);
    }

    float* dst = out + ((long)bp * Ss + m0) * Dd;
    #pragma unroll
    for (int i = 0; i < 4; i++)
        #pragma unroll
        for (int j = 0; j < 4; j++) {
            int rm = wm * 64 + i * 16;
            int gn = n0 + wn * 64 + j * 16;
            wmma::store_matrix_sync(&dst[(long)rm * Dd + gn], acc[i][j], Dd,
                                    wmma::mem_row_major);
        }
}

// ---------------- launch ----------------------------------------------------------
extern "C" void kernel_launch(void* const* d_in, const int* in_sizes, int n_in,
                              void* d_out, int out_size) {
    const float* x = (const float*)d_in[0];
    const void* pidx = d_in[1];
    const float* Wq = (const float*)d_in[2];
    const float* bq = (const float*)d_in[3];
    const float* Wk = (const float*)d_in[4];
    const float* bk = (const float*)d_in[5];
    const float* Wv = (const float*)d_in[6];
    const float* bv = (const float*)d_in[7];
    float* out = (float*)d_out;

    static int attr_done = 0;
    if (!attr_done) {
        cudaFuncSetAttribute(proj_tc, cudaFuncAttributeMaxDynamicSharedMemorySize, H_SMEM);
        cudaFuncSetAttribute(scores_tc, cudaFuncAttributeMaxDynamicSharedMemorySize, H_SMEM);
        cudaFuncSetAttribute(out_tc, cudaFuncAttributeMaxDynamicSharedMemorySize, H_SMEM);
        attr_done = 1;
    }

    decode_idx<<<1, 256>>>(pidx);
    zero_vpad<<<Bb * Pp, 256>>>();
    cvt_x<<<(Bb * Ss * Dd / 4) / 256, 256>>>(x);

    dim3 tg(Dd / 32, Dd / 32, 3);
    transpose_w<<<tg, dim3(32, 8)>>>(Wq, Wk, Wv);

    dim3 pg(Dd / 256, (Bb * Ss) / 128, 3);           // 3 x 32 x 3
    proj_tc<<<pg, 256, H_SMEM>>>(bq, bk, bv);

    dim3 sg(Ss / 256, Ss / 128, Bb);                 // 8 x 16 x 2
    scores_tc<<<sg, 256, H_SMEM>>>();

    stats_kernel<<<(Bb * Pp * Ss) / 8, 256>>>();

    dim3 og(Dd / 256, Ss / 128, Bb * Pp);            // 3 x 16 x 32
    out_tc<<<og, 256, H_SMEM>>>(out);
}

// round 13
// speedup vs baseline: 2.3715x; 1.1900x over previous
#include <cuda_runtime.h>
#include <cuda_fp16.h>
#include <mma.h>

using namespace nvcuda;

#define Bb 2
#define Ss 2048
#define Dd 768
#define Pp 16
#define SCALE 0.03608439182435161f   // 1/sqrt(768)

#define SVT (Ss + 64)                     // vt row stride (slack for over-read)
#define PSEG (Bb * Ss * (Ss + Pp * 128))  // padded P elems (front+back pad)

// ---------------- scratch (device globals) -------------------------------------
__device__ __align__(256) float g_sc[Bb * Ss * Ss];
__device__ __align__(256) __half g_xf[Bb * Ss * Dd];    // x, fp16
__device__ __align__(256) __half g_wtf[3 * Dd * Dd];    // W^T rows, fp16
__device__ __align__(256) __half g_qf[Bb * Ss * Dd];    // q (pre-scaled), fp16
__device__ __align__(256) __half g_kf[Bb * Ss * Dd];    // k, fp16
__device__ __align__(256) __half g_pf[PSEG];            // P, fp16 (zero-padded)
__device__ __align__(256) __half g_vt[Bb * Dd * SVT];   // v transposed [b][d][s]
__device__ int g_seg[Bb * Pp];                          // true segment starts
__device__ int g_s0a[Bb * Pp];                          // aligned-down starts
__device__ int g_Lp[Bb * Pp];                           // padded lengths (mult 64)
__device__ long long g_poff[Bb * Pp];

// ---------------- wmma types ----------------------------------------------------
typedef wmma::fragment<wmma::matrix_a, 16, 16, 16, __half, wmma::row_major> frag_ha;
typedef wmma::fragment<wmma::matrix_b, 16, 16, 16, __half, wmma::col_major> frag_hb;
typedef wmma::fragment<wmma::accumulator, 16, 16, 16, float> frag_c;

// Block tile 128(M) x 256(N), K-chunk 64. Warp tile 64x64, warps 2x4. 3 stages.
#define TLD 72                        // smem ld (elems): 144B rows
#define A_TILE 18432                  // 128 x TLD x 2B
#define H_STAGE 55296                 // A + B (B = 256 x TLD x 2B)
#define H_SMEM 165888                 // 3 stages

// ---------------- helpers -------------------------------------------------------
__device__ __forceinline__ unsigned smem_u32(const void* p) {
    unsigned a;
    asm("{ .reg .u64 t; cvta.to.shared.u64 t, %1; cvt.u32.u64 %0, t; }" : "=r"(a) : "l"(p));
    return a;
}
#define CP16(daddr, gptr) \
    asm volatile("cp.async.cg.shared.global [%0], [%1], 16;" :: "r"(daddr), "l"(gptr) : "memory")
__device__ __forceinline__ void cp_commit() { asm volatile("cp.async.commit_group;" ::: "memory"); }
__device__ __forceinline__ void cp_wait0() { asm volatile("cp.async.wait_group 0;" ::: "memory"); }
__device__ __forceinline__ void cp_wait1() { asm volatile("cp.async.wait_group 1;" ::: "memory"); }

// fp16 stage, K=64 chunk: A(128 rows, 128B each) + B(256 rows), 16B async copies
__device__ __forceinline__ void stage_h(const __half* A, long lda,
                                        const __half* B, long ldb,
                                        unsigned sb, int tid) {
    #pragma unroll
    for (int i = 0; i < 4; i++) {
        int ch = i * 256 + tid;              // 0..1023
        int r = ch >> 3, c16 = ch & 7;
        CP16(sb + (unsigned)(r * 144 + c16 * 16), A + (long)r * lda + c16 * 8);
    }
    #pragma unroll
    for (int i = 0; i < 8; i++) {
        int ch = i * 256 + tid;              // 0..2047
        int r = ch >> 3, c16 = ch & 7;
        CP16(sb + A_TILE + (unsigned)(r * 144 + c16 * 16), B + (long)r * ldb + c16 * 8);
    }
}

// fp16 MMA over one staged K=64 chunk; warp tile 64x64 at (wm, wn)
__device__ __forceinline__ void mma_chunk_h(frag_c (&acc)[4][4], const char* buf, int wm, int wn) {
    const __half* sA = (const __half*)buf;
    const __half* sB = (const __half*)(buf + A_TILE);
    #pragma unroll
    for (int ks = 0; ks < 4; ks++) {
        frag_ha a[4];
        frag_hb b[4];
        #pragma unroll
        for (int i = 0; i < 4; i++)
            wmma::load_matrix_sync(a[i], sA + (wm * 64 + i * 16) * TLD + ks * 16, TLD);
        #pragma unroll
        for (int j = 0; j < 4; j++)
            wmma::load_matrix_sync(b[j], sB + (wn * 64 + j * 16) * TLD + ks * 16, TLD);
        #pragma unroll
        for (int i = 0; i < 4; i++)
            #pragma unroll
            for (int j = 0; j < 4; j++)
                wmma::mma_sync(acc[i][j], a[i], b[j], acc[i][j]);
    }
}

// 3-stage pipelined GEMM mainloop over NC K=64 chunks
#define GEMM_LOOP(Ap, lda, Bp, ldb, NC)                                          \
    stage_h(Ap, lda, Bp, ldb, sbu, tid);                                         \
    cp_commit();                                                                 \
    if ((NC) > 1) { stage_h((Ap) + 64, lda, (Bp) + 64, ldb, sbu + H_STAGE, tid); \
                    cp_commit(); }                                               \
    for (int c = 0; c < (NC); c++) {                                             \
        if (c + 2 < (NC)) cp_wait1(); else cp_wait0();                           \
        __syncthreads();                                                         \
        if (c + 2 < (NC)) {                                                      \
            long kk = (long)(c + 2) * 64;                                        \
            stage_h((Ap) + kk, lda, (Bp) + kk, ldb,                              \
                    sbu + (unsigned)((c + 2) % 3) * H_STAGE, tid);               \
            cp_commit();                                                         \
        }                                                                        \
        mma_chunk_h(acc, smx + (c % 3) * H_STAGE, wm, wn);                       \
    }

// ---------------- decode patch indices + layout ----------------------------------
__global__ void decode_idx(const void* __restrict__ raw) {
    const long long* p64 = (const long long*)raw;
    const int* p32 = (const int*)raw;
    bool ok64 = true;
    for (int b = 0; b < Bb && ok64; b++) {
        long long prev = -1;
        for (int p = 0; p < Pp; p++) {
            long long v = p64[b * Pp + p];
            if (v < 0 || v >= Ss || v <= prev) { ok64 = false; break; }
            prev = v;
        }
    }
    for (int i = 0; i < Bb * Pp; i++)
        g_seg[i] = ok64 ? (int)p64[i] : p32[i];
    long long po = 0;
    for (int bp = 0; bp < Bb * Pp; bp++) {
        int p = bp & 15;
        int s0 = g_seg[bp];
        int e0 = (p == Pp - 1) ? Ss : g_seg[bp + 1];
        int s0a = s0 & ~63;
        int Lp = ((e0 - s0a) + 63) & ~63;
        g_s0a[bp] = s0a;
        g_Lp[bp] = Lp;
        g_poff[bp] = po;
        po += (long long)Ss * Lp;
    }
}

// ---------------- convert inputs to fp16 ------------------------------------------
__global__ void cvt_x(const float* __restrict__ x) {
    long i = (long)blockIdx.x * 256 + threadIdx.x;
    float4 v = ((const float4*)x)[i];
    __half h[4] = { __float2half(v.x), __float2half(v.y),
                    __float2half(v.z), __float2half(v.w) };
    *(uint2*)&g_xf[i * 4] = *(uint2*)h;
}

__global__ void transpose_w(const float* __restrict__ Wq, const float* __restrict__ Wk,
                            const float* __restrict__ Wv) {
    __shared__ float t[32][33];
    int z = blockIdx.z;
    const float* W = (z == 0) ? Wq : (z == 1) ? Wk : Wv;
    int x0 = blockIdx.x * 32, y0 = blockIdx.y * 32;
    int tx = threadIdx.x, ty = threadIdx.y;
    #pragma unroll
    for (int i = 0; i < 32; i += 8) t[ty + i][tx] = W[(y0 + ty + i) * Dd + x0 + tx];
    __syncthreads();
    #pragma unroll
    for (int i = 0; i < 32; i += 8)
        g_wtf[(long)z * Dd * Dd + (long)(x0 + ty + i) * Dd + y0 + tx] =
            __float2half(t[tx][ty + i]);
}

// ---------------- projection GEMM (x @ W^T-rows), fp16 single --------------------
__global__ void __launch_bounds__(256, 1) proj_tc(const float* __restrict__ b0,
                                                  const float* __restrict__ b1,
                                                  const float* __restrict__ b2) {
    extern __shared__ char smx[];
    unsigned sbu = smem_u32(smx);
    const int tid = threadIdx.x, warp = tid >> 5, lane = tid & 31;
    const int wm = warp >> 2, wn = warp & 3;
    const int z = blockIdx.z;
    const int n0 = blockIdx.x * 256, m0 = blockIdx.y * 128;

    const __half* A = g_xf + (long)m0 * Dd;
    const __half* B = g_wtf + (long)z * Dd * Dd + (long)n0 * Dd;

    frag_c acc[4][4];
    #pragma unroll
    for (int i = 0; i < 4; i++)
        #pragma unroll
        for (int j = 0; j < 4; j++) wmma::fill_fragment(acc[i][j], 0.f);

    const int NC = Dd / 64;
    GEMM_LOOP(A, Dd, B, Dd, NC)
    __syncthreads();

    const float* bias = (z == 0) ? b0 : (z == 1) ? b1 : b2;
    float* bounce = (float*)smx + warp * 320;        // 16x20 per warp
    #pragma unroll
    for (int i = 0; i < 4; i++)
        #pragma unroll
        for (int j = 0; j < 4; j++) {
            wmma::store_matrix_sync(bounce, acc[i][j], 20, wmma::mem_row_major);
            __syncwarp();
            int gm = m0 + wm * 64 + i * 16;
            int gn = n0 + wn * 64 + j * 16;
            if (z == 2) {
                // write v transposed: vt[(b*Dd + d)*SVT + s], 16B per thread
                int c = lane >> 1, rs = (lane & 1) * 8;
                int d = gn + c;
                float bi = bias[d];
                int bb = m0 >> 11;
                int sbase = (gm & (Ss - 1)) + rs;
                __half hh[8];
                #pragma unroll
                for (int t = 0; t < 8; t++)
                    hh[t] = __float2half(bounce[(rs + t) * 20 + c] + bi);
                *(uint4*)&g_vt[((long)bb * Dd + d) * SVT + sbase] = *(uint4*)hh;
            } else {
                int r = lane >> 1, cs = (lane & 1) * 8;
                __half hh[8];
                #pragma unroll
                for (int t = 0; t < 8; t++) {
                    float val = bounce[r * 20 + cs + t] + bias[gn + cs + t];
                    if (z == 0) val *= SCALE;
                    hh[t] = __float2half(val);
                }
                long dst = (long)(gm + r) * Dd + gn + cs;
                if (z == 0) *(uint4*)&g_qf[dst] = *(uint4*)hh;
                else        *(uint4*)&g_kf[dst] = *(uint4*)hh;
            }
            __syncwarp();
        }
}

// ---------------- scores GEMM: sc = (q*scale) @ k^T, fp16 single -----------------
__global__ void __launch_bounds__(256, 1) scores_tc() {
    extern __shared__ char smx[];
    unsigned sbu = smem_u32(smx);
    const int tid = threadIdx.x, warp = tid >> 5;
    const int wm = warp >> 2, wn = warp & 3;
    const int b = blockIdx.z;
    const int n0 = blockIdx.x * 256, m0 = blockIdx.y * 128;

    const __half* A = g_qf + ((long)b * Ss + m0) * Dd;
    const __half* B = g_kf + ((long)b * Ss + n0) * Dd;

    frag_c acc[4][4];
    #pragma unroll
    for (int i = 0; i < 4; i++)
        #pragma unroll
        for (int j = 0; j < 4; j++) wmma::fill_fragment(acc[i][j], 0.f);

    const int NC = Dd / 64;
    GEMM_LOOP(A, Dd, B, Dd, NC)

    float* dst = g_sc + (long)b * Ss * Ss;
    #pragma unroll
    for (int i = 0; i < 4; i++)
        #pragma unroll
        for (int j = 0; j < 4; j++) {
            int gm = m0 + wm * 64 + i * 16;
            int gn = n0 + wn * 64 + j * 16;
            wmma::store_matrix_sync(&dst[(long)gm * Ss + gn], acc[i][j], Ss,
                                    wmma::mem_row_major);
        }
}

// ---------------- softmax: single-exp, smem-cached -> padded P (fp16) ------------
// 8 warps/block, one (bp, q) row per warp. Zeros outside [s0, e0) within [s0a, s0a+Lp).
__global__ void __launch_bounds__(256) stats_kernel() {
    __shared__ __half cache[8][Ss];
    const int w = threadIdx.x >> 5;
    const int lane = threadIdx.x & 31;
    const int wid = blockIdx.x * 8 + w;
    const int q = wid & (Ss - 1);
    const int bp = wid / Ss;
    const int b = bp >> 4, p = bp & 15;
    const int s0 = g_seg[bp];
    const int e0 = (p == Pp - 1) ? Ss : g_seg[bp + 1];
    const int s0a = g_s0a[bp];
    const int Lp = g_Lp[bp];
    const float* row = g_sc + ((long)b * Ss + q) * Ss;
    float mx = -1e30f;
    for (int k = s0 + lane; k < e0; k += 32) mx = fmaxf(mx, row[k]);
    #pragma unroll
    for (int o = 16; o; o >>= 1) mx = fmaxf(mx, __shfl_xor_sync(0xffffffffu, mx, o));
    float sum = 0.f;
    for (int k = s0a + lane; k < s0a + Lp; k += 32) {
        float e = (k >= s0 && k < e0) ? __expf(row[k] - mx) : 0.f;
        cache[w][k - s0a] = __float2half(e);
        sum += e;
    }
    #pragma unroll
    for (int o = 16; o; o >>= 1) sum += __shfl_xor_sync(0xffffffffu, sum, o);
    float inv = 1.0f / sum;
    long long po = g_poff[bp] + (long long)q * Lp;
    for (int k = lane * 2; k < Lp; k += 64) {
        float2 e2 = __half22float2(*(const __half2*)&cache[w][k]);
        __half2 o2 = __floats2half2_rn(e2.x * inv, e2.y * inv);
        *(__half2*)&g_pf[po + k] = o2;
    }
}

// ---------------- output GEMM: out[bp] = P @ V (V read direct from vt) -----------
__global__ void __launch_bounds__(256, 1) out_tc(float* __restrict__ out) {
    extern __shared__ char smx[];
    unsigned sbu = smem_u32(smx);
    const int tid = threadIdx.x, warp = tid >> 5;
    const int wm = warp >> 2, wn = warp & 3;
    const int bp = blockIdx.z;
    const int b = bp >> 4;
    const int s0a = g_s0a[bp];
    const int Lp = g_Lp[bp];
    const int NC = Lp >> 6;
    const int n0 = blockIdx.x * 256, m0 = blockIdx.y * 128;

    const __half* A = g_pf + g_poff[bp] + (long long)m0 * Lp;
    const __half* B = g_vt + ((long)b * Dd + n0) * SVT + s0a;

    frag_c acc[4][4];
    #pragma unroll
    for (int i = 0; i < 4; i++)
        #pragma unroll
        for (int j = 0; j < 4; j++) wmma::fill_fragment(acc[i][j], 0.f);

    GEMM_LOOP(A, Lp, B, SVT, NC)

    float* dst = out + ((long)bp * Ss + m0) * Dd;
    #pragma unroll
    for (int i = 0; i < 4; i++)
        #pragma unroll
        for (int j = 0; j < 4; j++) {
            int rm = wm * 64 + i * 16;
            int gn = n0 + wn * 64 + j * 16;
            wmma::store_matrix_sync(&dst[(long)rm * Dd + gn], acc[i][j], Dd,
                                    wmma::mem_row_major);
        }
}

// ---------------- launch ----------------------------------------------------------
extern "C" void kernel_launch(void* const* d_in, const int* in_sizes, int n_in,
                              void* d_out, int out_size) {
    const float* x = (const float*)d_in[0];
    const void* pidx = d_in[1];
    const float* Wq = (const float*)d_in[2];
    const float* bq = (const float*)d_in[3];
    const float* Wk = (const float*)d_in[4];
    const float* bk = (const float*)d_in[5];
    const float* Wv = (const float*)d_in[6];
    const float* bv = (const float*)d_in[7];
    float* out = (float*)d_out;

    static int attr_done = 0;
    if (!attr_done) {
        cudaFuncSetAttribute(proj_tc, cudaFuncAttributeMaxDynamicSharedMemorySize, H_SMEM);
        cudaFuncSetAttribute(scores_tc, cudaFuncAttributeMaxDynamicSharedMemorySize, H_SMEM);
        cudaFuncSetAttribute(out_tc, cudaFuncAttributeMaxDynamicSharedMemorySize, H_SMEM);
        attr_done = 1;
    }

    decode_idx<<<1, 1>>>(pidx);
    cvt_x<<<(Bb * Ss * Dd / 4) / 256, 256>>>(x);

    dim3 tg(Dd / 32, Dd / 32, 3);
    transpose_w<<<tg, dim3(32, 8)>>>(Wq, Wk, Wv);

    dim3 pg(Dd / 256, (Bb * Ss) / 128, 3);           // 3 x 32 x 3
    proj_tc<<<pg, 256, H_SMEM>>>(bq, bk, bv);

    dim3 sg(Ss / 256, Ss / 128, Bb);                 // 8 x 16 x 2
    scores_tc<<<sg, 256, H_SMEM>>>();

    stats_kernel<<<(Bb * Pp * Ss) / 8, 256>>>();

    dim3 og(Dd / 256, Ss / 128, Bb * Pp);            // 3 x 16 x 32
    out_tc<<<og, 256, H_SMEM>>>(out);
}

// round 14
// speedup vs baseline: 2.3718x; 1.0001x over previous
#include <cuda_runtime.h>
#include <cuda_fp16.h>
#include <mma.h>

using namespace nvcuda;

#define Bb 2
#define Ss 2048
#define Dd 768
#define Pp 16
#define SCALE 0.03608439182435161f   // 1/sqrt(768)

#define SVT (Ss + 64)                     // vt row stride (slack for over-read)
#define PSEG (Bb * Ss * (Ss + Pp * 128))  // padded P elems (front+back pad)

// ---------------- scratch (device globals) -------------------------------------
__device__ __align__(256) float g_sc[Bb * Ss * Ss];
__device__ __align__(256) __half g_xf[Bb * Ss * Dd];    // x, fp16
__device__ __align__(256) __half g_wtf[3 * Dd * Dd];    // W^T rows, fp16
__device__ __align__(256) __half g_qf[Bb * Ss * Dd];    // q (pre-scaled), fp16
__device__ __align__(256) __half g_kf[Bb * Ss * Dd];    // k, fp16
__device__ __align__(256) __half g_pf[PSEG];            // P, fp16 (zero-padded)
__device__ __align__(256) __half g_vt[Bb * Dd * SVT];   // v transposed [b][d][s]
__device__ int g_seg[Bb * Pp];                          // true segment starts
__device__ int g_s0a[Bb * Pp];                          // aligned-down starts
__device__ int g_Lp[Bb * Pp];                           // padded lengths (mult 64)
__device__ long long g_poff[Bb * Pp];

// ---------------- wmma types ----------------------------------------------------
typedef wmma::fragment<wmma::matrix_a, 16, 16, 16, __half, wmma::row_major> frag_ha;
typedef wmma::fragment<wmma::matrix_b, 16, 16, 16, __half, wmma::col_major> frag_hb;
typedef wmma::fragment<wmma::accumulator, 16, 16, 16, float> frag_c;

// Block tile 128(M) x 256(N), K-chunk 64. Warp tile 32x64, warps 4x4 (512 thr).
#define NT 512
#define TLD 72                        // smem ld (elems): 144B rows
#define A_TILE 18432                  // 128 x TLD x 2B
#define H_STAGE 55296                 // A + B (B = 256 x TLD x 2B)
#define H_SMEM 165888                 // 3 stages

// ---------------- helpers -------------------------------------------------------
__device__ __forceinline__ unsigned smem_u32(const void* p) {
    unsigned a;
    asm("{ .reg .u64 t; cvta.to.shared.u64 t, %1; cvt.u32.u64 %0, t; }" : "=r"(a) : "l"(p));
    return a;
}
#define CP16(daddr, gptr) \
    asm volatile("cp.async.cg.shared.global [%0], [%1], 16;" :: "r"(daddr), "l"(gptr) : "memory")
__device__ __forceinline__ void cp_commit() { asm volatile("cp.async.commit_group;" ::: "memory"); }
__device__ __forceinline__ void cp_wait0() { asm volatile("cp.async.wait_group 0;" ::: "memory"); }
__device__ __forceinline__ void cp_wait1() { asm volatile("cp.async.wait_group 1;" ::: "memory"); }

// fp16 stage, K=64 chunk: A(128 rows) + B(256 rows), 16B async copies, 512 thr
__device__ __forceinline__ void stage_h(const __half* A, long lda,
                                        const __half* B, long ldb,
                                        unsigned sb, int tid) {
    #pragma unroll
    for (int i = 0; i < 2; i++) {
        int ch = i * NT + tid;               // 0..1023
        int r = ch >> 3, c16 = ch & 7;
        CP16(sb + (unsigned)(r * 144 + c16 * 16), A + (long)r * lda + c16 * 8);
    }
    #pragma unroll
    for (int i = 0; i < 4; i++) {
        int ch = i * NT + tid;               // 0..2047
        int r = ch >> 3, c16 = ch & 7;
        CP16(sb + A_TILE + (unsigned)(r * 144 + c16 * 16), B + (long)r * ldb + c16 * 8);
    }
}

// fp16 MMA over one staged K=64 chunk; warp tile 32x64 at (wm, wn), B streamed
__device__ __forceinline__ void mma_chunk_h(frag_c (&acc)[2][4], const char* buf, int wm, int wn) {
    const __half* sA = (const __half*)buf;
    const __half* sB = (const __half*)(buf + A_TILE);
    #pragma unroll
    for (int ks = 0; ks < 4; ks++) {
        frag_ha a[2];
        #pragma unroll
        for (int i = 0; i < 2; i++)
            wmma::load_matrix_sync(a[i], sA + (wm * 32 + i * 16) * TLD + ks * 16, TLD);
        #pragma unroll
        for (int j = 0; j < 4; j++) {
            frag_hb b;
            wmma::load_matrix_sync(b, sB + (wn * 64 + j * 16) * TLD + ks * 16, TLD);
            wmma::mma_sync(acc[0][j], a[0], b, acc[0][j]);
            wmma::mma_sync(acc[1][j], a[1], b, acc[1][j]);
        }
    }
}

// 3-stage pipelined GEMM mainloop over NC K=64 chunks
#define GEMM_LOOP(Ap, lda, Bp, ldb, NC)                                          \
    stage_h(Ap, lda, Bp, ldb, sbu, tid);                                         \
    cp_commit();                                                                 \
    if ((NC) > 1) { stage_h((Ap) + 64, lda, (Bp) + 64, ldb, sbu + H_STAGE, tid); \
                    cp_commit(); }                                               \
    for (int c = 0; c < (NC); c++) {                                             \
        if (c + 2 < (NC)) cp_wait1(); else cp_wait0();                           \
        __syncthreads();                                                         \
        if (c + 2 < (NC)) {                                                      \
            long kk = (long)(c + 2) * 64;                                        \
            stage_h((Ap) + kk, lda, (Bp) + kk, ldb,                              \
                    sbu + (unsigned)((c + 2) % 3) * H_STAGE, tid);               \
            cp_commit();                                                         \
        }                                                                        \
        mma_chunk_h(acc, smx + (c % 3) * H_STAGE, wm, wn);                       \
    }

// ---------------- decode patch indices + layout ----------------------------------
__global__ void decode_idx(const void* __restrict__ raw) {
    const long long* p64 = (const long long*)raw;
    const int* p32 = (const int*)raw;
    bool ok64 = true;
    for (int b = 0; b < Bb && ok64; b++) {
        long long prev = -1;
        for (int p = 0; p < Pp; p++) {
            long long v = p64[b * Pp + p];
            if (v < 0 || v >= Ss || v <= prev) { ok64 = false; break; }
            prev = v;
        }
    }
    for (int i = 0; i < Bb * Pp; i++)
        g_seg[i] = ok64 ? (int)p64[i] : p32[i];
    long long po = 0;
    for (int bp = 0; bp < Bb * Pp; bp++) {
        int p = bp & 15;
        int s0 = g_seg[bp];
        int e0 = (p == Pp - 1) ? Ss : g_seg[bp + 1];
        int s0a = s0 & ~63;
        int Lp = ((e0 - s0a) + 63) & ~63;
        g_s0a[bp] = s0a;
        g_Lp[bp] = Lp;
        g_poff[bp] = po;
        po += (long long)Ss * Lp;
    }
}

// ---------------- convert inputs to fp16 ------------------------------------------
__global__ void cvt_x(const float* __restrict__ x) {
    long i = (long)blockIdx.x * 256 + threadIdx.x;
    float4 v = ((const float4*)x)[i];
    __half h[4] = { __float2half(v.x), __float2half(v.y),
                    __float2half(v.z), __float2half(v.w) };
    *(uint2*)&g_xf[i * 4] = *(uint2*)h;
}

__global__ void transpose_w(const float* __restrict__ Wq, const float* __restrict__ Wk,
                            const float* __restrict__ Wv) {
    __shared__ float t[32][33];
    int z = blockIdx.z;
    const float* W = (z == 0) ? Wq : (z == 1) ? Wk : Wv;
    int x0 = blockIdx.x * 32, y0 = blockIdx.y * 32;
    int tx = threadIdx.x, ty = threadIdx.y;
    #pragma unroll
    for (int i = 0; i < 32; i += 8) t[ty + i][tx] = W[(y0 + ty + i) * Dd + x0 + tx];
    __syncthreads();
    #pragma unroll
    for (int i = 0; i < 32; i += 8)
        g_wtf[(long)z * Dd * Dd + (long)(x0 + ty + i) * Dd + y0 + tx] =
            __float2half(t[tx][ty + i]);
}

// ---------------- projection GEMM (x @ W^T-rows), fp16 single --------------------
__global__ void __launch_bounds__(NT, 1) proj_tc(const float* __restrict__ b0,
                                                 const float* __restrict__ b1,
                                                 const float* __restrict__ b2) {
    extern __shared__ char smx[];
    unsigned sbu = smem_u32(smx);
    const int tid = threadIdx.x, warp = tid >> 5, lane = tid & 31;
    const int wm = warp >> 2, wn = warp & 3;
    const int z = blockIdx.z;
    const int n0 = blockIdx.x * 256, m0 = blockIdx.y * 128;

    const __half* A = g_xf + (long)m0 * Dd;
    const __half* B = g_wtf + (long)z * Dd * Dd + (long)n0 * Dd;

    frag_c acc[2][4];
    #pragma unroll
    for (int i = 0; i < 2; i++)
        #pragma unroll
        for (int j = 0; j < 4; j++) wmma::fill_fragment(acc[i][j], 0.f);

    const int NC = Dd / 64;
    GEMM_LOOP(A, Dd, B, Dd, NC)
    __syncthreads();

    const float* bias = (z == 0) ? b0 : (z == 1) ? b1 : b2;
    float* bounce = (float*)smx + warp * 320;        // 16x20 per warp (16 warps = 20 KB)
    #pragma unroll
    for (int i = 0; i < 2; i++)
        #pragma unroll
        for (int j = 0; j < 4; j++) {
            wmma::store_matrix_sync(bounce, acc[i][j], 20, wmma::mem_row_major);
            __syncwarp();
            int gm = m0 + wm * 32 + i * 16;
            int gn = n0 + wn * 64 + j * 16;
            if (z == 2) {
                // write v transposed: vt[(b*Dd + d)*SVT + s], 16B per thread
                int c = lane >> 1, rs = (lane & 1) * 8;
                int d = gn + c;
                float bi = bias[d];
                int bb = m0 >> 11;
                int sbase = (gm & (Ss - 1)) + rs;
                __half hh[8];
                #pragma unroll
                for (int t = 0; t < 8; t++)
                    hh[t] = __float2half(bounce[(rs + t) * 20 + c] + bi);
                *(uint4*)&g_vt[((long)bb * Dd + d) * SVT + sbase] = *(uint4*)hh;
            } else {
                int r = lane >> 1, cs = (lane & 1) * 8;
                __half hh[8];
                #pragma unroll
                for (int t = 0; t < 8; t++) {
                    float val = bounce[r * 20 + cs + t] + bias[gn + cs + t];
                    if (z == 0) val *= SCALE;
                    hh[t] = __float2half(val);
                }
                long dst = (long)(gm + r) * Dd + gn + cs;
                if (z == 0) *(uint4*)&g_qf[dst] = *(uint4*)hh;
                else        *(uint4*)&g_kf[dst] = *(uint4*)hh;
            }
            __syncwarp();
        }
}

// ---------------- scores GEMM: sc = (q*scale) @ k^T, fp16 single -----------------
__global__ void __launch_bounds__(NT, 1) scores_tc() {
    extern __shared__ char smx[];
    unsigned sbu = smem_u32(smx);
    const int tid = threadIdx.x, warp = tid >> 5;
    const int wm = warp >> 2, wn = warp & 3;
    const int b = blockIdx.z;
    const int n0 = blockIdx.x * 256, m0 = blockIdx.y * 128;

    const __half* A = g_qf + ((long)b * Ss + m0) * Dd;
    const __half* B = g_kf + ((long)b * Ss + n0) * Dd;

    frag_c acc[2][4];
    #pragma unroll
    for (int i = 0; i < 2; i++)
        #pragma unroll
        for (int j = 0; j < 4; j++) wmma::fill_fragment(acc[i][j], 0.f);

    const int NC = Dd / 64;
    GEMM_LOOP(A, Dd, B, Dd, NC)

    float* dst = g_sc + (long)b * Ss * Ss;
    #pragma unroll
    for (int i = 0; i < 2; i++)
        #pragma unroll
        for (int j = 0; j < 4; j++) {
            int gm = m0 + wm * 32 + i * 16;
            int gn = n0 + wn * 64 + j * 16;
            wmma::store_matrix_sync(&dst[(long)gm * Ss + gn], acc[i][j], Ss,
                                    wmma::mem_row_major);
        }
}

// ---------------- softmax: single-exp, smem-cached -> padded P (fp16) ------------
// 8 warps/block, one (bp, q) row per warp. Zeros outside [s0, e0) within [s0a, s0a+Lp).
__global__ void __launch_bounds__(256) stats_kernel() {
    __shared__ __half cache[8][Ss];
    const int w = threadIdx.x >> 5;
    const int lane = threadIdx.x & 31;
    const int wid = blockIdx.x * 8 + w;
    const int q = wid & (Ss - 1);
    const int bp = wid / Ss;
    const int b = bp >> 4, p = bp & 15;
    const int s0 = g_seg[bp];
    const int e0 = (p == Pp - 1) ? Ss : g_seg[bp + 1];
    const int s0a = g_s0a[bp];
    const int Lp = g_Lp[bp];
    const float* row = g_sc + ((long)b * Ss + q) * Ss;
    float mx = -1e30f;
    for (int k = s0 + lane; k < e0; k += 32) mx = fmaxf(mx, row[k]);
    #pragma unroll
    for (int o = 16; o; o >>= 1) mx = fmaxf(mx, __shfl_xor_sync(0xffffffffu, mx, o));
    float sum = 0.f;
    for (int k = s0a + lane; k < s0a + Lp; k += 32) {
        float e = (k >= s0 && k < e0) ? __expf(row[k] - mx) : 0.f;
        cache[w][k - s0a] = __float2half(e);
        sum += e;
    }
    #pragma unroll
    for (int o = 16; o; o >>= 1) sum += __shfl_xor_sync(0xffffffffu, sum, o);
    float inv = 1.0f / sum;
    long long po = g_poff[bp] + (long long)q * Lp;
    for (int k = lane * 2; k < Lp; k += 64) {
        float2 e2 = __half22float2(*(const __half2*)&cache[w][k]);
        __half2 o2 = __floats2half2_rn(e2.x * inv, e2.y * inv);
        *(__half2*)&g_pf[po + k] = o2;
    }
}

// ---------------- output GEMM: out[bp] = P @ V (V read direct from vt) -----------
__global__ void __launch_bounds__(NT, 1) out_tc(float* __restrict__ out) {
    extern __shared__ char smx[];
    unsigned sbu = smem_u32(smx);
    const int tid = threadIdx.x, warp = tid >> 5;
    const int wm = warp >> 2, wn = warp & 3;
    const int bp = blockIdx.z;
    const int b = bp >> 4;
    const int s0a = g_s0a[bp];
    const int Lp = g_Lp[bp];
    const int NC = Lp >> 6;
    const int n0 = blockIdx.x * 256, m0 = blockIdx.y * 128;

    const __half* A = g_pf + g_poff[bp] + (long long)m0 * Lp;
    const __half* B = g_vt + ((long)b * Dd + n0) * SVT + s0a;

    frag_c acc[2][4];
    #pragma unroll
    for (int i = 0; i < 2; i++)
        #pragma unroll
        for (int j = 0; j < 4; j++) wmma::fill_fragment(acc[i][j], 0.f);

    GEMM_LOOP(A, Lp, B, SVT, NC)

    float* dst = out + ((long)bp * Ss + m0) * Dd;
    #pragma unroll
    for (int i = 0; i < 2; i++)
        #pragma unroll
        for (int j = 0; j < 4; j++) {
            int rm = wm * 32 + i * 16;
            int gn = n0 + wn * 64 + j * 16;
            wmma::store_matrix_sync(&dst[(long)rm * Dd + gn], acc[i][j], Dd,
                                    wmma::mem_row_major);
        }
}

// ---------------- launch ----------------------------------------------------------
extern "C" void kernel_launch(void* const* d_in, const int* in_sizes, int n_in,
                              void* d_out, int out_size) {
    const float* x = (const float*)d_in[0];
    const void* pidx = d_in[1];
    const float* Wq = (const float*)d_in[2];
    const float* bq = (const float*)d_in[3];
    const float* Wk = (const float*)d_in[4];
    const float* bk = (const float*)d_in[5];
    const float* Wv = (const float*)d_in[6];
    const float* bv = (const float*)d_in[7];
    float* out = (float*)d_out;

    static int attr_done = 0;
    if (!attr_done) {
        cudaFuncSetAttribute(proj_tc, cudaFuncAttributeMaxDynamicSharedMemorySize, H_SMEM);
        cudaFuncSetAttribute(scores_tc, cudaFuncAttributeMaxDynamicSharedMemorySize, H_SMEM);
        cudaFuncSetAttribute(out_tc, cudaFuncAttributeMaxDynamicSharedMemorySize, H_SMEM);
        attr_done = 1;
    }

    decode_idx<<<1, 1>>>(pidx);
    cvt_x<<<(Bb * Ss * Dd / 4) / 256, 256>>>(x);

    dim3 tg(Dd / 32, Dd / 32, 3);
    transpose_w<<<tg, dim3(32, 8)>>>(Wq, Wk, Wv);

    dim3 pg(Dd / 256, (Bb * Ss) / 128, 3);           // 3 x 32 x 3
    proj_tc<<<pg, NT, H_SMEM>>>(bq, bk, bv);

    dim3 sg(Ss / 256, Ss / 128, Bb);                 // 8 x 16 x 2
    scores_tc<<<sg, NT, H_SMEM>>>();

    stats_kernel<<<(Bb * Pp * Ss) / 8, 256>>>();

    dim3 og(Dd / 256, Ss / 128, Bb * Pp);            // 3 x 16 x 32
    out_tc<<<og, NT, H_SMEM>>>(out);
}

// round 15
// speedup vs baseline: 2.4137x; 1.0177x over previous
#include <cuda_runtime.h>
#include <cuda_fp16.h>
#include <mma.h>

using namespace nvcuda;

#define Bb 2
#define Ss 2048
#define Dd 768
#define Pp 16
#define SCALE 0.03608439182435161f   // 1/sqrt(768)

#define SVT (Ss + 64)                     // vt row stride (slack for over-read)
#define PSEG (Bb * Ss * (Ss + Pp * 64))   // padded P elems (16-granular pads)

// ---------------- scratch (device globals) -------------------------------------
__device__ __align__(256) float g_sc[Bb * Ss * Ss];
__device__ __align__(256) __half g_xf[Bb * Ss * Dd];    // x, fp16
__device__ __align__(256) __half g_wtf[3 * Dd * Dd];    // W^T rows, fp16
__device__ __align__(256) __half g_qf[Bb * Ss * Dd];    // q (pre-scaled), fp16
__device__ __align__(256) __half g_kf[Bb * Ss * Dd];    // k, fp16
__device__ __align__(256) __half g_pf[PSEG];            // P, fp16 (zero-padded)
__device__ __align__(256) __half g_vt[Bb * Dd * SVT];   // v transposed [b][d][s]
__device__ int g_seg[Bb * Pp];                          // true segment starts
__device__ int g_s0a[Bb * Pp];                          // 16-aligned-down starts
__device__ int g_Lp[Bb * Pp];                           // padded lengths (mult 16)
__device__ long long g_poff[Bb * Pp];

// ---------------- wmma types ----------------------------------------------------
typedef wmma::fragment<wmma::matrix_a, 16, 16, 16, __half, wmma::row_major> frag_ha;
typedef wmma::fragment<wmma::matrix_b, 16, 16, 16, __half, wmma::col_major> frag_hb;
typedef wmma::fragment<wmma::accumulator, 16, 16, 16, float> frag_c;

// Block tile 128(M) x 256(N), K-chunk 64. Warp tile 32x64, warps 4x4 (512 thr).
#define NT 512
#define TLD 72                        // smem ld (elems): 144B rows
#define A_TILE 18432                  // 128 x TLD x 2B
#define H_STAGE 55296                 // A + B (B = 256 x TLD x 2B)
#define H_SMEM 165888                 // 3 stages

// ---------------- helpers -------------------------------------------------------
__device__ __forceinline__ unsigned smem_u32(const void* p) {
    unsigned a;
    asm("{ .reg .u64 t; cvta.to.shared.u64 t, %1; cvt.u32.u64 %0, t; }" : "=r"(a) : "l"(p));
    return a;
}
#define CP16(daddr, gptr) \
    asm volatile("cp.async.cg.shared.global [%0], [%1], 16;" :: "r"(daddr), "l"(gptr) : "memory")
__device__ __forceinline__ void cp_commit() { asm volatile("cp.async.commit_group;" ::: "memory"); }
__device__ __forceinline__ void cp_wait0() { asm volatile("cp.async.wait_group 0;" ::: "memory"); }
__device__ __forceinline__ void cp_wait1() { asm volatile("cp.async.wait_group 1;" ::: "memory"); }

// fp16 stage, K=64 chunk: A(128 rows) + B(256 rows), 16B async copies, 512 thr
__device__ __forceinline__ void stage_h(const __half* A, long lda,
                                        const __half* B, long ldb,
                                        unsigned sb, int tid) {
    #pragma unroll
    for (int i = 0; i < 2; i++) {
        int ch = i * NT + tid;               // 0..1023
        int r = ch >> 3, c16 = ch & 7;
        CP16(sb + (unsigned)(r * 144 + c16 * 16), A + (long)r * lda + c16 * 8);
    }
    #pragma unroll
    for (int i = 0; i < 4; i++) {
        int ch = i * NT + tid;               // 0..2047
        int r = ch >> 3, c16 = ch & 7;
        CP16(sb + A_TILE + (unsigned)(r * 144 + c16 * 16), B + (long)r * ldb + c16 * 8);
    }
}

// partial stage: nch 16B-chunks (= nch*8 cols) per row, for the K tail
__device__ __forceinline__ void stage_tail(const __half* A, long lda,
                                           const __half* B, long ldb,
                                           unsigned sb, int tid, int nch) {
    for (int idx = tid; idx < 128 * nch; idx += NT) {
        int r = idx / nch, c = idx % nch;
        CP16(sb + (unsigned)(r * 144 + c * 16), A + (long)r * lda + c * 8);
    }
    for (int idx = tid; idx < 256 * nch; idx += NT) {
        int r = idx / nch, c = idx % nch;
        CP16(sb + A_TILE + (unsigned)(r * 144 + c * 16), B + (long)r * ldb + c * 8);
    }
}

// fp16 MMA over one staged K=64 chunk; warp tile 32x64 at (wm, wn), B streamed
__device__ __forceinline__ void mma_chunk_h(frag_c (&acc)[2][4], const char* buf, int wm, int wn) {
    const __half* sA = (const __half*)buf;
    const __half* sB = (const __half*)(buf + A_TILE);
    #pragma unroll
    for (int ks = 0; ks < 4; ks++) {
        frag_ha a[2];
        #pragma unroll
        for (int i = 0; i < 2; i++)
            wmma::load_matrix_sync(a[i], sA + (wm * 32 + i * 16) * TLD + ks * 16, TLD);
        #pragma unroll
        for (int j = 0; j < 4; j++) {
            frag_hb b;
            wmma::load_matrix_sync(b, sB + (wn * 64 + j * 16) * TLD + ks * 16, TLD);
            wmma::mma_sync(acc[0][j], a[0], b, acc[0][j]);
            wmma::mma_sync(acc[1][j], a[1], b, acc[1][j]);
        }
    }
}

// tail MMA: only nks K=16 steps
__device__ __forceinline__ void mma_tail_h(frag_c (&acc)[2][4], const char* buf,
                                           int wm, int wn, int nks) {
    const __half* sA = (const __half*)buf;
    const __half* sB = (const __half*)(buf + A_TILE);
    for (int ks = 0; ks < nks; ks++) {
        frag_ha a[2];
        #pragma unroll
        for (int i = 0; i < 2; i++)
            wmma::load_matrix_sync(a[i], sA + (wm * 32 + i * 16) * TLD + ks * 16, TLD);
        #pragma unroll
        for (int j = 0; j < 4; j++) {
            frag_hb b;
            wmma::load_matrix_sync(b, sB + (wn * 64 + j * 16) * TLD + ks * 16, TLD);
            wmma::mma_sync(acc[0][j], a[0], b, acc[0][j]);
            wmma::mma_sync(acc[1][j], a[1], b, acc[1][j]);
        }
    }
}

// 3-stage pipelined GEMM mainloop over NC K=64 chunks
#define GEMM_LOOP(Ap, lda, Bp, ldb, NC)                                          \
    stage_h(Ap, lda, Bp, ldb, sbu, tid);                                         \
    cp_commit();                                                                 \
    if ((NC) > 1) { stage_h((Ap) + 64, lda, (Bp) + 64, ldb, sbu + H_STAGE, tid); \
                    cp_commit(); }                                               \
    for (int c = 0; c < (NC); c++) {                                             \
        if (c + 2 < (NC)) cp_wait1(); else cp_wait0();                           \
        __syncthreads();                                                         \
        if (c + 2 < (NC)) {                                                      \
            long kk = (long)(c + 2) * 64;                                        \
            stage_h((Ap) + kk, lda, (Bp) + kk, ldb,                              \
                    sbu + (unsigned)((c + 2) % 3) * H_STAGE, tid);               \
            cp_commit();                                                         \
        }                                                                        \
        mma_chunk_h(acc, smx + (c % 3) * H_STAGE, wm, wn);                       \
    }

// ---------------- decode patch indices + layout (16-granular) --------------------
__global__ void decode_idx(const void* __restrict__ raw) {
    const long long* p64 = (const long long*)raw;
    const int* p32 = (const int*)raw;
    bool ok64 = true;
    for (int b = 0; b < Bb && ok64; b++) {
        long long prev = -1;
        for (int p = 0; p < Pp; p++) {
            long long v = p64[b * Pp + p];
            if (v < 0 || v >= Ss || v <= prev) { ok64 = false; break; }
            prev = v;
        }
    }
    for (int i = 0; i < Bb * Pp; i++)
        g_seg[i] = ok64 ? (int)p64[i] : p32[i];
    long long po = 0;
    for (int bp = 0; bp < Bb * Pp; bp++) {
        int p = bp & 15;
        int s0 = g_seg[bp];
        int e0 = (p == Pp - 1) ? Ss : g_seg[bp + 1];
        int s0a = s0 & ~15;
        int Lp = ((e0 - s0a) + 15) & ~15;
        g_s0a[bp] = s0a;
        g_Lp[bp] = Lp;
        g_poff[bp] = po;
        po += (long long)Ss * Lp;
    }
}

// ---------------- convert inputs to fp16 ------------------------------------------
__global__ void cvt_x(const float* __restrict__ x) {
    long i = (long)blockIdx.x * 256 + threadIdx.x;
    float4 v = ((const float4*)x)[i];
    __half h[4] = { __float2half(v.x), __float2half(v.y),
                    __float2half(v.z), __float2half(v.w) };
    *(uint2*)&g_xf[i * 4] = *(uint2*)h;
}

__global__ void transpose_w(const float* __restrict__ Wq, const float* __restrict__ Wk,
                            const float* __restrict__ Wv) {
    __shared__ float t[32][33];
    int z = blockIdx.z;
    const float* W = (z == 0) ? Wq : (z == 1) ? Wk : Wv;
    int x0 = blockIdx.x * 32, y0 = blockIdx.y * 32;
    int tx = threadIdx.x, ty = threadIdx.y;
    #pragma unroll
    for (int i = 0; i < 32; i += 8) t[ty + i][tx] = W[(y0 + ty + i) * Dd + x0 + tx];
    __syncthreads();
    #pragma unroll
    for (int i = 0; i < 32; i += 8)
        g_wtf[(long)z * Dd * Dd + (long)(x0 + ty + i) * Dd + y0 + tx] =
            __float2half(t[tx][ty + i]);
}

// ---------------- projection GEMM (x @ W^T-rows), fp16 single --------------------
__global__ void __launch_bounds__(NT, 1) proj_tc(const float* __restrict__ b0,
                                                 const float* __restrict__ b1,
                                                 const float* __restrict__ b2) {
    extern __shared__ char smx[];
    unsigned sbu = smem_u32(smx);
    const int tid = threadIdx.x, warp = tid >> 5, lane = tid & 31;
    const int wm = warp >> 2, wn = warp & 3;
    const int z = blockIdx.z;
    const int n0 = blockIdx.x * 256, m0 = blockIdx.y * 128;

    const __half* A = g_xf + (long)m0 * Dd;
    const __half* B = g_wtf + (long)z * Dd * Dd + (long)n0 * Dd;

    frag_c acc[2][4];
    #pragma unroll
    for (int i = 0; i < 2; i++)
        #pragma unroll
        for (int j = 0; j < 4; j++) wmma::fill_fragment(acc[i][j], 0.f);

    const int NC = Dd / 64;
    GEMM_LOOP(A, Dd, B, Dd, NC)
    __syncthreads();

    const float* bias = (z == 0) ? b0 : (z == 1) ? b1 : b2;
    float* bounce = (float*)smx + warp * 320;        // 16x20 per warp
    #pragma unroll
    for (int i = 0; i < 2; i++)
        #pragma unroll
        for (int j = 0; j < 4; j++) {
            wmma::store_matrix_sync(bounce, acc[i][j], 20, wmma::mem_row_major);
            __syncwarp();
            int gm = m0 + wm * 32 + i * 16;
            int gn = n0 + wn * 64 + j * 16;
            if (z == 2) {
                int c = lane >> 1, rs = (lane & 1) * 8;
                int d = gn + c;
                float bi = bias[d];
                int bb = m0 >> 11;
                int sbase = (gm & (Ss - 1)) + rs;
                __half hh[8];
                #pragma unroll
                for (int t = 0; t < 8; t++)
                    hh[t] = __float2half(bounce[(rs + t) * 20 + c] + bi);
                *(uint4*)&g_vt[((long)bb * Dd + d) * SVT + sbase] = *(uint4*)hh;
            } else {
                int r = lane >> 1, cs = (lane & 1) * 8;
                __half hh[8];
                #pragma unroll
                for (int t = 0; t < 8; t++) {
                    float val = bounce[r * 20 + cs + t] + bias[gn + cs + t];
                    if (z == 0) val *= SCALE;
                    hh[t] = __float2half(val);
                }
                long dst = (long)(gm + r) * Dd + gn + cs;
                if (z == 0) *(uint4*)&g_qf[dst] = *(uint4*)hh;
                else        *(uint4*)&g_kf[dst] = *(uint4*)hh;
            }
            __syncwarp();
        }
}

// ---------------- scores GEMM: sc = (q*scale) @ k^T, fp16 single -----------------
__global__ void __launch_bounds__(NT, 1) scores_tc() {
    extern __shared__ char smx[];
    unsigned sbu = smem_u32(smx);
    const int tid = threadIdx.x, warp = tid >> 5;
    const int wm = warp >> 2, wn = warp & 3;
    const int b = blockIdx.z;
    const int n0 = blockIdx.x * 256, m0 = blockIdx.y * 128;

    const __half* A = g_qf + ((long)b * Ss + m0) * Dd;
    const __half* B = g_kf + ((long)b * Ss + n0) * Dd;

    frag_c acc[2][4];
    #pragma unroll
    for (int i = 0; i < 2; i++)
        #pragma unroll
        for (int j = 0; j < 4; j++) wmma::fill_fragment(acc[i][j], 0.f);

    const int NC = Dd / 64;
    GEMM_LOOP(A, Dd, B, Dd, NC)

    float* dst = g_sc + (long)b * Ss * Ss;
    #pragma unroll
    for (int i = 0; i < 2; i++)
        #pragma unroll
        for (int j = 0; j < 4; j++) {
            int gm = m0 + wm * 32 + i * 16;
            int gn = n0 + wn * 64 + j * 16;
            wmma::store_matrix_sync(&dst[(long)gm * Ss + gn], acc[i][j], Ss,
                                    wmma::mem_row_major);
        }
}

// ---------------- softmax: single-exp, smem-cached -> padded P (fp16) ------------
__global__ void __launch_bounds__(256) stats_kernel() {
    __shared__ __half cache[8][Ss];
    const int w = threadIdx.x >> 5;
    const int lane = threadIdx.x & 31;
    const int wid = blockIdx.x * 8 + w;
    const int q = wid & (Ss - 1);
    const int bp = wid / Ss;
    const int b = bp >> 4, p = bp & 15;
    const int s0 = g_seg[bp];
    const int e0 = (p == Pp - 1) ? Ss : g_seg[bp + 1];
    const int s0a = g_s0a[bp];
    const int Lp = g_Lp[bp];
    const float* row = g_sc + ((long)b * Ss + q) * Ss;
    float mx = -1e30f;
    for (int k = s0 + lane; k < e0; k += 32) mx = fmaxf(mx, row[k]);
    #pragma unroll
    for (int o = 16; o; o >>= 1) mx = fmaxf(mx, __shfl_xor_sync(0xffffffffu, mx, o));
    float sum = 0.f;
    for (int k = s0a + lane; k < s0a + Lp; k += 32) {
        float e = (k >= s0 && k < e0) ? __expf(row[k] - mx) : 0.f;
        cache[w][k - s0a] = __float2half(e);
        sum += e;
    }
    #pragma unroll
    for (int o = 16; o; o >>= 1) sum += __shfl_xor_sync(0xffffffffu, sum, o);
    float inv = 1.0f / sum;
    long long po = g_poff[bp] + (long long)q * Lp;
    for (int k = lane * 2; k < Lp; k += 64) {
        float2 e2 = __half22float2(*(const __half2*)&cache[w][k]);
        __half2 o2 = __floats2half2_rn(e2.x * inv, e2.y * inv);
        *(__half2*)&g_pf[po + k] = o2;
    }
}

// ---------------- output GEMM: out[bp] = P @ V, 16-granular K --------------------
__global__ void __launch_bounds__(NT, 1) out_tc(float* __restrict__ out) {
    extern __shared__ char smx[];
    unsigned sbu = smem_u32(smx);
    const int tid = threadIdx.x, warp = tid >> 5;
    const int wm = warp >> 2, wn = warp & 3;
    const int bp = blockIdx.z;
    const int b = bp >> 4;
    const int s0a = g_s0a[bp];
    const int Lp = g_Lp[bp];
    const int NCf = Lp >> 6;           // full 64-chunks
    const int tail = Lp & 63;          // 0/16/32/48
    const int n0 = blockIdx.x * 256, m0 = blockIdx.y * 128;

    const __half* A = g_pf + g_poff[bp] + (long long)m0 * Lp;
    const __half* B = g_vt + ((long)b * Dd + n0) * SVT + s0a;

    frag_c acc[2][4];
    #pragma unroll
    for (int i = 0; i < 2; i++)
        #pragma unroll
        for (int j = 0; j < 4; j++) wmma::fill_fragment(acc[i][j], 0.f);

    if (NCf > 0) {
        GEMM_LOOP(A, Lp, B, SVT, NCf)
    }
    if (tail) {
        int slot = (NCf == 0) ? 1 : (NCf % 3);
        long kk = (long)NCf * 64;
        stage_tail(A + kk, Lp, B + kk, SVT, sbu + (unsigned)slot * H_STAGE,
                   tid, tail >> 3);
        cp_commit();
        cp_wait0();
        __syncthreads();
        mma_tail_h(acc, smx + slot * H_STAGE, wm, wn, tail >> 4);
    }

    float* dst = out + ((long)bp * Ss + m0) * Dd;
    #pragma unroll
    for (int i = 0; i < 2; i++)
        #pragma unroll
        for (int j = 0; j < 4; j++) {
            int rm = wm * 32 + i * 16;
            int gn = n0 + wn * 64 + j * 16;
            wmma::store_matrix_sync(&dst[(long)rm * Dd + gn], acc[i][j], Dd,
                                    wmma::mem_row_major);
        }
}

// ---------------- launch ----------------------------------------------------------
extern "C" void kernel_launch(void* const* d_in, const int* in_sizes, int n_in,
                              void* d_out, int out_size) {
    const float* x = (const float*)d_in[0];
    const void* pidx = d_in[1];
    const float* Wq = (const float*)d_in[2];
    const float* bq = (const float*)d_in[3];
    const float* Wk = (const float*)d_in[4];
    const float* bk = (const float*)d_in[5];
    const float* Wv = (const float*)d_in[6];
    const float* bv = (const float*)d_in[7];
    float* out = (float*)d_out;

    static int attr_done = 0;
    if (!attr_done) {
        cudaFuncSetAttribute(proj_tc, cudaFuncAttributeMaxDynamicSharedMemorySize, H_SMEM);
        cudaFuncSetAttribute(scores_tc, cudaFuncAttributeMaxDynamicSharedMemorySize, H_SMEM);
        cudaFuncSetAttribute(out_tc, cudaFuncAttributeMaxDynamicSharedMemorySize, H_SMEM);
        attr_done = 1;
    }

    decode_idx<<<1, 1>>>(pidx);
    cvt_x<<<(Bb * Ss * Dd / 4) / 256, 256>>>(x);

    dim3 tg(Dd / 32, Dd / 32, 3);
    transpose_w<<<tg, dim3(32, 8)>>>(Wq, Wk, Wv);

    dim3 pg(Dd / 256, (Bb * Ss) / 128, 3);           // 3 x 32 x 3
    proj_tc<<<pg, NT, H_SMEM>>>(bq, bk, bv);

    dim3 sg(Ss / 256, Ss / 128, Bb);                 // 8 x 16 x 2
    scores_tc<<<sg, NT, H_SMEM>>>();

    stats_kernel<<<(Bb * Pp * Ss) / 8, 256>>>();

    dim3 og(Dd / 256, Ss / 128, Bb * Pp);            // 3 x 16 x 32
    out_tc<<<og, NT, H_SMEM>>>(out);
}

// round 16
// speedup vs baseline: 2.4576x; 1.0182x over previous
#include <cuda_runtime.h>
#include <cuda_fp16.h>
#include <mma.h>

using namespace nvcuda;

#define Bb 2
#define Ss 2048
#define Dd 768
#define Pp 16
#define SCALE 0.03608439182435161f   // 1/sqrt(768)

#define SVT (Ss + 64)                     // vt row stride (slack for over-read)
#define PSEG (Bb * Ss * (Ss + Pp * 64))   // padded P elems (16-granular pads)

// ---------------- scratch (device globals) -------------------------------------
__device__ __align__(256) float g_sc[Bb * Ss * Ss];
__device__ __align__(256) __half g_xf[Bb * Ss * Dd];    // x, fp16
__device__ __align__(256) __half g_wtf[3 * Dd * Dd];    // W^T rows, fp16
__device__ __align__(256) __half g_qf[Bb * Ss * Dd];    // q (pre-scaled), fp16
__device__ __align__(256) __half g_kf[Bb * Ss * Dd];    // k, fp16
__device__ __align__(256) __half g_pf[PSEG];            // P, fp16 (zero-padded)
__device__ __align__(256) __half g_vt[Bb * Dd * SVT];   // v transposed [b][d][s]
__device__ int g_seg[Bb * Pp];                          // true segment starts
__device__ int g_s0a[Bb * Pp];                          // 16-aligned-down starts
__device__ int g_Lp[Bb * Pp];                           // padded lengths (mult 16)
__device__ long long g_poff[Bb * Pp];

// ---------------- wmma types ----------------------------------------------------
typedef wmma::fragment<wmma::matrix_a, 16, 16, 16, __half, wmma::row_major> frag_ha;
typedef wmma::fragment<wmma::matrix_b, 16, 16, 16, __half, wmma::col_major> frag_hb;
typedef wmma::fragment<wmma::accumulator, 16, 16, 16, float> frag_c;

// Block tile 128(M) x 256(N), K-chunk 64. Warp tile 32x64, warps 4x4 (512 thr).
#define NT 512
#define TLD 72                        // smem ld (elems): 144B rows
#define A_TILE 18432                  // 128 x TLD x 2B
#define H_STAGE 55296                 // A + B (B = 256 x TLD x 2B)
#define H_SMEM 165888                 // 3 stages

// ---------------- helpers -------------------------------------------------------
__device__ __forceinline__ unsigned smem_u32(const void* p) {
    unsigned a;
    asm("{ .reg .u64 t; cvta.to.shared.u64 t, %1; cvt.u32.u64 %0, t; }" : "=r"(a) : "l"(p));
    return a;
}
#define CP16(daddr, gptr) \
    asm volatile("cp.async.cg.shared.global [%0], [%1], 16;" :: "r"(daddr), "l"(gptr) : "memory")
__device__ __forceinline__ void cp_commit() { asm volatile("cp.async.commit_group;" ::: "memory"); }
__device__ __forceinline__ void cp_wait0() { asm volatile("cp.async.wait_group 0;" ::: "memory"); }
__device__ __forceinline__ void cp_wait1() { asm volatile("cp.async.wait_group 1;" ::: "memory"); }

// fp16 stage, full K=64 chunk: A(128 rows) + B(256 rows), 16B async copies, 512 thr
__device__ __forceinline__ void stage_h(const __half* A, long lda,
                                        const __half* B, long ldb,
                                        unsigned sb, int tid) {
    #pragma unroll
    for (int i = 0; i < 2; i++) {
        int ch = i * NT + tid;               // 0..1023
        int r = ch >> 3, c16 = ch & 7;
        CP16(sb + (unsigned)(r * 144 + c16 * 16), A + (long)r * lda + c16 * 8);
    }
    #pragma unroll
    for (int i = 0; i < 4; i++) {
        int ch = i * NT + tid;               // 0..2047
        int r = ch >> 3, c16 = ch & 7;
        CP16(sb + A_TILE + (unsigned)(r * 144 + c16 * 16), B + (long)r * ldb + c16 * 8);
    }
}

// variable-width stage: nch 16B-chunks per row (nch in 2,4,6,8)
__device__ __forceinline__ void stage_v(const __half* A, long lda,
                                        const __half* B, long ldb,
                                        unsigned sb, int tid, int nch) {
    if (nch == 8) { stage_h(A, lda, B, ldb, sb, tid); return; }
    for (int idx = tid; idx < 128 * nch; idx += NT) {
        int r = idx / nch, c = idx - r * nch;
        CP16(sb + (unsigned)(r * 144 + c * 16), A + (long)r * lda + c * 8);
    }
    for (int idx = tid; idx < 256 * nch; idx += NT) {
        int r = idx / nch, c = idx - r * nch;
        CP16(sb + A_TILE + (unsigned)(r * 144 + c * 16), B + (long)r * ldb + c * 8);
    }
}

// fp16 MMA over one staged K=64 chunk; warp tile 32x64 at (wm, wn), B streamed
__device__ __forceinline__ void mma_chunk_h(frag_c (&acc)[2][4], const char* buf, int wm, int wn) {
    const __half* sA = (const __half*)buf;
    const __half* sB = (const __half*)(buf + A_TILE);
    #pragma unroll
    for (int ks = 0; ks < 4; ks++) {
        frag_ha a[2];
        #pragma unroll
        for (int i = 0; i < 2; i++)
            wmma::load_matrix_sync(a[i], sA + (wm * 32 + i * 16) * TLD + ks * 16, TLD);
        #pragma unroll
        for (int j = 0; j < 4; j++) {
            frag_hb b;
            wmma::load_matrix_sync(b, sB + (wn * 64 + j * 16) * TLD + ks * 16, TLD);
            wmma::mma_sync(acc[0][j], a[0], b, acc[0][j]);
            wmma::mma_sync(acc[1][j], a[1], b, acc[1][j]);
        }
    }
}

// variable-width MMA: nks K=16 steps (1..4)
__device__ __forceinline__ void mma_v(frag_c (&acc)[2][4], const char* buf,
                                      int wm, int wn, int nks) {
    if (nks == 4) { mma_chunk_h(acc, buf, wm, wn); return; }
    const __half* sA = (const __half*)buf;
    const __half* sB = (const __half*)(buf + A_TILE);
    for (int ks = 0; ks < nks; ks++) {
        frag_ha a[2];
        #pragma unroll
        for (int i = 0; i < 2; i++)
            wmma::load_matrix_sync(a[i], sA + (wm * 32 + i * 16) * TLD + ks * 16, TLD);
        #pragma unroll
        for (int j = 0; j < 4; j++) {
            frag_hb b;
            wmma::load_matrix_sync(b, sB + (wn * 64 + j * 16) * TLD + ks * 16, TLD);
            wmma::mma_sync(acc[0][j], a[0], b, acc[0][j]);
            wmma::mma_sync(acc[1][j], a[1], b, acc[1][j]);
        }
    }
}

// 3-stage pipelined GEMM mainloop over NC full K=64 chunks
#define GEMM_LOOP(Ap, lda, Bp, ldb, NC)                                          \
    stage_h(Ap, lda, Bp, ldb, sbu, tid);                                         \
    cp_commit();                                                                 \
    if ((NC) > 1) { stage_h((Ap) + 64, lda, (Bp) + 64, ldb, sbu + H_STAGE, tid); \
                    cp_commit(); }                                               \
    for (int c = 0; c < (NC); c++) {                                             \
        if (c + 2 < (NC)) cp_wait1(); else cp_wait0();                           \
        __syncthreads();                                                         \
        if (c + 2 < (NC)) {                                                      \
            long kk = (long)(c + 2) * 64;                                        \
            stage_h((Ap) + kk, lda, (Bp) + kk, ldb,                              \
                    sbu + (unsigned)((c + 2) % 3) * H_STAGE, tid);               \
            cp_commit();                                                         \
        }                                                                        \
        mma_chunk_h(acc, smx + (c % 3) * H_STAGE, wm, wn);                       \
    }

// ---------------- decode patch indices + layout (16-granular) --------------------
__global__ void decode_idx(const void* __restrict__ raw) {
    const long long* p64 = (const long long*)raw;
    const int* p32 = (const int*)raw;
    bool ok64 = true;
    for (int b = 0; b < Bb && ok64; b++) {
        long long prev = -1;
        for (int p = 0; p < Pp; p++) {
            long long v = p64[b * Pp + p];
            if (v < 0 || v >= Ss || v <= prev) { ok64 = false; break; }
            prev = v;
        }
    }
    for (int i = 0; i < Bb * Pp; i++)
        g_seg[i] = ok64 ? (int)p64[i] : p32[i];
    long long po = 0;
    for (int bp = 0; bp < Bb * Pp; bp++) {
        int p = bp & 15;
        int s0 = g_seg[bp];
        int e0 = (p == Pp - 1) ? Ss : g_seg[bp + 1];
        int s0a = s0 & ~15;
        int Lp = ((e0 - s0a) + 15) & ~15;
        g_s0a[bp] = s0a;
        g_Lp[bp] = Lp;
        g_poff[bp] = po;
        po += (long long)Ss * Lp;
    }
}

// ---------------- fused input prep: cvt_x (blocks 0..3071) + transpose_w ---------
#define CVT_BLOCKS 3072
#define TW_PER_Z 576                 // 24 x 24 tiles per weight matrix
__global__ void prep_inputs(const float* __restrict__ x,
                            const float* __restrict__ Wq,
                            const float* __restrict__ Wk,
                            const float* __restrict__ Wv) {
    int bid = blockIdx.x;
    if (bid < CVT_BLOCKS) {
        long i = (long)bid * 256 + threadIdx.x;
        float4 v = ((const float4*)x)[i];
        __half h[4] = { __float2half(v.x), __float2half(v.y),
                        __float2half(v.z), __float2half(v.w) };
        *(uint2*)&g_xf[i * 4] = *(uint2*)h;
        return;
    }
    __shared__ float t[32][33];
    int b2 = bid - CVT_BLOCKS;
    int z = b2 / TW_PER_Z;
    int rem = b2 - z * TW_PER_Z;
    int bx = rem % 24, by = rem / 24;
    const float* W = (z == 0) ? Wq : (z == 1) ? Wk : Wv;
    int x0 = bx * 32, y0 = by * 32;
    int tx = threadIdx.x & 31, ty = threadIdx.x >> 5;   // 32 x 8
    #pragma unroll
    for (int i = 0; i < 32; i += 8) t[ty + i][tx] = W[(y0 + ty + i) * Dd + x0 + tx];
    __syncthreads();
    #pragma unroll
    for (int i = 0; i < 32; i += 8)
        g_wtf[(long)z * Dd * Dd + (long)(x0 + ty + i) * Dd + y0 + tx] =
            __float2half(t[tx][ty + i]);
}

// ---------------- projection GEMM (x @ W^T-rows), fp16 single --------------------
__global__ void __launch_bounds__(NT, 1) proj_tc(const float* __restrict__ b0,
                                                 const float* __restrict__ b1,
                                                 const float* __restrict__ b2) {
    extern __shared__ char smx[];
    unsigned sbu = smem_u32(smx);
    const int tid = threadIdx.x, warp = tid >> 5, lane = tid & 31;
    const int wm = warp >> 2, wn = warp & 3;
    const int z = blockIdx.z;
    const int n0 = blockIdx.x * 256, m0 = blockIdx.y * 128;

    const __half* A = g_xf + (long)m0 * Dd;
    const __half* B = g_wtf + (long)z * Dd * Dd + (long)n0 * Dd;

    frag_c acc[2][4];
    #pragma unroll
    for (int i = 0; i < 2; i++)
        #pragma unroll
        for (int j = 0; j < 4; j++) wmma::fill_fragment(acc[i][j], 0.f);

    const int NC = Dd / 64;
    GEMM_LOOP(A, Dd, B, Dd, NC)
    __syncthreads();

    const float* bias = (z == 0) ? b0 : (z == 1) ? b1 : b2;
    float* bounce = (float*)smx + warp * 320;        // 16x20 per warp
    #pragma unroll
    for (int i = 0; i < 2; i++)
        #pragma unroll
        for (int j = 0; j < 4; j++) {
            wmma::store_matrix_sync(bounce, acc[i][j], 20, wmma::mem_row_major);
            __syncwarp();
            int gm = m0 + wm * 32 + i * 16;
            int gn = n0 + wn * 64 + j * 16;
            if (z == 2) {
                int c = lane >> 1, rs = (lane & 1) * 8;
                int d = gn + c;
                float bi = bias[d];
                int bb = m0 >> 11;
                int sbase = (gm & (Ss - 1)) + rs;
                __half hh[8];
                #pragma unroll
                for (int t = 0; t < 8; t++)
                    hh[t] = __float2half(bounce[(rs + t) * 20 + c] + bi);
                *(uint4*)&g_vt[((long)bb * Dd + d) * SVT + sbase] = *(uint4*)hh;
            } else {
                int r = lane >> 1, cs = (lane & 1) * 8;
                __half hh[8];
                #pragma unroll
                for (int t = 0; t < 8; t++) {
                    float val = bounce[r * 20 + cs + t] + bias[gn + cs + t];
                    if (z == 0) val *= SCALE;
                    hh[t] = __float2half(val);
                }
                long dst = (long)(gm + r) * Dd + gn + cs;
                if (z == 0) *(uint4*)&g_qf[dst] = *(uint4*)hh;
                else        *(uint4*)&g_kf[dst] = *(uint4*)hh;
            }
            __syncwarp();
        }
}

// ---------------- scores GEMM: sc = (q*scale) @ k^T, fp16 single -----------------
__global__ void __launch_bounds__(NT, 1) scores_tc() {
    extern __shared__ char smx[];
    unsigned sbu = smem_u32(smx);
    const int tid = threadIdx.x, warp = tid >> 5;
    const int wm = warp >> 2, wn = warp & 3;
    const int b = blockIdx.z;
    const int n0 = blockIdx.x * 256, m0 = blockIdx.y * 128;

    const __half* A = g_qf + ((long)b * Ss + m0) * Dd;
    const __half* B = g_kf + ((long)b * Ss + n0) * Dd;

    frag_c acc[2][4];
    #pragma unroll
    for (int i = 0; i < 2; i++)
        #pragma unroll
        for (int j = 0; j < 4; j++) wmma::fill_fragment(acc[i][j], 0.f);

    const int NC = Dd / 64;
    GEMM_LOOP(A, Dd, B, Dd, NC)

    float* dst = g_sc + (long)b * Ss * Ss;
    #pragma unroll
    for (int i = 0; i < 2; i++)
        #pragma unroll
        for (int j = 0; j < 4; j++) {
            int gm = m0 + wm * 32 + i * 16;
            int gn = n0 + wn * 64 + j * 16;
            wmma::store_matrix_sync(&dst[(long)gm * Ss + gn], acc[i][j], Ss,
                                    wmma::mem_row_major);
        }
}

// ---------------- softmax: single-exp, smem-cached -> padded P (fp16) ------------
__global__ void __launch_bounds__(256) stats_kernel() {
    __shared__ __half cache[8][Ss];
    const int w = threadIdx.x >> 5;
    const int lane = threadIdx.x & 31;
    const int wid = blockIdx.x * 8 + w;
    const int q = wid & (Ss - 1);
    const int bp = wid / Ss;
    const int b = bp >> 4, p = bp & 15;
    const int s0 = g_seg[bp];
    const int e0 = (p == Pp - 1) ? Ss : g_seg[bp + 1];
    const int s0a = g_s0a[bp];
    const int Lp = g_Lp[bp];
    const float* row = g_sc + ((long)b * Ss + q) * Ss;
    float mx = -1e30f;
    for (int k = s0 + lane; k < e0; k += 32) mx = fmaxf(mx, row[k]);
    #pragma unroll
    for (int o = 16; o; o >>= 1) mx = fmaxf(mx, __shfl_xor_sync(0xffffffffu, mx, o));
    float sum = 0.f;
    for (int k = s0a + lane; k < s0a + Lp; k += 32) {
        float e = (k >= s0 && k < e0) ? __expf(row[k] - mx) : 0.f;
        cache[w][k - s0a] = __float2half(e);
        sum += e;
    }
    #pragma unroll
    for (int o = 16; o; o >>= 1) sum += __shfl_xor_sync(0xffffffffu, sum, o);
    float inv = 1.0f / sum;
    long long po = g_poff[bp] + (long long)q * Lp;
    for (int k = lane * 2; k < Lp; k += 64) {
        float2 e2 = __half22float2(*(const __half2*)&cache[w][k]);
        __half2 o2 = __floats2half2_rn(e2.x * inv, e2.y * inv);
        *(__half2*)&g_pf[po + k] = o2;
    }
}

// ---------------- output GEMM: out[bp] = P @ V, fully pipelined variable-K -------
__global__ void __launch_bounds__(NT, 1) out_tc(float* __restrict__ out) {
    extern __shared__ char smx[];
    unsigned sbu = smem_u32(smx);
    const int tid = threadIdx.x, warp = tid >> 5;
    const int wm = warp >> 2, wn = warp & 3;
    const int bp = blockIdx.z;
    const int b = bp >> 4;
    const int s0a = g_s0a[bp];
    const int Lp = g_Lp[bp];
    const int NC = (Lp + 63) >> 6;     // variable-width chunks (last may be 16..64)
    const int n0 = blockIdx.x * 256, m0 = blockIdx.y * 128;

    const __half* A = g_pf + g_poff[bp] + (long long)m0 * Lp;
    const __half* B = g_vt + ((long)b * Dd + n0) * SVT + s0a;

    frag_c acc[2][4];
    #pragma unroll
    for (int i = 0; i < 2; i++)
        #pragma unroll
        for (int j = 0; j < 4; j++) wmma::fill_fragment(acc[i][j], 0.f);

    // chunk width helper: Lp is a multiple of 16
    #define CWID(c) (((Lp - (c) * 64) > 64) ? 64 : (Lp - (c) * 64))

    stage_v(A, Lp, B, SVT, sbu, tid, CWID(0) >> 3);
    cp_commit();
    if (NC > 1) {
        stage_v(A + 64, Lp, B + 64, SVT, sbu + H_STAGE, tid, CWID(1) >> 3);
        cp_commit();
    }
    for (int c = 0; c < NC; c++) {
        if (c + 2 < NC) cp_wait1(); else cp_wait0();
        __syncthreads();
        if (c + 2 < NC) {
            long kk = (long)(c + 2) * 64;
            stage_v(A + kk, Lp, B + kk, SVT,
                    sbu + (unsigned)((c + 2) % 3) * H_STAGE, tid, CWID(c + 2) >> 3);
            cp_commit();
        }
        mma_v(acc, smx + (c % 3) * H_STAGE, wm, wn, CWID(c) >> 4);
    }
    #undef CWID

    float* dst = out + ((long)bp * Ss + m0) * Dd;
    #pragma unroll
    for (int i = 0; i < 2; i++)
        #pragma unroll
        for (int j = 0; j < 4; j++) {
            int rm = wm * 32 + i * 16;
            int gn = n0 + wn * 64 + j * 16;
            wmma::store_matrix_sync(&dst[(long)rm * Dd + gn], acc[i][j], Dd,
                                    wmma::mem_row_major);
        }
}

// ---------------- launch ----------------------------------------------------------
extern "C" void kernel_launch(void* const* d_in, const int* in_sizes, int n_in,
                              void* d_out, int out_size) {
    const float* x = (const float*)d_in[0];
    const void* pidx = d_in[1];
    const float* Wq = (const float*)d_in[2];
    const float* bq = (const float*)d_in[3];
    const float* Wk = (const float*)d_in[4];
    const float* bk = (const float*)d_in[5];
    const float* Wv = (const float*)d_in[6];
    const float* bv = (const float*)d_in[7];
    float* out = (float*)d_out;

    static int attr_done = 0;
    if (!attr_done) {
        cudaFuncSetAttribute(proj_tc, cudaFuncAttributeMaxDynamicSharedMemorySize, H_SMEM);
        cudaFuncSetAttribute(scores_tc, cudaFuncAttributeMaxDynamicSharedMemorySize, H_SMEM);
        cudaFuncSetAttribute(out_tc, cudaFuncAttributeMaxDynamicSharedMemorySize, H_SMEM);
        attr_done = 1;
    }

    decode_idx<<<1, 1>>>(pidx);
    prep_inputs<<<CVT_BLOCKS + 3 * TW_PER_Z, 256>>>(x, Wq, Wk, Wv);

    dim3 pg(Dd / 256, (Bb * Ss) / 128, 3);           // 3 x 32 x 3
    proj_tc<<<pg, NT, H_SMEM>>>(bq, bk, bv);

    dim3 sg(Ss / 256, Ss / 128, Bb);                 // 8 x 16 x 2
    scores_tc<<<sg, NT, H_SMEM>>>();

    stats_kernel<<<(Bb * Pp * Ss) / 8, 256>>>();

    dim3 og(Dd / 256, Ss / 128, Bb * Pp);            // 3 x 16 x 32
    out_tc<<<og, NT, H_SMEM>>>(out);
}

// round 17
// speedup vs baseline: 2.4984x; 1.0166x over previous
#include <cuda_runtime.h>
#include <cuda_fp16.h>
#include <mma.h>

using namespace nvcuda;

#define Bb 2
#define Ss 2048
#define Dd 768
#define Pp 16
#define SCALE 0.03608439182435161f   // 1/sqrt(768)

#define SVT (Ss + 64)                     // vt row stride (slack for over-read)
#define PSEG (Bb * Ss * (Ss + Pp * 64))   // padded P elems (16-granular pads)

// ---------------- scratch (device globals) -------------------------------------
__device__ __align__(256) float g_sc[Bb * Ss * Ss];
__device__ __align__(256) __half g_xf[Bb * Ss * Dd];    // x, fp16
__device__ __align__(256) __half g_wtf[3 * Dd * Dd];    // W^T rows, fp16
__device__ __align__(256) __half g_qf[Bb * Ss * Dd];    // q (pre-scaled), fp16
__device__ __align__(256) __half g_kf[Bb * Ss * Dd];    // k, fp16
__device__ __align__(256) __half g_pf[PSEG];            // P, fp16 (zero-padded)
__device__ __align__(256) __half g_vt[Bb * Dd * SVT];   // v transposed [b][d][s]
__device__ int g_seg[Bb * Pp];
__device__ int g_s0a[Bb * Pp];
__device__ int g_Lp[Bb * Pp];
__device__ long long g_poff[Bb * Pp];

// ---------------- wmma types ----------------------------------------------------
typedef wmma::fragment<wmma::matrix_a, 16, 16, 16, __half, wmma::row_major> frag_ha;
typedef wmma::fragment<wmma::matrix_b, 16, 16, 16, __half, wmma::col_major> frag_hb;
typedef wmma::fragment<wmma::accumulator, 16, 16, 16, float> frag_c;

// Block tile 128(M) x 256(N), K-chunk 64. Warp tile 32x64, warps 4x4 (512 thr).
#define NT 512
#define TLD 72
#define A_TILE 18432
#define H_STAGE 55296
#define H_SMEM 165888                 // 3 stages

// ---------------- helpers -------------------------------------------------------
__device__ __forceinline__ unsigned smem_u32(const void* p) {
    unsigned a;
    asm("{ .reg .u64 t; cvta.to.shared.u64 t, %1; cvt.u32.u64 %0, t; }" : "=r"(a) : "l"(p));
    return a;
}
#define CP16(daddr, gptr) \
    asm volatile("cp.async.cg.shared.global [%0], [%1], 16;" :: "r"(daddr), "l"(gptr) : "memory")
__device__ __forceinline__ void cp_commit() { asm volatile("cp.async.commit_group;" ::: "memory"); }
__device__ __forceinline__ void cp_wait0() { asm volatile("cp.async.wait_group 0;" ::: "memory"); }
__device__ __forceinline__ void cp_wait1() { asm volatile("cp.async.wait_group 1;" ::: "memory"); }

__device__ __forceinline__ void stage_h(const __half* A, long lda,
                                        const __half* B, long ldb,
                                        unsigned sb, int tid) {
    #pragma unroll
    for (int i = 0; i < 2; i++) {
        int ch = i * NT + tid;
        int r = ch >> 3, c16 = ch & 7;
        CP16(sb + (unsigned)(r * 144 + c16 * 16), A + (long)r * lda + c16 * 8);
    }
    #pragma unroll
    for (int i = 0; i < 4; i++) {
        int ch = i * NT + tid;
        int r = ch >> 3, c16 = ch & 7;
        CP16(sb + A_TILE + (unsigned)(r * 144 + c16 * 16), B + (long)r * ldb + c16 * 8);
    }
}

__device__ __forceinline__ void stage_v(const __half* A, long lda,
                                        const __half* B, long ldb,
                                        unsigned sb, int tid, int nch) {
    if (nch == 8) { stage_h(A, lda, B, ldb, sb, tid); return; }
    for (int idx = tid; idx < 128 * nch; idx += NT) {
        int r = idx / nch, c = idx - r * nch;
        CP16(sb + (unsigned)(r * 144 + c * 16), A + (long)r * lda + c * 8);
    }
    for (int idx = tid; idx < 256 * nch; idx += NT) {
        int r = idx / nch, c = idx - r * nch;
        CP16(sb + A_TILE + (unsigned)(r * 144 + c * 16), B + (long)r * ldb + c * 8);
    }
}

__device__ __forceinline__ void mma_chunk_h(frag_c (&acc)[2][4], const char* buf, int wm, int wn) {
    const __half* sA = (const __half*)buf;
    const __half* sB = (const __half*)(buf + A_TILE);
    #pragma unroll
    for (int ks = 0; ks < 4; ks++) {
        frag_ha a[2];
        #pragma unroll
        for (int i = 0; i < 2; i++)
            wmma::load_matrix_sync(a[i], sA + (wm * 32 + i * 16) * TLD + ks * 16, TLD);
        #pragma unroll
        for (int j = 0; j < 4; j++) {
            frag_hb b;
            wmma::load_matrix_sync(b, sB + (wn * 64 + j * 16) * TLD + ks * 16, TLD);
            wmma::mma_sync(acc[0][j], a[0], b, acc[0][j]);
            wmma::mma_sync(acc[1][j], a[1], b, acc[1][j]);
        }
    }
}

__device__ __forceinline__ void mma_v(frag_c (&acc)[2][4], const char* buf,
                                      int wm, int wn, int nks) {
    if (nks == 4) { mma_chunk_h(acc, buf, wm, wn); return; }
    const __half* sA = (const __half*)buf;
    const __half* sB = (const __half*)(buf + A_TILE);
    for (int ks = 0; ks < nks; ks++) {
        frag_ha a[2];
        #pragma unroll
        for (int i = 0; i < 2; i++)
            wmma::load_matrix_sync(a[i], sA + (wm * 32 + i * 16) * TLD + ks * 16, TLD);
        #pragma unroll
        for (int j = 0; j < 4; j++) {
            frag_hb b;
            wmma::load_matrix_sync(b, sB + (wn * 64 + j * 16) * TLD + ks * 16, TLD);
            wmma::mma_sync(acc[0][j], a[0], b, acc[0][j]);
            wmma::mma_sync(acc[1][j], a[1], b, acc[1][j]);
        }
    }
}

#define GEMM_LOOP(Ap, lda, Bp, ldb, NC)                                          \
    stage_h(Ap, lda, Bp, ldb, sbu, tid);                                         \
    cp_commit();                                                                 \
    if ((NC) > 1) { stage_h((Ap) + 64, lda, (Bp) + 64, ldb, sbu + H_STAGE, tid); \
                    cp_commit(); }                                               \
    for (int c = 0; c < (NC); c++) {                                             \
        if (c + 2 < (NC)) cp_wait1(); else cp_wait0();                           \
        __syncthreads();                                                         \
        if (c + 2 < (NC)) {                                                      \
            long kk = (long)(c + 2) * 64;                                        \
            stage_h((Ap) + kk, lda, (Bp) + kk, ldb,                              \
                    sbu + (unsigned)((c + 2) % 3) * H_STAGE, tid);               \
            cp_commit();                                                         \
        }                                                                        \
        mma_chunk_h(acc, smx + (c % 3) * H_STAGE, wm, wn);                       \
    }

// ---------------- decode patch indices + layout (16-granular) --------------------
__global__ void decode_idx(const void* __restrict__ raw) {
    const long long* p64 = (const long long*)raw;
    const int* p32 = (const int*)raw;
    bool ok64 = true;
    for (int b = 0; b < Bb && ok64; b++) {
        long long prev = -1;
        for (int p = 0; p < Pp; p++) {
            long long v = p64[b * Pp + p];
            if (v < 0 || v >= Ss || v <= prev) { ok64 = false; break; }
            prev = v;
        }
    }
    for (int i = 0; i < Bb * Pp; i++)
        g_seg[i] = ok64 ? (int)p64[i] : p32[i];
    long long po = 0;
    for (int bp = 0; bp < Bb * Pp; bp++) {
        int p = bp & 15;
        int s0 = g_seg[bp];
        int e0 = (p == Pp - 1) ? Ss : g_seg[bp + 1];
        int s0a = s0 & ~15;
        int Lp = ((e0 - s0a) + 15) & ~15;
        g_s0a[bp] = s0a;
        g_Lp[bp] = Lp;
        g_poff[bp] = po;
        po += (long long)Ss * Lp;
    }
}

// ---------------- fused input prep: cvt_x + transpose_w --------------------------
#define CVT_BLOCKS 3072
#define TW_PER_Z 576
__global__ void prep_inputs(const float* __restrict__ x,
                            const float* __restrict__ Wq,
                            const float* __restrict__ Wk,
                            const float* __restrict__ Wv) {
    int bid = blockIdx.x;
    if (bid < CVT_BLOCKS) {
        long i = (long)bid * 256 + threadIdx.x;
        float4 v = ((const float4*)x)[i];
        __half h[4] = { __float2half(v.x), __float2half(v.y),
                        __float2half(v.z), __float2half(v.w) };
        *(uint2*)&g_xf[i * 4] = *(uint2*)h;
        return;
    }
    __shared__ float t[32][33];
    int b2 = bid - CVT_BLOCKS;
    int z = b2 / TW_PER_Z;
    int rem = b2 - z * TW_PER_Z;
    int bx = rem % 24, by = rem / 24;
    const float* W = (z == 0) ? Wq : (z == 1) ? Wk : Wv;
    int x0 = bx * 32, y0 = by * 32;
    int tx = threadIdx.x & 31, ty = threadIdx.x >> 5;
    #pragma unroll
    for (int i = 0; i < 32; i += 8) t[ty + i][tx] = W[(y0 + ty + i) * Dd + x0 + tx];
    __syncthreads();
    #pragma unroll
    for (int i = 0; i < 32; i += 8)
        g_wtf[(long)z * Dd * Dd + (long)(x0 + ty + i) * Dd + y0 + tx] =
            __float2half(t[tx][ty + i]);
}

// ---------------- projection GEMM for q/k (z = 0,1) ------------------------------
__global__ void __launch_bounds__(NT, 1) proj_qk(const float* __restrict__ b0,
                                                 const float* __restrict__ b1) {
    extern __shared__ char smx[];
    unsigned sbu = smem_u32(smx);
    const int tid = threadIdx.x, warp = tid >> 5, lane = tid & 31;
    const int wm = warp >> 2, wn = warp & 3;
    const int z = blockIdx.z;
    const int n0 = blockIdx.x * 256, m0 = blockIdx.y * 128;

    const __half* A = g_xf + (long)m0 * Dd;
    const __half* B = g_wtf + (long)z * Dd * Dd + (long)n0 * Dd;

    frag_c acc[2][4];
    #pragma unroll
    for (int i = 0; i < 2; i++)
        #pragma unroll
        for (int j = 0; j < 4; j++) wmma::fill_fragment(acc[i][j], 0.f);

    const int NC = Dd / 64;
    GEMM_LOOP(A, Dd, B, Dd, NC)
    __syncthreads();

    const float* bias = (z == 0) ? b0 : b1;
    float* bounce = (float*)smx + warp * 320;
    #pragma unroll
    for (int i = 0; i < 2; i++)
        #pragma unroll
        for (int j = 0; j < 4; j++) {
            wmma::store_matrix_sync(bounce, acc[i][j], 20, wmma::mem_row_major);
            __syncwarp();
            int gm = m0 + wm * 32 + i * 16;
            int gn = n0 + wn * 64 + j * 16;
            int r = lane >> 1, cs = (lane & 1) * 8;
            __half hh[8];
            #pragma unroll
            for (int t = 0; t < 8; t++) {
                float val = bounce[r * 20 + cs + t] + bias[gn + cs + t];
                if (z == 0) val *= SCALE;
                hh[t] = __float2half(val);
            }
            long dst = (long)(gm + r) * Dd + gn + cs;
            if (z == 0) *(uint4*)&g_qf[dst] = *(uint4*)hh;
            else        *(uint4*)&g_kf[dst] = *(uint4*)hh;
            __syncwarp();
        }
}

// ---------------- projection GEMM for v (writes vt transposed) -------------------
__global__ void __launch_bounds__(NT, 1) proj_v(const float* __restrict__ bv) {
    extern __shared__ char smx[];
    unsigned sbu = smem_u32(smx);
    const int tid = threadIdx.x, warp = tid >> 5, lane = tid & 31;
    const int wm = warp >> 2, wn = warp & 3;
    const int n0 = blockIdx.x * 256, m0 = blockIdx.y * 128;

    const __half* A = g_xf + (long)m0 * Dd;
    const __half* B = g_wtf + (long)2 * Dd * Dd + (long)n0 * Dd;

    frag_c acc[2][4];
    #pragma unroll
    for (int i = 0; i < 2; i++)
        #pragma unroll
        for (int j = 0; j < 4; j++) wmma::fill_fragment(acc[i][j], 0.f);

    const int NC = Dd / 64;
    GEMM_LOOP(A, Dd, B, Dd, NC)
    __syncthreads();

    float* bounce = (float*)smx + warp * 320;
    #pragma unroll
    for (int i = 0; i < 2; i++)
        #pragma unroll
        for (int j = 0; j < 4; j++) {
            wmma::store_matrix_sync(bounce, acc[i][j], 20, wmma::mem_row_major);
            __syncwarp();
            int gm = m0 + wm * 32 + i * 16;
            int gn = n0 + wn * 64 + j * 16;
            int c = lane >> 1, rs = (lane & 1) * 8;
            int d = gn + c;
            float bi = bv[d];
            int bb = m0 >> 11;
            int sbase = (gm & (Ss - 1)) + rs;
            __half hh[8];
            #pragma unroll
            for (int t = 0; t < 8; t++)
                hh[t] = __float2half(bounce[(rs + t) * 20 + c] + bi);
            *(uint4*)&g_vt[((long)bb * Dd + d) * SVT + sbase] = *(uint4*)hh;
            __syncwarp();
        }
}

// ---------------- scores GEMM: sc = (q*scale) @ k^T ------------------------------
__global__ void __launch_bounds__(NT, 1) scores_tc() {
    extern __shared__ char smx[];
    unsigned sbu = smem_u32(smx);
    const int tid = threadIdx.x, warp = tid >> 5;
    const int wm = warp >> 2, wn = warp & 3;
    const int b = blockIdx.z;
    const int n0 = blockIdx.x * 256, m0 = blockIdx.y * 128;

    const __half* A = g_qf + ((long)b * Ss + m0) * Dd;
    const __half* B = g_kf + ((long)b * Ss + n0) * Dd;

    frag_c acc[2][4];
    #pragma unroll
    for (int i = 0; i < 2; i++)
        #pragma unroll
        for (int j = 0; j < 4; j++) wmma::fill_fragment(acc[i][j], 0.f);

    const int NC = Dd / 64;
    GEMM_LOOP(A, Dd, B, Dd, NC)

    float* dst = g_sc + (long)b * Ss * Ss;
    #pragma unroll
    for (int i = 0; i < 2; i++)
        #pragma unroll
        for (int j = 0; j < 4; j++) {
            int gm = m0 + wm * 32 + i * 16;
            int gn = n0 + wn * 64 + j * 16;
            wmma::store_matrix_sync(&dst[(long)gm * Ss + gn], acc[i][j], Ss,
                                    wmma::mem_row_major);
        }
}

// ---------------- softmax: single-exp, smem-cached -> padded P (fp16) ------------
__global__ void __launch_bounds__(256) stats_kernel() {
    __shared__ __half cache[8][Ss];
    const int w = threadIdx.x >> 5;
    const int lane = threadIdx.x & 31;
    const int wid = blockIdx.x * 8 + w;
    const int q = wid & (Ss - 1);
    const int bp = wid / Ss;
    const int b = bp >> 4, p = bp & 15;
    const int s0 = g_seg[bp];
    const int e0 = (p == Pp - 1) ? Ss : g_seg[bp + 1];
    const int s0a = g_s0a[bp];
    const int Lp = g_Lp[bp];
    const float* row = g_sc + ((long)b * Ss + q) * Ss;
    float mx = -1e30f;
    for (int k = s0 + lane; k < e0; k += 32) mx = fmaxf(mx, row[k]);
    #pragma unroll
    for (int o = 16; o; o >>= 1) mx = fmaxf(mx, __shfl_xor_sync(0xffffffffu, mx, o));
    float sum = 0.f;
    for (int k = s0a + lane; k < s0a + Lp; k += 32) {
        float e = (k >= s0 && k < e0) ? __expf(row[k] - mx) : 0.f;
        cache[w][k - s0a] = __float2half(e);
        sum += e;
    }
    #pragma unroll
    for (int o = 16; o; o >>= 1) sum += __shfl_xor_sync(0xffffffffu, sum, o);
    float inv = 1.0f / sum;
    long long po = g_poff[bp] + (long long)q * Lp;
    for (int k = lane * 2; k < Lp; k += 64) {
        float2 e2 = __half22float2(*(const __half2*)&cache[w][k]);
        __half2 o2 = __floats2half2_rn(e2.x * inv, e2.y * inv);
        *(__half2*)&g_pf[po + k] = o2;
    }
}

// ---------------- output GEMM: out[bp] = P @ V, pipelined variable-K -------------
__global__ void __launch_bounds__(NT, 1) out_tc(float* __restrict__ out) {
    extern __shared__ char smx[];
    unsigned sbu = smem_u32(smx);
    const int tid = threadIdx.x, warp = tid >> 5;
    const int wm = warp >> 2, wn = warp & 3;
    const int bp = blockIdx.z;
    const int b = bp >> 4;
    const int s0a = g_s0a[bp];
    const int Lp = g_Lp[bp];
    const int NC = (Lp + 63) >> 6;
    const int n0 = blockIdx.x * 256, m0 = blockIdx.y * 128;

    const __half* A = g_pf + g_poff[bp] + (long long)m0 * Lp;
    const __half* B = g_vt + ((long)b * Dd + n0) * SVT + s0a;

    frag_c acc[2][4];
    #pragma unroll
    for (int i = 0; i < 2; i++)
        #pragma unroll
        for (int j = 0; j < 4; j++) wmma::fill_fragment(acc[i][j], 0.f);

    #define CWID(c) (((Lp - (c) * 64) > 64) ? 64 : (Lp - (c) * 64))
    stage_v(A, Lp, B, SVT, sbu, tid, CWID(0) >> 3);
    cp_commit();
    if (NC > 1) {
        stage_v(A + 64, Lp, B + 64, SVT, sbu + H_STAGE, tid, CWID(1) >> 3);
        cp_commit();
    }
    for (int c = 0; c < NC; c++) {
        if (c + 2 < NC) cp_wait1(); else cp_wait0();
        __syncthreads();
        if (c + 2 < NC) {
            long kk = (long)(c + 2) * 64;
            stage_v(A + kk, Lp, B + kk, SVT,
                    sbu + (unsigned)((c + 2) % 3) * H_STAGE, tid, CWID(c + 2) >> 3);
            cp_commit();
        }
        mma_v(acc, smx + (c % 3) * H_STAGE, wm, wn, CWID(c) >> 4);
    }
    #undef CWID

    float* dst = out + ((long)bp * Ss + m0) * Dd;
    #pragma unroll
    for (int i = 0; i < 2; i++)
        #pragma unroll
        for (int j = 0; j < 4; j++) {
            int rm = wm * 32 + i * 16;
            int gn = n0 + wn * 64 + j * 16;
            wmma::store_matrix_sync(&dst[(long)rm * Dd + gn], acc[i][j], Dd,
                                    wmma::mem_row_major);
        }
}

// ---------------- launch ----------------------------------------------------------
extern "C" void kernel_launch(void* const* d_in, const int* in_sizes, int n_in,
                              void* d_out, int out_size) {
    const float* x = (const float*)d_in[0];
    const void* pidx = d_in[1];
    const float* Wq = (const float*)d_in[2];
    const float* bq = (const float*)d_in[3];
    const float* Wk = (const float*)d_in[4];
    const float* bk = (const float*)d_in[5];
    const float* Wv = (const float*)d_in[6];
    const float* bv = (const float*)d_in[7];
    float* out = (float*)d_out;

    static cudaStream_t sv = nullptr;
    static cudaEvent_t eFork, ePrep, eDec, eJoin;
    if (!sv) {
        cudaStreamCreateWithFlags(&sv, cudaStreamNonBlocking);
        cudaEventCreateWithFlags(&eFork, cudaEventDisableTiming);
        cudaEventCreateWithFlags(&ePrep, cudaEventDisableTiming);
        cudaEventCreateWithFlags(&eDec, cudaEventDisableTiming);
        cudaEventCreateWithFlags(&eJoin, cudaEventDisableTiming);
        cudaFuncSetAttribute(proj_qk, cudaFuncAttributeMaxDynamicSharedMemorySize, H_SMEM);
        cudaFuncSetAttribute(proj_v, cudaFuncAttributeMaxDynamicSharedMemorySize, H_SMEM);
        cudaFuncSetAttribute(scores_tc, cudaFuncAttributeMaxDynamicSharedMemorySize, H_SMEM);
        cudaFuncSetAttribute(out_tc, cudaFuncAttributeMaxDynamicSharedMemorySize, H_SMEM);
    }

    // fork: side stream handles decode (|| prep) then proj_v (|| proj_qk+scores)
    cudaEventRecord(eFork, 0);
    cudaStreamWaitEvent(sv, eFork, 0);
    decode_idx<<<1, 1, 0, sv>>>(pidx);
    cudaEventRecord(eDec, sv);

    prep_inputs<<<CVT_BLOCKS + 3 * TW_PER_Z, 256>>>(x, Wq, Wk, Wv);
    cudaEventRecord(ePrep, 0);
    cudaStreamWaitEvent(sv, ePrep, 0);

    dim3 pgv(Dd / 256, (Bb * Ss) / 128);             // 3 x 32
    proj_v<<<pgv, NT, H_SMEM, sv>>>(bv);
    cudaEventRecord(eJoin, sv);

    dim3 pg(Dd / 256, (Bb * Ss) / 128, 2);           // 3 x 32 x 2
    proj_qk<<<pg, NT, H_SMEM>>>(bq, bk);

    dim3 sg(Ss / 256, Ss / 128, Bb);                 // 8 x 16 x 2
    scores_tc<<<sg, NT, H_SMEM>>>();

    cudaStreamWaitEvent(0, eDec, 0);                 // stats needs decode results
    stats_kernel<<<(Bb * Pp * Ss) / 8, 256>>>();

    cudaStreamWaitEvent(0, eJoin, 0);                // out needs v
    dim3 og(Dd / 256, Ss / 128, Bb * Pp);            // 3 x 16 x 32
    out_tc<<<og, NT, H_SMEM>>>(out);
}